// round 1
// baseline (speedup 1.0000x reference)
#include <cuda_runtime.h>
#include <cstdint>

#define B_SZ 4
#define DIMC 384
#define L_SEQ 4096
#define D_INNER 768
#define D_STATE 16
#define DT_RANK 24
#define XPN 56                      // DT_RANK + 2*D_STATE
#define M_TOTAL (B_SZ * L_SEQ)      // 16384

// ---------------- scratch (no allocations allowed) ----------------
__device__ float g_xn[(size_t)M_TOTAL * DIMC];          // layernormed x, (B*L, C)
__device__ float g_xz[(size_t)M_TOTAL * 2 * D_INNER];   // in_proj out, (B*L, 1536)
__device__ float g_xc[(size_t)M_TOTAL * D_INNER];       // conv+silu out, (B*L, 768)
__device__ float g_xdbl[(size_t)M_TOTAL * XPN];         // x_proj out, (B*L, 56)
__device__ float g_dtv[(size_t)M_TOTAL * D_INNER];      // softplus(dt), (B*L, 768)
__device__ float g_y[(size_t)M_TOTAL * D_INNER];        // scan+gate out, (B*L, 768)

// ---------------- LayerNorm: x (B,C,L) -> xn (B*L, C) ----------------
// block = 256 threads handles 64 consecutive l for one b.
__global__ __launch_bounds__(256) void ln_kernel(const float* __restrict__ x,
                                                 const float* __restrict__ w,
                                                 const float* __restrict__ bsh,
                                                 float* __restrict__ xn) {
    int b  = blockIdx.y;
    int l0 = blockIdx.x * 64;
    int tid = threadIdx.x;
    int ll = tid & 63;
    int cg = tid >> 6;   // 0..3

    __shared__ float ssum[4][64];
    __shared__ float ssq[4][64];
    __shared__ float smean[64];
    __shared__ float srstd[64];
    __shared__ float st[16][65];

    const float* xb = x + (size_t)b * DIMC * L_SEQ;

    float s = 0.f, sq = 0.f;
    for (int c = cg; c < DIMC; c += 4) {
        float v = xb[(size_t)c * L_SEQ + l0 + ll];
        s += v; sq += v * v;
    }
    ssum[cg][ll] = s; ssq[cg][ll] = sq;
    __syncthreads();
    if (tid < 64) {
        float S = ssum[0][tid] + ssum[1][tid] + ssum[2][tid] + ssum[3][tid];
        float Q = ssq[0][tid] + ssq[1][tid] + ssq[2][tid] + ssq[3][tid];
        float mu = S * (1.f / DIMC);
        float var = Q * (1.f / DIMC) - mu * mu;
        smean[tid] = mu;
        srstd[tid] = rsqrtf(var + 1e-5f);
    }
    __syncthreads();

    // transpose-write 16c x 64l tiles so xn writes are c-fastest (coalesced)
    for (int c0 = 0; c0 < DIMC; c0 += 16) {
        #pragma unroll
        for (int r = 0; r < 4; r++) {
            int c = c0 + cg + r * 4;
            float v = xb[(size_t)c * L_SEQ + l0 + ll];
            st[cg + r * 4][ll] = (v - smean[ll]) * srstd[ll] * w[c] + bsh[c];
        }
        __syncthreads();
        int c2 = tid & 15, lr = tid >> 4;
        #pragma unroll
        for (int p = 0; p < 4; p++) {
            int l = lr + p * 16;
            xn[((size_t)b * L_SEQ + l0 + l) * DIMC + c0 + c2] = st[c2][l];
        }
        __syncthreads();
    }
}

// ---------------- generic fp32 tiled GEMM ----------------
// C[m,n] = sum_k A[m,k] * W[n,k]
// BM=128, BN=64, BK=16, 128 threads, 8x8 per thread.
// mode 0: plain store C[m*ldc+n]
// mode 1: softplus(acc + bias[n])
// mode 2: transposed store out[(b*DIMC + n)*L + l],  m = b*L + l
#define BM 128
#define BN 64
#define BK 16
#define SPAD 4

__global__ __launch_bounds__(128) void gemm_kernel(
    const float* __restrict__ A, int lda, int K,
    const float* __restrict__ W, int ldw, int N,
    float* __restrict__ C, int ldc, int mode,
    const float* __restrict__ bias) {

    __shared__ float As[BK][BM + SPAD];
    __shared__ float Bs[BK][BN + SPAD];

    int tid = threadIdx.x;
    int m0 = blockIdx.y * BM;
    int n0 = blockIdx.x * BN;
    int tm = tid & 15;   // 16 thread-rows
    int tn = tid >> 4;   // 8 thread-cols

    float acc[8][8];
    #pragma unroll
    for (int i = 0; i < 8; i++)
        #pragma unroll
        for (int j = 0; j < 8; j++) acc[i][j] = 0.f;

    for (int kt = 0; kt < K; kt += BK) {
        // load A tile: 128x16 = 512 float4
        #pragma unroll
        for (int r = 0; r < 4; r++) {
            int q = tid + 128 * r;
            int m = q >> 2;
            int kq = (q & 3) * 4;
            int kk = kt + kq;
            float4 v = make_float4(0.f, 0.f, 0.f, 0.f);
            if (kk < K) v = *(const float4*)&A[(size_t)(m0 + m) * lda + kk];
            As[kq + 0][m] = v.x; As[kq + 1][m] = v.y;
            As[kq + 2][m] = v.z; As[kq + 3][m] = v.w;
        }
        // load W tile: 64x16 = 256 float4
        #pragma unroll
        for (int r = 0; r < 2; r++) {
            int q = tid + 128 * r;
            int n = q >> 2;
            int kq = (q & 3) * 4;
            int kk = kt + kq;
            float4 v = make_float4(0.f, 0.f, 0.f, 0.f);
            if (kk < K && (n0 + n) < N)
                v = *(const float4*)&W[(size_t)(n0 + n) * ldw + kk];
            Bs[kq + 0][n] = v.x; Bs[kq + 1][n] = v.y;
            Bs[kq + 2][n] = v.z; Bs[kq + 3][n] = v.w;
        }
        __syncthreads();

        #pragma unroll
        for (int k = 0; k < BK; k++) {
            float a[8], bb[8];
            *(float4*)&a[0]  = *(const float4*)&As[k][tm * 8];
            *(float4*)&a[4]  = *(const float4*)&As[k][tm * 8 + 4];
            *(float4*)&bb[0] = *(const float4*)&Bs[k][tn * 8];
            *(float4*)&bb[4] = *(const float4*)&Bs[k][tn * 8 + 4];
            #pragma unroll
            for (int i = 0; i < 8; i++)
                #pragma unroll
                for (int j = 0; j < 8; j++)
                    acc[i][j] = fmaf(a[i], bb[j], acc[i][j]);
        }
        __syncthreads();
    }

    int mbase = m0 + tm * 8;
    int nbase = n0 + tn * 8;

    if (mode == 2) {
        int b = mbase >> 12;       // / L_SEQ
        int l = mbase & (L_SEQ - 1);
        #pragma unroll
        for (int j = 0; j < 8; j++) {
            int n = nbase + j;
            if (n < N) {
                float4 v0 = make_float4(acc[0][j], acc[1][j], acc[2][j], acc[3][j]);
                float4 v1 = make_float4(acc[4][j], acc[5][j], acc[6][j], acc[7][j]);
                float* dst = C + ((size_t)b * DIMC + n) * L_SEQ + l;
                *(float4*)dst = v0;
                *(float4*)(dst + 4) = v1;
            }
        }
    } else {
        #pragma unroll
        for (int i = 0; i < 8; i++) {
            int m = mbase + i;
            #pragma unroll
            for (int j = 0; j < 8; j++) {
                int n = nbase + j;
                if (n < N) {
                    float v = acc[i][j];
                    if (mode == 1) {
                        v += bias[n];
                        v = fmaxf(v, 0.f) + log1pf(__expf(-fabsf(v)));  // stable softplus
                    }
                    C[(size_t)m * ldc + n] = v;
                }
            }
        }
    }
}

// ---------------- depthwise causal conv1d (k=4) + SiLU ----------------
__global__ __launch_bounds__(256) void conv_silu_kernel(const float* __restrict__ cw,
                                                        const float* __restrict__ cb,
                                                        const float* __restrict__ xz,
                                                        float* __restrict__ xc) {
    int idx = blockIdx.x * blockDim.x + threadIdx.x;
    if (idx >= M_TOTAL * D_INNER) return;
    int d = idx % D_INNER;
    int m = idx / D_INNER;       // b*L + l
    int l = m & (L_SEQ - 1);

    float w0 = cw[d * 4 + 0], w1 = cw[d * 4 + 1];
    float w2 = cw[d * 4 + 2], w3 = cw[d * 4 + 3];

    const float* xb = xz + (size_t)m * (2 * D_INNER) + d;
    float acc = cb[d];
    if (l >= 3) acc = fmaf(w0, xb[-3 * 2 * D_INNER], acc);
    if (l >= 2) acc = fmaf(w1, xb[-2 * 2 * D_INNER], acc);
    if (l >= 1) acc = fmaf(w2, xb[-1 * 2 * D_INNER], acc);
    acc = fmaf(w3, xb[0], acc);
    float sg = 1.f / (1.f + __expf(-acc));
    xc[(size_t)m * D_INNER + d] = acc * sg;
}

// ---------------- selective scan + gating epilogue ----------------
// warp layout: lane = half*16 + n; each warp owns 2 channels (d0, d0+1).
// carried dep per step: h = exp(dt*A_n)*h + (dt*x)*B_n;  y = sum_n h*C_n.
__global__ __launch_bounds__(128) void scan_kernel(const float* __restrict__ A_log,
                                                   const float* __restrict__ Dp,
                                                   const float* __restrict__ dtv,
                                                   const float* __restrict__ xc,
                                                   const float* __restrict__ xdbl,
                                                   const float* __restrict__ xz,
                                                   float* __restrict__ y) {
    int warp = (blockIdx.x * blockDim.x + threadIdx.x) >> 5;   // 0..1535
    int lane = threadIdx.x & 31;
    int b = warp / (D_INNER / 2);
    int dpair = warp % (D_INNER / 2);
    int half = lane >> 4;
    int n = lane & 15;
    int d = dpair * 2 + half;

    float An = -__expf(A_log[d * D_STATE + n]);
    float Dd = Dp[d];
    float h = 0.f;

    const float* dtp = dtv  + (size_t)b * L_SEQ * D_INNER + d;
    const float* xcp = xc   + (size_t)b * L_SEQ * D_INNER + d;
    const float* bcp = xdbl + (size_t)b * L_SEQ * XPN + DT_RANK + n;   // B; C at +16
    const float* zp  = xz   + (size_t)b * L_SEQ * (2 * D_INNER) + D_INNER + d;
    float* yp = y + (size_t)b * L_SEQ * D_INNER + d;

    #pragma unroll 2
    for (int l = 0; l < L_SEQ; l++) {
        float dt = dtp[(size_t)l * D_INNER];
        float xv = xcp[(size_t)l * D_INNER];
        float Bn = bcp[(size_t)l * XPN];
        float Cn = bcp[(size_t)l * XPN + D_STATE];

        float e = __expf(dt * An);
        h = fmaf(e, h, dt * xv * Bn);

        float p = h * Cn;
        p += __shfl_xor_sync(0xffffffffu, p, 8);
        p += __shfl_xor_sync(0xffffffffu, p, 4);
        p += __shfl_xor_sync(0xffffffffu, p, 2);
        p += __shfl_xor_sync(0xffffffffu, p, 1);

        if (n == 0) {
            float zv = zp[(size_t)l * (2 * D_INNER)];
            float yv = p + xv * Dd;
            yv *= zv / (1.f + __expf(-zv));   // silu gate
            yp[(size_t)l * D_INNER] = yv;
        }
    }
}

// ---------------- launch ----------------
extern "C" void kernel_launch(void* const* d_in, const int* in_sizes, int n_in,
                              void* d_out, int out_size) {
    const float* x          = (const float*)d_in[0];
    const float* ln_w       = (const float*)d_in[1];
    const float* ln_b       = (const float*)d_in[2];
    const float* in_proj_w  = (const float*)d_in[3];
    const float* conv_w     = (const float*)d_in[4];
    const float* conv_b     = (const float*)d_in[5];
    const float* x_proj_w   = (const float*)d_in[6];
    const float* dt_w       = (const float*)d_in[7];
    const float* dt_b       = (const float*)d_in[8];
    const float* A_log      = (const float*)d_in[9];
    const float* Dp         = (const float*)d_in[10];
    const float* out_proj_w = (const float*)d_in[11];
    float* out = (float*)d_out;

    float *p_xn, *p_xz, *p_xc, *p_xdbl, *p_dtv, *p_y;
    cudaGetSymbolAddress((void**)&p_xn,   g_xn);
    cudaGetSymbolAddress((void**)&p_xz,   g_xz);
    cudaGetSymbolAddress((void**)&p_xc,   g_xc);
    cudaGetSymbolAddress((void**)&p_xdbl, g_xdbl);
    cudaGetSymbolAddress((void**)&p_dtv,  g_dtv);
    cudaGetSymbolAddress((void**)&p_y,    g_y);

    // 1) LayerNorm
    ln_kernel<<<dim3(L_SEQ / 64, B_SZ), 256>>>(x, ln_w, ln_b, p_xn);

    // 2) in_proj: (16384,384) x (1536,384)^T -> (16384,1536)
    gemm_kernel<<<dim3(2 * D_INNER / BN, M_TOTAL / BM), 128>>>(
        p_xn, DIMC, DIMC, in_proj_w, DIMC, 2 * D_INNER, p_xz, 2 * D_INNER, 0, nullptr);

    // 3) depthwise conv + silu
    {
        int total = M_TOTAL * D_INNER;
        conv_silu_kernel<<<(total + 255) / 256, 256>>>(conv_w, conv_b, p_xz, p_xc);
    }

    // 4) x_proj: (16384,768) x (56,768)^T -> (16384,56)
    gemm_kernel<<<dim3((XPN + BN - 1) / BN, M_TOTAL / BM), 128>>>(
        p_xc, D_INNER, D_INNER, x_proj_w, D_INNER, XPN, p_xdbl, XPN, 0, nullptr);

    // 5) dt: (16384,24) x (768,24)^T + bias, softplus -> (16384,768)
    gemm_kernel<<<dim3(D_INNER / BN, M_TOTAL / BM), 128>>>(
        p_xdbl, XPN, DT_RANK, dt_w, DT_RANK, D_INNER, p_dtv, D_INNER, 1, dt_b);

    // 6) selective scan + gating -> y (16384,768)
    scan_kernel<<<(B_SZ * (D_INNER / 2) * 32) / 128, 128>>>(
        A_log, Dp, p_dtv, p_xc, p_xdbl, p_xz, p_y);

    // 7) out_proj: (16384,768) x (384,768)^T -> out (B,C,L) transposed store
    gemm_kernel<<<dim3(DIMC / BN, M_TOTAL / BM), 128>>>(
        p_y, D_INNER, D_INNER, out_proj_w, D_INNER, DIMC, out, 0, 2, nullptr);
}

// round 2
// speedup vs baseline: 1.0307x; 1.0307x over previous
#include <cuda_runtime.h>
#include <cstdint>

#define B_SZ 4
#define DIMC 384
#define L_SEQ 4096
#define D_INNER 768
#define D_STATE 16
#define DT_RANK 24
#define XPN 56                      // DT_RANK + 2*D_STATE
#define M_TOTAL (B_SZ * L_SEQ)      // 16384

// ---------------- scratch (no allocations allowed) ----------------
__device__ float g_xn[(size_t)M_TOTAL * DIMC];          // layernormed x, (B*L, C)
__device__ float g_xz[(size_t)M_TOTAL * 2 * D_INNER];   // in_proj out, (B*L, 1536)
__device__ float g_xc[(size_t)M_TOTAL * D_INNER];       // conv+silu out, (B*L, 768)
__device__ float g_xdbl[(size_t)M_TOTAL * XPN];         // x_proj out, (B*L, 56)
__device__ float g_dtv[(size_t)M_TOTAL * D_INNER];      // softplus(dt), (B*L, 768)
__device__ float g_y[(size_t)M_TOTAL * D_INNER];        // scan+gate out, (B*L, 768)

// ---------------- LayerNorm: x (B,C,L) -> xn (B*L, C) ----------------
__global__ __launch_bounds__(256) void ln_kernel(const float* __restrict__ x,
                                                 const float* __restrict__ w,
                                                 const float* __restrict__ bsh,
                                                 float* __restrict__ xn) {
    int b  = blockIdx.y;
    int l0 = blockIdx.x * 64;
    int tid = threadIdx.x;
    int ll = tid & 63;
    int cg = tid >> 6;   // 0..3

    __shared__ float ssum[4][64];
    __shared__ float ssq[4][64];
    __shared__ float smean[64];
    __shared__ float srstd[64];
    __shared__ float st[16][65];

    const float* xb = x + (size_t)b * DIMC * L_SEQ;

    float s = 0.f, sq = 0.f;
    for (int c = cg; c < DIMC; c += 4) {
        float v = xb[(size_t)c * L_SEQ + l0 + ll];
        s += v; sq += v * v;
    }
    ssum[cg][ll] = s; ssq[cg][ll] = sq;
    __syncthreads();
    if (tid < 64) {
        float S = ssum[0][tid] + ssum[1][tid] + ssum[2][tid] + ssum[3][tid];
        float Q = ssq[0][tid] + ssq[1][tid] + ssq[2][tid] + ssq[3][tid];
        float mu = S * (1.f / DIMC);
        float var = Q * (1.f / DIMC) - mu * mu;
        smean[tid] = mu;
        srstd[tid] = rsqrtf(var + 1e-5f);
    }
    __syncthreads();

    for (int c0 = 0; c0 < DIMC; c0 += 16) {
        #pragma unroll
        for (int r = 0; r < 4; r++) {
            int c = c0 + cg + r * 4;
            float v = xb[(size_t)c * L_SEQ + l0 + ll];
            st[cg + r * 4][ll] = (v - smean[ll]) * srstd[ll] * w[c] + bsh[c];
        }
        __syncthreads();
        int c2 = tid & 15, lr = tid >> 4;
        #pragma unroll
        for (int p = 0; p < 4; p++) {
            int l = lr + p * 16;
            xn[((size_t)b * L_SEQ + l0 + l) * DIMC + c0 + c2] = st[c2][l];
        }
        __syncthreads();
    }
}

// ---------------- fp32 tiled GEMM, 128x128x16, 256 thr, double-buffered ----------------
// C[m,n] = sum_k A[m,k] * W[n,k]
// mode 0: plain store    mode 1: softplus(acc+bias[n])   mode 2: transposed (B,C,L) store
#define BM 128
#define BN 128
#define BKK 16
#define PAD 4

__global__ __launch_bounds__(256, 2) void gemm2_kernel(
    const float* __restrict__ A, int lda, int K,
    const float* __restrict__ W, int ldw, int N,
    float* __restrict__ C, int ldc, int mode,
    const float* __restrict__ bias) {

    __shared__ float As[2][BKK][BM + PAD];
    __shared__ float Bs[2][BKK][BN + PAD];

    int tid = threadIdx.x;
    int m0 = blockIdx.y * BM;
    int n0 = blockIdx.x * BN;
    int tm = tid & 15;    // 0..15
    int tn = tid >> 4;    // 0..15

    // global staging indices: thread loads rows lr, lr+64 at k offset lk..lk+3
    int lr = tid >> 2;          // 0..63
    int lk = (tid & 3) * 4;     // 0,4,8,12

    float4 pa[2], pb[2];
    int nt = (K + BKK - 1) / BKK;

    // prefetch tile 0 into registers
    {
        int kk = lk;
        #pragma unroll
        for (int r = 0; r < 2; r++) {
            int m = lr + r * 64;
            float4 v = make_float4(0.f, 0.f, 0.f, 0.f);
            if (kk < K) v = *(const float4*)&A[(size_t)(m0 + m) * lda + kk];
            pa[r] = v;
            float4 u = make_float4(0.f, 0.f, 0.f, 0.f);
            if (kk < K && (n0 + m) < N) u = *(const float4*)&W[(size_t)(n0 + m) * ldw + kk];
            pb[r] = u;
        }
    }

    float acc[8][8];
    #pragma unroll
    for (int i = 0; i < 8; i++)
        #pragma unroll
        for (int j = 0; j < 8; j++) acc[i][j] = 0.f;

    for (int t = 0; t < nt; t++) {
        int buf = t & 1;
        // store staged regs to smem
        #pragma unroll
        for (int r = 0; r < 2; r++) {
            int m = lr + r * 64;
            As[buf][lk + 0][m] = pa[r].x;
            As[buf][lk + 1][m] = pa[r].y;
            As[buf][lk + 2][m] = pa[r].z;
            As[buf][lk + 3][m] = pa[r].w;
            Bs[buf][lk + 0][m] = pb[r].x;
            Bs[buf][lk + 1][m] = pb[r].y;
            Bs[buf][lk + 2][m] = pb[r].z;
            Bs[buf][lk + 3][m] = pb[r].w;
        }
        __syncthreads();

        // prefetch next tile
        if (t + 1 < nt) {
            int kk = (t + 1) * BKK + lk;
            #pragma unroll
            for (int r = 0; r < 2; r++) {
                int m = lr + r * 64;
                float4 v = make_float4(0.f, 0.f, 0.f, 0.f);
                if (kk < K) v = *(const float4*)&A[(size_t)(m0 + m) * lda + kk];
                pa[r] = v;
                float4 u = make_float4(0.f, 0.f, 0.f, 0.f);
                if (kk < K && (n0 + m) < N) u = *(const float4*)&W[(size_t)(n0 + m) * ldw + kk];
                pb[r] = u;
            }
        }

        // compute from current buffer
        const float (*Ab)[BM + PAD] = As[buf];
        const float (*Bb)[BN + PAD] = Bs[buf];
        #pragma unroll
        for (int k = 0; k < BKK; k++) {
            float a[8], b[8];
            *(float4*)&a[0] = *(const float4*)&Ab[k][tm * 4];
            *(float4*)&a[4] = *(const float4*)&Ab[k][64 + tm * 4];
            *(float4*)&b[0] = *(const float4*)&Bb[k][tn * 4];
            *(float4*)&b[4] = *(const float4*)&Bb[k][64 + tn * 4];
            #pragma unroll
            for (int i = 0; i < 8; i++)
                #pragma unroll
                for (int j = 0; j < 8; j++)
                    acc[i][j] = fmaf(a[i], b[j], acc[i][j]);
        }
        __syncthreads();
    }

    // epilogue
    if (mode == 2) {
        // out[(b*DIMC + n)*L + l], m = b*L + l ; rows within one b (BM | L)
        int b = m0 >> 12;                 // m0 / L_SEQ
        int lbase = m0 & (L_SEQ - 1);
        #pragma unroll
        for (int jh = 0; jh < 2; jh++) {
            #pragma unroll
            for (int j4 = 0; j4 < 4; j4++) {
                int j = jh * 4 + j4;
                int n = n0 + jh * 64 + tn * 4 + j4;
                if (n < N) {
                    float* dst = C + ((size_t)b * DIMC + n) * L_SEQ + lbase;
                    #pragma unroll
                    for (int ih = 0; ih < 2; ih++) {
                        float4 v = make_float4(acc[ih * 4 + 0][j], acc[ih * 4 + 1][j],
                                               acc[ih * 4 + 2][j], acc[ih * 4 + 3][j]);
                        *(float4*)&dst[ih * 64 + tm * 4] = v;
                    }
                }
            }
        }
    } else {
        #pragma unroll
        for (int ih = 0; ih < 2; ih++) {
            #pragma unroll
            for (int i4 = 0; i4 < 4; i4++) {
                int i = ih * 4 + i4;
                int m = m0 + ih * 64 + tm * 4 + i4;
                #pragma unroll
                for (int jh = 0; jh < 2; jh++) {
                    int n = n0 + jh * 64 + tn * 4;
                    if (n < N) {
                        float4 v = make_float4(acc[i][jh * 4 + 0], acc[i][jh * 4 + 1],
                                               acc[i][jh * 4 + 2], acc[i][jh * 4 + 3]);
                        if (mode == 1) {
                            float* vv = (float*)&v;
                            #pragma unroll
                            for (int j = 0; j < 4; j++) {
                                float z = vv[j] + bias[n + j];
                                vv[j] = fmaxf(z, 0.f) + log1pf(__expf(-fabsf(z)));
                            }
                        }
                        // guard partial tail columns (x_proj N=56)
                        if (n + 3 < N) {
                            *(float4*)&C[(size_t)m * ldc + n] = v;
                        } else {
                            float* vv = (float*)&v;
                            #pragma unroll
                            for (int j = 0; j < 4; j++)
                                if (n + j < N) C[(size_t)m * ldc + n + j] = vv[j];
                        }
                    }
                }
            }
        }
    }
}

// ---------------- depthwise causal conv1d (k=4) + SiLU ----------------
__global__ __launch_bounds__(256) void conv_silu_kernel(const float* __restrict__ cw,
                                                        const float* __restrict__ cb,
                                                        const float* __restrict__ xz,
                                                        float* __restrict__ xc) {
    int idx = blockIdx.x * blockDim.x + threadIdx.x;
    if (idx >= M_TOTAL * D_INNER) return;
    int d = idx % D_INNER;
    int m = idx / D_INNER;       // b*L + l
    int l = m & (L_SEQ - 1);

    float w0 = cw[d * 4 + 0], w1 = cw[d * 4 + 1];
    float w2 = cw[d * 4 + 2], w3 = cw[d * 4 + 3];

    const float* xb = xz + (size_t)m * (2 * D_INNER) + d;
    float acc = cb[d];
    if (l >= 3) acc = fmaf(w0, xb[-3 * 2 * D_INNER], acc);
    if (l >= 2) acc = fmaf(w1, xb[-2 * 2 * D_INNER], acc);
    if (l >= 1) acc = fmaf(w2, xb[-1 * 2 * D_INNER], acc);
    acc = fmaf(w3, xb[0], acc);
    float sg = 1.f / (1.f + __expf(-acc));
    xc[(size_t)m * D_INNER + d] = acc * sg;
}

// ---------------- selective scan + gating epilogue ----------------
__global__ __launch_bounds__(128) void scan_kernel(const float* __restrict__ A_log,
                                                   const float* __restrict__ Dp,
                                                   const float* __restrict__ dtv,
                                                   const float* __restrict__ xc,
                                                   const float* __restrict__ xdbl,
                                                   const float* __restrict__ xz,
                                                   float* __restrict__ y) {
    int warp = (blockIdx.x * blockDim.x + threadIdx.x) >> 5;   // 0..1535
    int lane = threadIdx.x & 31;
    int b = warp / (D_INNER / 2);
    int dpair = warp % (D_INNER / 2);
    int half = lane >> 4;
    int n = lane & 15;
    int d = dpair * 2 + half;

    float An = -__expf(A_log[d * D_STATE + n]);
    float Dd = Dp[d];
    float h = 0.f;

    const float* dtp = dtv  + (size_t)b * L_SEQ * D_INNER + d;
    const float* xcp = xc   + (size_t)b * L_SEQ * D_INNER + d;
    const float* bcp = xdbl + (size_t)b * L_SEQ * XPN + DT_RANK + n;
    const float* zp  = xz   + (size_t)b * L_SEQ * (2 * D_INNER) + D_INNER + d;
    float* yp = y + (size_t)b * L_SEQ * D_INNER + d;

    #pragma unroll 4
    for (int l = 0; l < L_SEQ; l++) {
        float dt = dtp[(size_t)l * D_INNER];
        float xv = xcp[(size_t)l * D_INNER];
        float Bn = bcp[(size_t)l * XPN];
        float Cn = bcp[(size_t)l * XPN + D_STATE];

        float e = __expf(dt * An);
        h = fmaf(e, h, dt * xv * Bn);

        float p = h * Cn;
        p += __shfl_xor_sync(0xffffffffu, p, 8);
        p += __shfl_xor_sync(0xffffffffu, p, 4);
        p += __shfl_xor_sync(0xffffffffu, p, 2);
        p += __shfl_xor_sync(0xffffffffu, p, 1);

        if (n == 0) {
            float zv = zp[(size_t)l * (2 * D_INNER)];
            float yv = p + xv * Dd;
            yv *= zv / (1.f + __expf(-zv));
            yp[(size_t)l * D_INNER] = yv;
        }
    }
}

// ---------------- launch ----------------
extern "C" void kernel_launch(void* const* d_in, const int* in_sizes, int n_in,
                              void* d_out, int out_size) {
    const float* x          = (const float*)d_in[0];
    const float* ln_w       = (const float*)d_in[1];
    const float* ln_b       = (const float*)d_in[2];
    const float* in_proj_w  = (const float*)d_in[3];
    const float* conv_w     = (const float*)d_in[4];
    const float* conv_b     = (const float*)d_in[5];
    const float* x_proj_w   = (const float*)d_in[6];
    const float* dt_w       = (const float*)d_in[7];
    const float* dt_b       = (const float*)d_in[8];
    const float* A_log      = (const float*)d_in[9];
    const float* Dp         = (const float*)d_in[10];
    const float* out_proj_w = (const float*)d_in[11];
    float* out = (float*)d_out;

    float *p_xn, *p_xz, *p_xc, *p_xdbl, *p_dtv, *p_y;
    cudaGetSymbolAddress((void**)&p_xn,   g_xn);
    cudaGetSymbolAddress((void**)&p_xz,   g_xz);
    cudaGetSymbolAddress((void**)&p_xc,   g_xc);
    cudaGetSymbolAddress((void**)&p_xdbl, g_xdbl);
    cudaGetSymbolAddress((void**)&p_dtv,  g_dtv);
    cudaGetSymbolAddress((void**)&p_y,    g_y);

    // 1) LayerNorm
    ln_kernel<<<dim3(L_SEQ / 64, B_SZ), 256>>>(x, ln_w, ln_b, p_xn);

    // 2) in_proj: (16384,384) x (1536,384)^T -> (16384,1536)
    gemm2_kernel<<<dim3(2 * D_INNER / BN, M_TOTAL / BM), 256>>>(
        p_xn, DIMC, DIMC, in_proj_w, DIMC, 2 * D_INNER, p_xz, 2 * D_INNER, 0, nullptr);

    // 3) depthwise conv + silu
    {
        int total = M_TOTAL * D_INNER;
        conv_silu_kernel<<<(total + 255) / 256, 256>>>(conv_w, conv_b, p_xz, p_xc);
    }

    // 4) x_proj: (16384,768) x (56,768)^T -> (16384,56)
    gemm2_kernel<<<dim3((XPN + BN - 1) / BN, M_TOTAL / BM), 256>>>(
        p_xc, D_INNER, D_INNER, x_proj_w, D_INNER, XPN, p_xdbl, XPN, 0, nullptr);

    // 5) dt: (16384,24) x (768,24)^T + bias, softplus -> (16384,768)
    gemm2_kernel<<<dim3(D_INNER / BN, M_TOTAL / BM), 256>>>(
        p_xdbl, XPN, DT_RANK, dt_w, DT_RANK, D_INNER, p_dtv, D_INNER, 1, dt_b);

    // 6) selective scan + gating -> y (16384,768)
    scan_kernel<<<(B_SZ * (D_INNER / 2) * 32) / 128, 128>>>(
        A_log, Dp, p_dtv, p_xc, p_xdbl, p_xz, p_y);

    // 7) out_proj: (16384,768) x (384,768)^T -> out (B,C,L) transposed store
    gemm2_kernel<<<dim3(DIMC / BN, M_TOTAL / BM), 256>>>(
        p_y, D_INNER, D_INNER, out_proj_w, D_INNER, DIMC, out, 2 * D_INNER /*unused*/, 2, nullptr);
}

// round 3
// speedup vs baseline: 3.7093x; 3.5988x over previous
#include <cuda_runtime.h>
#include <cstdint>

#define B_SZ 4
#define DIMC 384
#define L_SEQ 4096
#define D_INNER 768
#define D_STATE 16
#define DT_RANK 24
#define XPN 56                      // DT_RANK + 2*D_STATE
#define M_TOTAL (B_SZ * L_SEQ)      // 16384

// ---------------- scratch (no allocations allowed) ----------------
__device__ float g_xn[(size_t)M_TOTAL * DIMC];
__device__ float g_xz[(size_t)M_TOTAL * 2 * D_INNER];
__device__ float g_xc[(size_t)M_TOTAL * D_INNER];
__device__ float g_xdbl[(size_t)M_TOTAL * XPN];
__device__ float g_dtv[(size_t)M_TOTAL * D_INNER];
__device__ float g_y[(size_t)M_TOTAL * D_INNER];

// ---------------- LayerNorm: x (B,C,L) -> xn (B*L, C) ----------------
__global__ __launch_bounds__(256) void ln_kernel(const float* __restrict__ x,
                                                 const float* __restrict__ w,
                                                 const float* __restrict__ bsh,
                                                 float* __restrict__ xn) {
    int b  = blockIdx.y;
    int l0 = blockIdx.x * 64;
    int tid = threadIdx.x;
    int ll = tid & 63;
    int cg = tid >> 6;

    __shared__ float ssum[4][64];
    __shared__ float ssq[4][64];
    __shared__ float smean[64];
    __shared__ float srstd[64];
    __shared__ float st[16][65];

    const float* xb = x + (size_t)b * DIMC * L_SEQ;

    float s = 0.f, sq = 0.f;
    for (int c = cg; c < DIMC; c += 4) {
        float v = xb[(size_t)c * L_SEQ + l0 + ll];
        s += v; sq += v * v;
    }
    ssum[cg][ll] = s; ssq[cg][ll] = sq;
    __syncthreads();
    if (tid < 64) {
        float S = ssum[0][tid] + ssum[1][tid] + ssum[2][tid] + ssum[3][tid];
        float Q = ssq[0][tid] + ssq[1][tid] + ssq[2][tid] + ssq[3][tid];
        float mu = S * (1.f / DIMC);
        float var = Q * (1.f / DIMC) - mu * mu;
        smean[tid] = mu;
        srstd[tid] = rsqrtf(var + 1e-5f);
    }
    __syncthreads();

    for (int c0 = 0; c0 < DIMC; c0 += 16) {
        #pragma unroll
        for (int r = 0; r < 4; r++) {
            int c = c0 + cg + r * 4;
            float v = xb[(size_t)c * L_SEQ + l0 + ll];
            st[cg + r * 4][ll] = (v - smean[ll]) * srstd[ll] * w[c] + bsh[c];
        }
        __syncthreads();
        int c2 = tid & 15, lr = tid >> 4;
        #pragma unroll
        for (int p = 0; p < 4; p++) {
            int l = lr + p * 16;
            xn[((size_t)b * L_SEQ + l0 + l) * DIMC + c0 + c2] = st[c2][l];
        }
        __syncthreads();
    }
}

// ---------------- fp32 tiled GEMM, 128x128x16, 256 thr, double-buffered ----------------
#define BM 128
#define BN 128
#define BKK 16
#define PAD 4

__global__ __launch_bounds__(256, 2) void gemm2_kernel(
    const float* __restrict__ A, int lda, int K,
    const float* __restrict__ W, int ldw, int N,
    float* __restrict__ C, int ldc, int mode,
    const float* __restrict__ bias) {

    __shared__ float As[2][BKK][BM + PAD];
    __shared__ float Bs[2][BKK][BN + PAD];

    int tid = threadIdx.x;
    int m0 = blockIdx.y * BM;
    int n0 = blockIdx.x * BN;
    int tm = tid & 15;
    int tn = tid >> 4;

    int lr = tid >> 2;
    int lk = (tid & 3) * 4;

    float4 pa[2], pb[2];
    int nt = (K + BKK - 1) / BKK;

    {
        int kk = lk;
        #pragma unroll
        for (int r = 0; r < 2; r++) {
            int m = lr + r * 64;
            float4 v = make_float4(0.f, 0.f, 0.f, 0.f);
            if (kk < K) v = *(const float4*)&A[(size_t)(m0 + m) * lda + kk];
            pa[r] = v;
            float4 u = make_float4(0.f, 0.f, 0.f, 0.f);
            if (kk < K && (n0 + m) < N) u = *(const float4*)&W[(size_t)(n0 + m) * ldw + kk];
            pb[r] = u;
        }
    }

    float acc[8][8];
    #pragma unroll
    for (int i = 0; i < 8; i++)
        #pragma unroll
        for (int j = 0; j < 8; j++) acc[i][j] = 0.f;

    for (int t = 0; t < nt; t++) {
        int buf = t & 1;
        #pragma unroll
        for (int r = 0; r < 2; r++) {
            int m = lr + r * 64;
            As[buf][lk + 0][m] = pa[r].x;
            As[buf][lk + 1][m] = pa[r].y;
            As[buf][lk + 2][m] = pa[r].z;
            As[buf][lk + 3][m] = pa[r].w;
            Bs[buf][lk + 0][m] = pb[r].x;
            Bs[buf][lk + 1][m] = pb[r].y;
            Bs[buf][lk + 2][m] = pb[r].z;
            Bs[buf][lk + 3][m] = pb[r].w;
        }
        __syncthreads();

        if (t + 1 < nt) {
            int kk = (t + 1) * BKK + lk;
            #pragma unroll
            for (int r = 0; r < 2; r++) {
                int m = lr + r * 64;
                float4 v = make_float4(0.f, 0.f, 0.f, 0.f);
                if (kk < K) v = *(const float4*)&A[(size_t)(m0 + m) * lda + kk];
                pa[r] = v;
                float4 u = make_float4(0.f, 0.f, 0.f, 0.f);
                if (kk < K && (n0 + m) < N) u = *(const float4*)&W[(size_t)(n0 + m) * ldw + kk];
                pb[r] = u;
            }
        }

        const float (*Ab)[BM + PAD] = As[buf];
        const float (*Bb)[BN + PAD] = Bs[buf];
        #pragma unroll
        for (int k = 0; k < BKK; k++) {
            float a[8], b[8];
            *(float4*)&a[0] = *(const float4*)&Ab[k][tm * 4];
            *(float4*)&a[4] = *(const float4*)&Ab[k][64 + tm * 4];
            *(float4*)&b[0] = *(const float4*)&Bb[k][tn * 4];
            *(float4*)&b[4] = *(const float4*)&Bb[k][64 + tn * 4];
            #pragma unroll
            for (int i = 0; i < 8; i++)
                #pragma unroll
                for (int j = 0; j < 8; j++)
                    acc[i][j] = fmaf(a[i], b[j], acc[i][j]);
        }
        __syncthreads();
    }

    if (mode == 2) {
        int b = m0 >> 12;
        int lbase = m0 & (L_SEQ - 1);
        #pragma unroll
        for (int jh = 0; jh < 2; jh++) {
            #pragma unroll
            for (int j4 = 0; j4 < 4; j4++) {
                int j = jh * 4 + j4;
                int n = n0 + jh * 64 + tn * 4 + j4;
                if (n < N) {
                    float* dst = C + ((size_t)b * DIMC + n) * L_SEQ + lbase;
                    #pragma unroll
                    for (int ih = 0; ih < 2; ih++) {
                        float4 v = make_float4(acc[ih * 4 + 0][j], acc[ih * 4 + 1][j],
                                               acc[ih * 4 + 2][j], acc[ih * 4 + 3][j]);
                        *(float4*)&dst[ih * 64 + tm * 4] = v;
                    }
                }
            }
        }
    } else {
        #pragma unroll
        for (int ih = 0; ih < 2; ih++) {
            #pragma unroll
            for (int i4 = 0; i4 < 4; i4++) {
                int i = ih * 4 + i4;
                int m = m0 + ih * 64 + tm * 4 + i4;
                #pragma unroll
                for (int jh = 0; jh < 2; jh++) {
                    int n = n0 + jh * 64 + tn * 4;
                    if (n < N) {
                        float4 v = make_float4(acc[i][jh * 4 + 0], acc[i][jh * 4 + 1],
                                               acc[i][jh * 4 + 2], acc[i][jh * 4 + 3]);
                        if (mode == 1) {
                            float* vv = (float*)&v;
                            #pragma unroll
                            for (int j = 0; j < 4; j++) {
                                float z = vv[j] + bias[n + j];
                                vv[j] = fmaxf(z, 0.f) + log1pf(__expf(-fabsf(z)));
                            }
                        }
                        if (n + 3 < N) {
                            *(float4*)&C[(size_t)m * ldc + n] = v;
                        } else {
                            float* vv = (float*)&v;
                            #pragma unroll
                            for (int j = 0; j < 4; j++)
                                if (n + j < N) C[(size_t)m * ldc + n + j] = vv[j];
                        }
                    }
                }
            }
        }
    }
}

// ---------------- depthwise causal conv1d (k=4) + SiLU ----------------
__global__ __launch_bounds__(256) void conv_silu_kernel(const float* __restrict__ cw,
                                                        const float* __restrict__ cb,
                                                        const float* __restrict__ xz,
                                                        float* __restrict__ xc) {
    int idx = blockIdx.x * blockDim.x + threadIdx.x;
    if (idx >= M_TOTAL * D_INNER) return;
    int d = idx % D_INNER;
    int m = idx / D_INNER;
    int l = m & (L_SEQ - 1);

    float w0 = cw[d * 4 + 0], w1 = cw[d * 4 + 1];
    float w2 = cw[d * 4 + 2], w3 = cw[d * 4 + 3];

    const float* xb = xz + (size_t)m * (2 * D_INNER) + d;
    float acc = cb[d];
    if (l >= 3) acc = fmaf(w0, xb[-3 * 2 * D_INNER], acc);
    if (l >= 2) acc = fmaf(w1, xb[-2 * 2 * D_INNER], acc);
    if (l >= 1) acc = fmaf(w2, xb[-1 * 2 * D_INNER], acc);
    acc = fmaf(w3, xb[0], acc);
    float sg = 1.f / (1.f + __expf(-acc));
    xc[(size_t)m * D_INNER + d] = acc * sg;
}

// ---------------- selective scan v2: smem-staged, chunked ----------------
// grid (48, 4): block handles one batch b, channels [16g, 16g+16).
// 256 threads = 8 warps; warp w owns channels 2w, 2w+1; lane = half*16 + n.
// Per chunk of 64 steps: bulk-coalesced load of B/C/dt/x/z into double-buffered
// smem (prefetched one chunk ahead in registers); inner loop all-smem.
#define SCH 64
#define NCHUNK (L_SEQ / SCH)

__global__ __launch_bounds__(256) void scan2_kernel(const float* __restrict__ A_log,
                                                    const float* __restrict__ Dp,
                                                    const float* __restrict__ dtv,
                                                    const float* __restrict__ xc,
                                                    const float* __restrict__ xdbl,
                                                    const float* __restrict__ xz,
                                                    float* __restrict__ y) {
    int b = blockIdx.y;
    int g = blockIdx.x;
    int d0 = g * 16;
    int tid = threadIdx.x;
    size_t bL = (size_t)b * L_SEQ;

    __shared__ float sBC[2][SCH][32];   // [l][0..15]=B, [l][16..31]=C
    __shared__ float sD[2][SCH][16];
    __shared__ float sX[2][SCH][16];
    __shared__ float sZ[2][SCH][16];
    __shared__ float sY[SCH][16];

    int lane = tid & 31;
    int w = tid >> 5;
    int half = lane >> 4;
    int n = lane & 15;
    int dl = 2 * w + half;

    float An = -__expf(A_log[(d0 + dl) * D_STATE + n]);
    float Dd = Dp[d0 + (tid & 15)];     // for flush phase (dd = tid&15 there)
    float h = 0.f;

    float rBC[8], rD[4], rX[4], rZ[4];

    // prefetch chunk 0
    {
        #pragma unroll
        for (int i = 0; i < 8; i++) {
            int idx = tid + i * 256;
            int l = idx >> 5, j = idx & 31;
            rBC[i] = xdbl[(bL + l) * XPN + DT_RANK + j];
        }
        #pragma unroll
        for (int i = 0; i < 4; i++) {
            int idx = tid + i * 256;
            int l = idx >> 4, dd = idx & 15;
            size_t row = bL + l;
            rD[i] = dtv[row * D_INNER + d0 + dd];
            rX[i] = xc[row * D_INNER + d0 + dd];
            rZ[i] = xz[row * 2 * D_INNER + D_INNER + d0 + dd];
        }
    }

    for (int c = 0; c < NCHUNK; c++) {
        int buf = c & 1;
        // stage registers -> smem
        #pragma unroll
        for (int i = 0; i < 8; i++) {
            int idx = tid + i * 256;
            sBC[buf][idx >> 5][idx & 31] = rBC[i];
        }
        #pragma unroll
        for (int i = 0; i < 4; i++) {
            int idx = tid + i * 256;
            int l = idx >> 4, dd = idx & 15;
            sD[buf][l][dd] = rD[i];
            sX[buf][l][dd] = rX[i];
            sZ[buf][l][dd] = rZ[i];
        }
        __syncthreads();

        // prefetch next chunk
        if (c + 1 < NCHUNK) {
            int l0n = (c + 1) * SCH;
            #pragma unroll
            for (int i = 0; i < 8; i++) {
                int idx = tid + i * 256;
                int l = idx >> 5, j = idx & 31;
                rBC[i] = xdbl[(bL + l0n + l) * XPN + DT_RANK + j];
            }
            #pragma unroll
            for (int i = 0; i < 4; i++) {
                int idx = tid + i * 256;
                int l = idx >> 4, dd = idx & 15;
                size_t row = bL + l0n + l;
                rD[i] = dtv[row * D_INNER + d0 + dd];
                rX[i] = xc[row * D_INNER + d0 + dd];
                rZ[i] = xz[row * 2 * D_INNER + D_INNER + d0 + dd];
            }
        }

        // scan 64 steps from smem
        #pragma unroll 4
        for (int l = 0; l < SCH; l++) {
            float dt = sD[buf][l][dl];
            float xv = sX[buf][l][dl];
            float Bn = sBC[buf][l][n];
            float Cn = sBC[buf][l][16 + n];
            float e = __expf(dt * An);
            h = fmaf(e, h, dt * xv * Bn);
            float p = h * Cn;
            p += __shfl_xor_sync(0xffffffffu, p, 8);
            p += __shfl_xor_sync(0xffffffffu, p, 4);
            p += __shfl_xor_sync(0xffffffffu, p, 2);
            p += __shfl_xor_sync(0xffffffffu, p, 1);
            if (n == 0) sY[l][dl] = p;
        }
        __syncthreads();

        // flush y chunk (gate + skip), coalesced
        int l0 = c * SCH;
        #pragma unroll
        for (int i = 0; i < 4; i++) {
            int idx = tid + i * 256;
            int l = idx >> 4, dd = idx & 15;
            float p = sY[l][dd];
            float xv = sX[buf][l][dd];
            float zv = sZ[buf][l][dd];
            float yv = fmaf(xv, Dd, p);
            yv *= zv / (1.f + __expf(-zv));
            y[(bL + l0 + l) * D_INNER + d0 + dd] = yv;
        }
        // no extra sync needed: next iter writes the OTHER smem buffer, and
        // sY is rewritten only after the next __syncthreads().
    }
}

// ---------------- launch ----------------
extern "C" void kernel_launch(void* const* d_in, const int* in_sizes, int n_in,
                              void* d_out, int out_size) {
    const float* x          = (const float*)d_in[0];
    const float* ln_w       = (const float*)d_in[1];
    const float* ln_b       = (const float*)d_in[2];
    const float* in_proj_w  = (const float*)d_in[3];
    const float* conv_w     = (const float*)d_in[4];
    const float* conv_b     = (const float*)d_in[5];
    const float* x_proj_w   = (const float*)d_in[6];
    const float* dt_w       = (const float*)d_in[7];
    const float* dt_b       = (const float*)d_in[8];
    const float* A_log      = (const float*)d_in[9];
    const float* Dp         = (const float*)d_in[10];
    const float* out_proj_w = (const float*)d_in[11];
    float* out = (float*)d_out;

    float *p_xn, *p_xz, *p_xc, *p_xdbl, *p_dtv, *p_y;
    cudaGetSymbolAddress((void**)&p_xn,   g_xn);
    cudaGetSymbolAddress((void**)&p_xz,   g_xz);
    cudaGetSymbolAddress((void**)&p_xc,   g_xc);
    cudaGetSymbolAddress((void**)&p_xdbl, g_xdbl);
    cudaGetSymbolAddress((void**)&p_dtv,  g_dtv);
    cudaGetSymbolAddress((void**)&p_y,    g_y);

    // 1) LayerNorm
    ln_kernel<<<dim3(L_SEQ / 64, B_SZ), 256>>>(x, ln_w, ln_b, p_xn);

    // 2) in_proj
    gemm2_kernel<<<dim3(2 * D_INNER / BN, M_TOTAL / BM), 256>>>(
        p_xn, DIMC, DIMC, in_proj_w, DIMC, 2 * D_INNER, p_xz, 2 * D_INNER, 0, nullptr);

    // 3) depthwise conv + silu
    {
        int total = M_TOTAL * D_INNER;
        conv_silu_kernel<<<(total + 255) / 256, 256>>>(conv_w, conv_b, p_xz, p_xc);
    }

    // 4) x_proj
    gemm2_kernel<<<dim3((XPN + BN - 1) / BN, M_TOTAL / BM), 256>>>(
        p_xc, D_INNER, D_INNER, x_proj_w, D_INNER, XPN, p_xdbl, XPN, 0, nullptr);

    // 5) dt + softplus
    gemm2_kernel<<<dim3(D_INNER / BN, M_TOTAL / BM), 256>>>(
        p_xdbl, XPN, DT_RANK, dt_w, DT_RANK, D_INNER, p_dtv, D_INNER, 1, dt_b);

    // 6) selective scan v2
    scan2_kernel<<<dim3(D_INNER / 16, B_SZ), 256>>>(
        A_log, Dp, p_dtv, p_xc, p_xdbl, p_xz, p_y);

    // 7) out_proj (transposed store)
    gemm2_kernel<<<dim3(DIMC / BN, M_TOTAL / BM), 256>>>(
        p_y, D_INNER, D_INNER, out_proj_w, D_INNER, DIMC, out, 0, 2, nullptr);
}

// round 5
// speedup vs baseline: 4.8162x; 1.2984x over previous
#include <cuda_runtime.h>
#include <cuda_bf16.h>
#include <cstdint>

#define B_SZ 4
#define DIMC 384
#define L_SEQ 4096
#define D_INNER 768
#define D_STATE 16
#define DT_RANK 24
#define XPN 56
#define M_TOTAL (B_SZ * L_SEQ)      // 16384

// ---------------- scratch (no allocations allowed) ----------------
__device__ float g_xz[(size_t)M_TOTAL * 2 * D_INNER];
__device__ float g_xc[(size_t)M_TOTAL * D_INNER];
__device__ float g_xdbl[(size_t)M_TOTAL * XPN];
__device__ float g_dtv[(size_t)M_TOTAL * D_INNER];

__device__ __nv_bfloat16 g_xn_hi[(size_t)M_TOTAL * DIMC];
__device__ __nv_bfloat16 g_xn_lo[(size_t)M_TOTAL * DIMC];
__device__ __nv_bfloat16 g_y_hi[(size_t)M_TOTAL * D_INNER];
__device__ __nv_bfloat16 g_y_lo[(size_t)M_TOTAL * D_INNER];
__device__ __nv_bfloat16 g_wi_hi[(size_t)2 * D_INNER * DIMC];
__device__ __nv_bfloat16 g_wi_lo[(size_t)2 * D_INNER * DIMC];
__device__ __nv_bfloat16 g_wo_hi[(size_t)DIMC * D_INNER];
__device__ __nv_bfloat16 g_wo_lo[(size_t)DIMC * D_INNER];

// ---------------- small PTX helpers (all base-target, sm_80+) ----------------
__device__ __forceinline__ uint32_t smem_u32(const void* p) {
    uint32_t a;
    asm("{ .reg .u64 t; cvta.to.shared.u64 t, %1; cvt.u32.u64 %0, t; }" : "=r"(a) : "l"(p));
    return a;
}
__device__ __forceinline__ void cpasync16(uint32_t sa, const void* g) {
    asm volatile("cp.async.cg.shared.global [%0], [%1], 16;" :: "r"(sa), "l"(g) : "memory");
}
__device__ __forceinline__ void cp_commit() {
    asm volatile("cp.async.commit_group;" ::: "memory");
}
template <int N> __device__ __forceinline__ void cp_wait() {
    asm volatile("cp.async.wait_group %0;" :: "n"(N) : "memory");
}
__device__ __forceinline__ void ldsm4(uint32_t* r, uint32_t addr) {
    asm volatile("ldmatrix.sync.aligned.m8n8.x4.shared.b16 {%0,%1,%2,%3}, [%4];"
                 : "=r"(r[0]), "=r"(r[1]), "=r"(r[2]), "=r"(r[3]) : "r"(addr));
}
__device__ __forceinline__ void mma16816(float* d, const uint32_t* a, const uint32_t* b) {
    asm volatile(
        "mma.sync.aligned.m16n8k16.row.col.f32.bf16.bf16.f32 "
        "{%0,%1,%2,%3}, {%4,%5,%6,%7}, {%8,%9}, {%0,%1,%2,%3};"
        : "+f"(d[0]), "+f"(d[1]), "+f"(d[2]), "+f"(d[3])
        : "r"(a[0]), "r"(a[1]), "r"(a[2]), "r"(a[3]), "r"(b[0]), "r"(b[1]));
}

// ---------------- bf16-split mma.sync GEMM ----------------
// C[m,n] = sum_k A[m,k]*W[n,k];  A = Ah+Al, W = Bh+Bl (bf16 pairs, row-major [., K])
// CTA tile 128x128, 8 warps each 32x64, BK=32, cp.async double buffer.
// mode 0: C[m*ldc+n] fp32;  mode 2: out[(b*DIMC+n)*L_SEQ + l], m = b*L_SEQ + l.
#define LDSROW 40                 // halves per smem row (80B, 16B aligned, conflict-free)
#define TILE_H (128 * LDSROW)     // halves per tile (5120)
#define BUF_B  (4 * TILE_H * 2)   // bytes per buffer (40960)

__global__ __launch_bounds__(256, 1) void mmagemm_kernel(
    const __nv_bfloat16* __restrict__ Ah, const __nv_bfloat16* __restrict__ Al,
    const __nv_bfloat16* __restrict__ Bh, const __nv_bfloat16* __restrict__ Bl,
    int K, float* __restrict__ C, int ldc, int mode) {

    extern __shared__ __align__(16) uint8_t dsm[];
    uint32_t dsm_u = smem_u32(dsm);

    int tid = threadIdx.x;
    int wid = tid >> 5;
    int lane = tid & 31;
    int warp_m = wid & 3;     // 4 warps over m (4*32 = 128)
    int warp_n = wid >> 2;    // 2 warps over n (2*64 = 128)
    int m0 = blockIdx.y * 128;
    int n0 = blockIdx.x * 128;

    float acc[2][8][4];
    #pragma unroll
    for (int mt = 0; mt < 2; mt++)
        #pragma unroll
        for (int nt = 0; nt < 8; nt++)
            #pragma unroll
            for (int q = 0; q < 4; q++) acc[mt][nt][q] = 0.f;

    int nchunks = K >> 5;

    // chunk loader: 4 tiles (Ah,Al,Bh,Bl) of 128x32 bf16, 8 cp.async/thread
    auto load_chunk = [&](int c, int buf) {
        int kc = c << 5;
        uint32_t sbase = dsm_u + buf * BUF_B;
        #pragma unroll
        for (int i = 0; i < 8; i++) {
            int u = tid + i * 256;
            int tile = u >> 9;
            int v = u & 511;
            int row = v >> 2;
            int seg = v & 3;
            uint32_t sa = sbase + (tile * TILE_H + row * LDSROW + seg * 8) * 2;
            const __nv_bfloat16* g;
            if (tile == 0)      g = Ah + (size_t)(m0 + row) * K + kc + seg * 8;
            else if (tile == 1) g = Al + (size_t)(m0 + row) * K + kc + seg * 8;
            else if (tile == 2) g = Bh + (size_t)(n0 + row) * K + kc + seg * 8;
            else                g = Bl + (size_t)(n0 + row) * K + kc + seg * 8;
            cpasync16(sa, g);
        }
        cp_commit();
    };

    load_chunk(0, 0);

    for (int c = 0; c < nchunks; c++) {
        if (c + 1 < nchunks) {
            load_chunk(c + 1, (c + 1) & 1);
            cp_wait<1>();
        } else {
            cp_wait<0>();
        }
        __syncthreads();

        uint32_t base = dsm_u + (c & 1) * BUF_B;
        #pragma unroll
        for (int kk = 0; kk < 32; kk += 16) {
            uint32_t aH[2][4], aL[2][4], bH[8][2], bL[8][2];
            // A fragments: lanes 0-7 -> m0-7@k0, 8-15 -> m8-15@k0, 16-23 -> m0-7@k8, 24-31 -> m8-15@k8
            {
                int arow = warp_m * 32 + (lane & 15);
                int ak = kk + (lane >> 4) * 8;
                #pragma unroll
                for (int mt = 0; mt < 2; mt++) {
                    uint32_t addr = base + ((arow + mt * 16) * LDSROW + ak) * 2;
                    ldsm4(aH[mt], addr);
                    ldsm4(aL[mt], addr + TILE_H * 2);
                }
            }
            // B fragments: lanes 0-7 -> n0-7@k0, 8-15 -> n0-7@k8, 16-23 -> n8-15@k0, 24-31 -> n8-15@k8
            {
                int brow = warp_n * 64 + (lane & 7) + (lane >> 4) * 8;
                int bk = kk + ((lane >> 3) & 1) * 8;
                #pragma unroll
                for (int g2 = 0; g2 < 4; g2++) {
                    uint32_t addr = base + 2 * TILE_H * 2 + ((brow + g2 * 16) * LDSROW + bk) * 2;
                    uint32_t r[4];
                    ldsm4(r, addr);
                    bH[g2 * 2][0] = r[0]; bH[g2 * 2][1] = r[1];
                    bH[g2 * 2 + 1][0] = r[2]; bH[g2 * 2 + 1][1] = r[3];
                    ldsm4(r, addr + TILE_H * 2);
                    bL[g2 * 2][0] = r[0]; bL[g2 * 2][1] = r[1];
                    bL[g2 * 2 + 1][0] = r[2]; bL[g2 * 2 + 1][1] = r[3];
                }
            }
            #pragma unroll
            for (int mt = 0; mt < 2; mt++)
                #pragma unroll
                for (int nt = 0; nt < 8; nt++) {
                    mma16816(acc[mt][nt], aH[mt], bH[nt]);
                    mma16816(acc[mt][nt], aH[mt], bL[nt]);
                    mma16816(acc[mt][nt], aL[mt], bH[nt]);
                }
        }
        __syncthreads();
    }

    // epilogue
    if (mode == 0) {
        #pragma unroll
        for (int mt = 0; mt < 2; mt++) {
            int m = m0 + warp_m * 32 + mt * 16 + (lane >> 2);
            #pragma unroll
            for (int nt = 0; nt < 8; nt++) {
                int n = n0 + warp_n * 64 + nt * 8 + (lane & 3) * 2;
                float2 v0 = make_float2(acc[mt][nt][0], acc[mt][nt][1]);
                float2 v1 = make_float2(acc[mt][nt][2], acc[mt][nt][3]);
                *(float2*)&C[(size_t)m * ldc + n] = v0;
                *(float2*)&C[(size_t)(m + 8) * ldc + n] = v1;
            }
        }
    } else {
        // mode 2: transpose through smem, store to out (B, DIMC, L_SEQ)
        float* sT = (float*)dsm;   // [128 n][132 m]
        #pragma unroll
        for (int mt = 0; mt < 2; mt++) {
            int ml = warp_m * 32 + mt * 16 + (lane >> 2);
            #pragma unroll
            for (int nt = 0; nt < 8; nt++) {
                int nl = warp_n * 64 + nt * 8 + (lane & 3) * 2;
                sT[nl * 132 + ml]           = acc[mt][nt][0];
                sT[(nl + 1) * 132 + ml]     = acc[mt][nt][1];
                sT[nl * 132 + ml + 8]       = acc[mt][nt][2];
                sT[(nl + 1) * 132 + ml + 8] = acc[mt][nt][3];
            }
        }
        __syncthreads();
        int b = m0 >> 12;
        int l0 = m0 & (L_SEQ - 1);
        int n = tid >> 1;
        int lh = (tid & 1) * 64;
        float* dst = C + ((size_t)b * DIMC + n0 + n) * L_SEQ + l0 + lh;
        const float* src = sT + n * 132 + lh;
        #pragma unroll
        for (int q = 0; q < 16; q++)
            *(float4*)(dst + q * 4) = *(const float4*)(src + q * 4);
    }
}

// ---------------- fp32 -> bf16 hi/lo split ----------------
__global__ __launch_bounds__(256) void cvt_kernel(const float* __restrict__ s,
                                                  __nv_bfloat16* __restrict__ hi,
                                                  __nv_bfloat16* __restrict__ lo, int n4) {
    int i = blockIdx.x * blockDim.x + threadIdx.x;
    if (i >= n4) return;
    float4 v = *(const float4*)(s + (size_t)i * 4);
    float vv[4] = {v.x, v.y, v.z, v.w};
    #pragma unroll
    for (int j = 0; j < 4; j++) {
        __nv_bfloat16 h = __float2bfloat16(vv[j]);
        hi[(size_t)i * 4 + j] = h;
        lo[(size_t)i * 4 + j] = __float2bfloat16(vv[j] - __bfloat162float(h));
    }
}

// ---------------- LayerNorm: x (B,C,L) -> xn hi/lo (B*L, C) bf16 ----------------
__global__ __launch_bounds__(256) void ln_kernel(const float* __restrict__ x,
                                                 const float* __restrict__ w,
                                                 const float* __restrict__ bsh,
                                                 __nv_bfloat16* __restrict__ xnh,
                                                 __nv_bfloat16* __restrict__ xnl) {
    int b  = blockIdx.y;
    int l0 = blockIdx.x * 64;
    int tid = threadIdx.x;
    int ll = tid & 63;
    int cg = tid >> 6;

    __shared__ float ssum[4][64];
    __shared__ float ssq[4][64];
    __shared__ float smean[64];
    __shared__ float srstd[64];
    __shared__ float st[16][65];

    const float* xb = x + (size_t)b * DIMC * L_SEQ;

    float s = 0.f, sq = 0.f;
    for (int c = cg; c < DIMC; c += 4) {
        float v = xb[(size_t)c * L_SEQ + l0 + ll];
        s += v; sq += v * v;
    }
    ssum[cg][ll] = s; ssq[cg][ll] = sq;
    __syncthreads();
    if (tid < 64) {
        float S = ssum[0][tid] + ssum[1][tid] + ssum[2][tid] + ssum[3][tid];
        float Q = ssq[0][tid] + ssq[1][tid] + ssq[2][tid] + ssq[3][tid];
        float mu = S * (1.f / DIMC);
        float var = Q * (1.f / DIMC) - mu * mu;
        smean[tid] = mu;
        srstd[tid] = rsqrtf(var + 1e-5f);
    }
    __syncthreads();

    for (int c0 = 0; c0 < DIMC; c0 += 16) {
        #pragma unroll
        for (int r = 0; r < 4; r++) {
            int c = c0 + cg + r * 4;
            float v = xb[(size_t)c * L_SEQ + l0 + ll];
            st[cg + r * 4][ll] = (v - smean[ll]) * srstd[ll] * w[c] + bsh[c];
        }
        __syncthreads();
        int c2 = tid & 15, lr = tid >> 4;
        #pragma unroll
        for (int p = 0; p < 4; p++) {
            int l = lr + p * 16;
            float v = st[c2][l];
            __nv_bfloat16 h = __float2bfloat16(v);
            size_t o = ((size_t)b * L_SEQ + l0 + l) * DIMC + c0 + c2;
            xnh[o] = h;
            xnl[o] = __float2bfloat16(v - __bfloat162float(h));
        }
        __syncthreads();
    }
}

// ---------------- fp32 tiled GEMM (x_proj / dt) ----------------
#define BM 128
#define BN 128
#define BKK 16
#define PAD 4

__global__ __launch_bounds__(256, 2) void gemm2_kernel(
    const float* __restrict__ A, int lda, int K,
    const float* __restrict__ W, int ldw, int N,
    float* __restrict__ C, int ldc, int mode,
    const float* __restrict__ bias) {

    __shared__ float As[2][BKK][BM + PAD];
    __shared__ float Bs[2][BKK][BN + PAD];

    int tid = threadIdx.x;
    int m0 = blockIdx.y * BM;
    int n0 = blockIdx.x * BN;
    int tm = tid & 15;
    int tn = tid >> 4;

    int lr = tid >> 2;
    int lk = (tid & 3) * 4;

    float4 pa[2], pb[2];
    int nt = (K + BKK - 1) / BKK;

    {
        int kk = lk;
        #pragma unroll
        for (int r = 0; r < 2; r++) {
            int m = lr + r * 64;
            float4 v = make_float4(0.f, 0.f, 0.f, 0.f);
            if (kk < K) v = *(const float4*)&A[(size_t)(m0 + m) * lda + kk];
            pa[r] = v;
            float4 u = make_float4(0.f, 0.f, 0.f, 0.f);
            if (kk < K && (n0 + m) < N) u = *(const float4*)&W[(size_t)(n0 + m) * ldw + kk];
            pb[r] = u;
        }
    }

    float acc[8][8];
    #pragma unroll
    for (int i = 0; i < 8; i++)
        #pragma unroll
        for (int j = 0; j < 8; j++) acc[i][j] = 0.f;

    for (int t = 0; t < nt; t++) {
        int buf = t & 1;
        #pragma unroll
        for (int r = 0; r < 2; r++) {
            int m = lr + r * 64;
            As[buf][lk + 0][m] = pa[r].x;
            As[buf][lk + 1][m] = pa[r].y;
            As[buf][lk + 2][m] = pa[r].z;
            As[buf][lk + 3][m] = pa[r].w;
            Bs[buf][lk + 0][m] = pb[r].x;
            Bs[buf][lk + 1][m] = pb[r].y;
            Bs[buf][lk + 2][m] = pb[r].z;
            Bs[buf][lk + 3][m] = pb[r].w;
        }
        __syncthreads();

        if (t + 1 < nt) {
            int kk = (t + 1) * BKK + lk;
            #pragma unroll
            for (int r = 0; r < 2; r++) {
                int m = lr + r * 64;
                float4 v = make_float4(0.f, 0.f, 0.f, 0.f);
                if (kk < K) v = *(const float4*)&A[(size_t)(m0 + m) * lda + kk];
                pa[r] = v;
                float4 u = make_float4(0.f, 0.f, 0.f, 0.f);
                if (kk < K && (n0 + m) < N) u = *(const float4*)&W[(size_t)(n0 + m) * ldw + kk];
                pb[r] = u;
            }
        }

        const float (*Ab)[BM + PAD] = As[buf];
        const float (*Bb)[BN + PAD] = Bs[buf];
        #pragma unroll
        for (int k = 0; k < BKK; k++) {
            float a[8], b[8];
            *(float4*)&a[0] = *(const float4*)&Ab[k][tm * 4];
            *(float4*)&a[4] = *(const float4*)&Ab[k][64 + tm * 4];
            *(float4*)&b[0] = *(const float4*)&Bb[k][tn * 4];
            *(float4*)&b[4] = *(const float4*)&Bb[k][64 + tn * 4];
            #pragma unroll
            for (int i = 0; i < 8; i++)
                #pragma unroll
                for (int j = 0; j < 8; j++)
                    acc[i][j] = fmaf(a[i], b[j], acc[i][j]);
        }
        __syncthreads();
    }

    #pragma unroll
    for (int ih = 0; ih < 2; ih++) {
        #pragma unroll
        for (int i4 = 0; i4 < 4; i4++) {
            int i = ih * 4 + i4;
            int m = m0 + ih * 64 + tm * 4 + i4;
            #pragma unroll
            for (int jh = 0; jh < 2; jh++) {
                int n = n0 + jh * 64 + tn * 4;
                if (n < N) {
                    float4 v = make_float4(acc[i][jh * 4 + 0], acc[i][jh * 4 + 1],
                                           acc[i][jh * 4 + 2], acc[i][jh * 4 + 3]);
                    if (mode == 1) {
                        float* vv = (float*)&v;
                        #pragma unroll
                        for (int j = 0; j < 4; j++) {
                            float z = vv[j] + bias[n + j];
                            vv[j] = fmaxf(z, 0.f) + log1pf(__expf(-fabsf(z)));
                        }
                    }
                    if (n + 3 < N) {
                        *(float4*)&C[(size_t)m * ldc + n] = v;
                    } else {
                        float* vv = (float*)&v;
                        #pragma unroll
                        for (int j = 0; j < 4; j++)
                            if (n + j < N) C[(size_t)m * ldc + n + j] = vv[j];
                    }
                }
            }
        }
    }
}

// ---------------- depthwise causal conv1d (k=4) + SiLU ----------------
__global__ __launch_bounds__(256) void conv_silu_kernel(const float* __restrict__ cw,
                                                        const float* __restrict__ cb,
                                                        const float* __restrict__ xz,
                                                        float* __restrict__ xc) {
    int idx = blockIdx.x * blockDim.x + threadIdx.x;
    if (idx >= M_TOTAL * D_INNER) return;
    int d = idx % D_INNER;
    int m = idx / D_INNER;
    int l = m & (L_SEQ - 1);

    float w0 = cw[d * 4 + 0], w1 = cw[d * 4 + 1];
    float w2 = cw[d * 4 + 2], w3 = cw[d * 4 + 3];

    const float* xb = xz + (size_t)m * (2 * D_INNER) + d;
    float acc = cb[d];
    if (l >= 3) acc = fmaf(w0, xb[-3 * 2 * D_INNER], acc);
    if (l >= 2) acc = fmaf(w1, xb[-2 * 2 * D_INNER], acc);
    if (l >= 1) acc = fmaf(w2, xb[-1 * 2 * D_INNER], acc);
    acc = fmaf(w3, xb[0], acc);
    float sg = 1.f / (1.f + __expf(-acc));
    xc[(size_t)m * D_INNER + d] = acc * sg;
}

// ---------------- selective scan: smem-staged, chunked; writes y hi/lo ----------------
#define SCH 64
#define NCHUNK (L_SEQ / SCH)

__global__ __launch_bounds__(256) void scan2_kernel(const float* __restrict__ A_log,
                                                    const float* __restrict__ Dp,
                                                    const float* __restrict__ dtv,
                                                    const float* __restrict__ xc,
                                                    const float* __restrict__ xdbl,
                                                    const float* __restrict__ xz,
                                                    __nv_bfloat16* __restrict__ yh,
                                                    __nv_bfloat16* __restrict__ yl) {
    int b = blockIdx.y;
    int g = blockIdx.x;
    int d0 = g * 16;
    int tid = threadIdx.x;
    size_t bL = (size_t)b * L_SEQ;

    __shared__ float sBC[2][SCH][32];
    __shared__ float sD[2][SCH][16];
    __shared__ float sX[2][SCH][16];
    __shared__ float sZ[2][SCH][16];
    __shared__ float sY[SCH][16];

    int lane = tid & 31;
    int w = tid >> 5;
    int half = lane >> 4;
    int n = lane & 15;
    int dl = 2 * w + half;

    float An = -__expf(A_log[(d0 + dl) * D_STATE + n]);
    float Dd = Dp[d0 + (tid & 15)];
    float h = 0.f;

    float rBC[8], rD[4], rX[4], rZ[4];

    {
        #pragma unroll
        for (int i = 0; i < 8; i++) {
            int idx = tid + i * 256;
            rBC[i] = xdbl[(bL + (idx >> 5)) * XPN + DT_RANK + (idx & 31)];
        }
        #pragma unroll
        for (int i = 0; i < 4; i++) {
            int idx = tid + i * 256;
            int l = idx >> 4, dd = idx & 15;
            size_t row = bL + l;
            rD[i] = dtv[row * D_INNER + d0 + dd];
            rX[i] = xc[row * D_INNER + d0 + dd];
            rZ[i] = xz[row * 2 * D_INNER + D_INNER + d0 + dd];
        }
    }

    for (int c = 0; c < NCHUNK; c++) {
        int buf = c & 1;
        #pragma unroll
        for (int i = 0; i < 8; i++) {
            int idx = tid + i * 256;
            sBC[buf][idx >> 5][idx & 31] = rBC[i];
        }
        #pragma unroll
        for (int i = 0; i < 4; i++) {
            int idx = tid + i * 256;
            int l = idx >> 4, dd = idx & 15;
            sD[buf][l][dd] = rD[i];
            sX[buf][l][dd] = rX[i];
            sZ[buf][l][dd] = rZ[i];
        }
        __syncthreads();

        if (c + 1 < NCHUNK) {
            int l0n = (c + 1) * SCH;
            #pragma unroll
            for (int i = 0; i < 8; i++) {
                int idx = tid + i * 256;
                rBC[i] = xdbl[(bL + l0n + (idx >> 5)) * XPN + DT_RANK + (idx & 31)];
            }
            #pragma unroll
            for (int i = 0; i < 4; i++) {
                int idx = tid + i * 256;
                int l = idx >> 4, dd = idx & 15;
                size_t row = bL + l0n + l;
                rD[i] = dtv[row * D_INNER + d0 + dd];
                rX[i] = xc[row * D_INNER + d0 + dd];
                rZ[i] = xz[row * 2 * D_INNER + D_INNER + d0 + dd];
            }
        }

        #pragma unroll 4
        for (int l = 0; l < SCH; l++) {
            float dt = sD[buf][l][dl];
            float xv = sX[buf][l][dl];
            float Bn = sBC[buf][l][n];
            float Cn = sBC[buf][l][16 + n];
            float e = __expf(dt * An);
            h = fmaf(e, h, dt * xv * Bn);
            float p = h * Cn;
            p += __shfl_xor_sync(0xffffffffu, p, 8);
            p += __shfl_xor_sync(0xffffffffu, p, 4);
            p += __shfl_xor_sync(0xffffffffu, p, 2);
            p += __shfl_xor_sync(0xffffffffu, p, 1);
            if (n == 0) sY[l][dl] = p;
        }
        __syncthreads();

        int l0 = c * SCH;
        #pragma unroll
        for (int i = 0; i < 4; i++) {
            int idx = tid + i * 256;
            int l = idx >> 4, dd = idx & 15;
            float p = sY[l][dd];
            float xv = sX[buf][l][dd];
            float zv = sZ[buf][l][dd];
            float yv = fmaf(xv, Dd, p);
            yv *= zv / (1.f + __expf(-zv));
            size_t o = (bL + l0 + l) * D_INNER + d0 + dd;
            __nv_bfloat16 hh = __float2bfloat16(yv);
            yh[o] = hh;
            yl[o] = __float2bfloat16(yv - __bfloat162float(hh));
        }
    }
}

// ---------------- launch ----------------
extern "C" void kernel_launch(void* const* d_in, const int* in_sizes, int n_in,
                              void* d_out, int out_size) {
    const float* x          = (const float*)d_in[0];
    const float* ln_w       = (const float*)d_in[1];
    const float* ln_b       = (const float*)d_in[2];
    const float* in_proj_w  = (const float*)d_in[3];
    const float* conv_w     = (const float*)d_in[4];
    const float* conv_b     = (const float*)d_in[5];
    const float* x_proj_w   = (const float*)d_in[6];
    const float* dt_w       = (const float*)d_in[7];
    const float* dt_b       = (const float*)d_in[8];
    const float* A_log      = (const float*)d_in[9];
    const float* Dp         = (const float*)d_in[10];
    const float* out_proj_w = (const float*)d_in[11];
    float* out = (float*)d_out;

    float *p_xz, *p_xc, *p_xdbl, *p_dtv;
    __nv_bfloat16 *p_xnh, *p_xnl, *p_yh, *p_yl, *p_wih, *p_wil, *p_woh, *p_wol;
    cudaGetSymbolAddress((void**)&p_xz,   g_xz);
    cudaGetSymbolAddress((void**)&p_xc,   g_xc);
    cudaGetSymbolAddress((void**)&p_xdbl, g_xdbl);
    cudaGetSymbolAddress((void**)&p_dtv,  g_dtv);
    cudaGetSymbolAddress((void**)&p_xnh,  g_xn_hi);
    cudaGetSymbolAddress((void**)&p_xnl,  g_xn_lo);
    cudaGetSymbolAddress((void**)&p_yh,   g_y_hi);
    cudaGetSymbolAddress((void**)&p_yl,   g_y_lo);
    cudaGetSymbolAddress((void**)&p_wih,  g_wi_hi);
    cudaGetSymbolAddress((void**)&p_wil,  g_wi_lo);
    cudaGetSymbolAddress((void**)&p_woh,  g_wo_hi);
    cudaGetSymbolAddress((void**)&p_wol,  g_wo_lo);

    const int MM_SMEM = 2 * BUF_B;   // 81920 B
    static bool attr_set = false;
    if (!attr_set) {
        cudaFuncSetAttribute(mmagemm_kernel, cudaFuncAttributeMaxDynamicSharedMemorySize, MM_SMEM);
        attr_set = true;
    }

    // 0) weight hi/lo conversion
    {
        int n4i = (2 * D_INNER * DIMC) / 4;
        cvt_kernel<<<(n4i + 255) / 256, 256>>>(in_proj_w, p_wih, p_wil, n4i);
        int n4o = (DIMC * D_INNER) / 4;
        cvt_kernel<<<(n4o + 255) / 256, 256>>>(out_proj_w, p_woh, p_wol, n4o);
    }

    // 1) LayerNorm -> xn hi/lo
    ln_kernel<<<dim3(L_SEQ / 64, B_SZ), 256>>>(x, ln_w, ln_b, p_xnh, p_xnl);

    // 2) in_proj (mma.sync bf16-split): (16384,384)x(1536,384)^T -> xz fp32
    mmagemm_kernel<<<dim3(2 * D_INNER / 128, M_TOTAL / 128), 256, MM_SMEM>>>(
        p_xnh, p_xnl, p_wih, p_wil, DIMC, p_xz, 2 * D_INNER, 0);

    // 3) depthwise conv + silu
    {
        int total = M_TOTAL * D_INNER;
        conv_silu_kernel<<<(total + 255) / 256, 256>>>(conv_w, conv_b, p_xz, p_xc);
    }

    // 4) x_proj (fp32 SIMT)
    gemm2_kernel<<<dim3((XPN + BN - 1) / BN, M_TOTAL / BM), 256>>>(
        p_xc, D_INNER, D_INNER, x_proj_w, D_INNER, XPN, p_xdbl, XPN, 0, nullptr);

    // 5) dt + softplus (fp32 SIMT)
    gemm2_kernel<<<dim3(D_INNER / BN, M_TOTAL / BM), 256>>>(
        p_xdbl, XPN, DT_RANK, dt_w, DT_RANK, D_INNER, p_dtv, D_INNER, 1, dt_b);

    // 6) selective scan -> y hi/lo
    scan2_kernel<<<dim3(D_INNER / 16, B_SZ), 256>>>(
        A_log, Dp, p_dtv, p_xc, p_xdbl, p_xz, p_yh, p_yl);

    // 7) out_proj (mma.sync bf16-split, transposed store)
    mmagemm_kernel<<<dim3(DIMC / 128, M_TOTAL / 128), 256, MM_SMEM>>>(
        p_yh, p_yl, p_woh, p_wol, D_INNER, out, 0, 2);
}

// round 6
// speedup vs baseline: 5.0518x; 1.0489x over previous
#include <cuda_runtime.h>
#include <cuda_bf16.h>
#include <cstdint>

#define B_SZ 4
#define DIMC 384
#define L_SEQ 4096
#define D_INNER 768
#define D_STATE 16
#define DT_RANK 24
#define XPN 56
#define M_TOTAL (B_SZ * L_SEQ)      // 16384

// ---------------- scratch (no allocations allowed) ----------------
__device__ float g_xz[(size_t)M_TOTAL * 2 * D_INNER];
__device__ float g_xc[(size_t)M_TOTAL * D_INNER];
__device__ float g_xdbl[(size_t)M_TOTAL * XPN];
__device__ float g_dtv[(size_t)M_TOTAL * D_INNER];

__device__ __nv_bfloat16 g_xn_hi[(size_t)M_TOTAL * DIMC];
__device__ __nv_bfloat16 g_xn_lo[(size_t)M_TOTAL * DIMC];
__device__ __nv_bfloat16 g_xc_hi[(size_t)M_TOTAL * D_INNER];
__device__ __nv_bfloat16 g_xc_lo[(size_t)M_TOTAL * D_INNER];
__device__ __nv_bfloat16 g_y_hi[(size_t)M_TOTAL * D_INNER];
__device__ __nv_bfloat16 g_y_lo[(size_t)M_TOTAL * D_INNER];
__device__ __nv_bfloat16 g_wi_hi[(size_t)2 * D_INNER * DIMC];
__device__ __nv_bfloat16 g_wi_lo[(size_t)2 * D_INNER * DIMC];
__device__ __nv_bfloat16 g_wo_hi[(size_t)DIMC * D_INNER];
__device__ __nv_bfloat16 g_wo_lo[(size_t)DIMC * D_INNER];
__device__ __nv_bfloat16 g_wx_hi[(size_t)XPN * D_INNER];
__device__ __nv_bfloat16 g_wx_lo[(size_t)XPN * D_INNER];

// ---------------- small PTX helpers (all base-target, sm_80+) ----------------
__device__ __forceinline__ uint32_t smem_u32(const void* p) {
    uint32_t a;
    asm("{ .reg .u64 t; cvta.to.shared.u64 t, %1; cvt.u32.u64 %0, t; }" : "=r"(a) : "l"(p));
    return a;
}
__device__ __forceinline__ void cpasync16(uint32_t sa, const void* g, int sz) {
    asm volatile("cp.async.cg.shared.global [%0], [%1], 16, %2;" :: "r"(sa), "l"(g), "r"(sz) : "memory");
}
__device__ __forceinline__ void cp_commit() {
    asm volatile("cp.async.commit_group;" ::: "memory");
}
template <int N> __device__ __forceinline__ void cp_wait() {
    asm volatile("cp.async.wait_group %0;" :: "n"(N) : "memory");
}
__device__ __forceinline__ void ldsm4(uint32_t* r, uint32_t addr) {
    asm volatile("ldmatrix.sync.aligned.m8n8.x4.shared.b16 {%0,%1,%2,%3}, [%4];"
                 : "=r"(r[0]), "=r"(r[1]), "=r"(r[2]), "=r"(r[3]) : "r"(addr));
}
__device__ __forceinline__ void mma16816(float* d, const uint32_t* a, const uint32_t* b) {
    asm volatile(
        "mma.sync.aligned.m16n8k16.row.col.f32.bf16.bf16.f32 "
        "{%0,%1,%2,%3}, {%4,%5,%6,%7}, {%8,%9}, {%0,%1,%2,%3};"
        : "+f"(d[0]), "+f"(d[1]), "+f"(d[2]), "+f"(d[3])
        : "r"(a[0]), "r"(a[1]), "r"(a[2]), "r"(a[3]), "r"(b[0]), "r"(b[1]));
}

// ---------------- bf16-split mma.sync GEMM (512 thr, 16 warps, 32x32/warp) ----------------
// C[m,n] = sum_k A[m,k]*W[n,k];  A = Ah+Al, W = Bh+Bl (bf16 pairs, row-major [., K])
// CTA tile 128x128, BK=32, cp.async double buffer. Nn = true N (B rows >= Nn zero-filled).
// mode 0: C[m*ldc+n] fp32 (mask n<Nn);  mode 2: out[(b*DIMC+n)*L_SEQ + l], m = b*L_SEQ + l.
#define LDSROW 40                 // halves per smem row (80B, 16B aligned, conflict-free)
#define TILE_H (128 * LDSROW)     // halves per tile (5120)
#define BUF_B  (4 * TILE_H * 2)   // bytes per buffer (40960)

__global__ __launch_bounds__(512, 1) void mmagemm_kernel(
    const __nv_bfloat16* __restrict__ Ah, const __nv_bfloat16* __restrict__ Al,
    const __nv_bfloat16* __restrict__ Bh, const __nv_bfloat16* __restrict__ Bl,
    int K, int Nn, float* __restrict__ C, int ldc, int mode) {

    extern __shared__ __align__(16) uint8_t dsm[];
    uint32_t dsm_u = smem_u32(dsm);

    int tid = threadIdx.x;
    int wid = tid >> 5;
    int lane = tid & 31;
    int warp_m = wid & 3;     // 4 warps over m (4*32 = 128)
    int warp_n = wid >> 2;    // 4 warps over n (4*32 = 128)
    int m0 = blockIdx.y * 128;
    int n0 = blockIdx.x * 128;

    float acc[2][4][4];
    #pragma unroll
    for (int mt = 0; mt < 2; mt++)
        #pragma unroll
        for (int nt = 0; nt < 4; nt++)
            #pragma unroll
            for (int q = 0; q < 4; q++) acc[mt][nt][q] = 0.f;

    int nchunks = K >> 5;

    // chunk loader: 4 tiles (Ah,Al,Bh,Bl) of 128x32 bf16, 4 cp.async per thread
    auto load_chunk = [&](int c) {
        int kc = c << 5;
        uint32_t sbase = dsm_u + (c & 1) * BUF_B;
        #pragma unroll
        for (int i = 0; i < 4; i++) {
            int u = tid + i * 512;
            int tile = u >> 9;
            int v = u & 511;
            int row = v >> 2;
            int seg = v & 3;
            uint32_t sa = sbase + (tile * TILE_H + row * LDSROW + seg * 8) * 2;
            const __nv_bfloat16* g;
            int sz = 16;
            if (tile == 0)      g = Ah + (size_t)(m0 + row) * K + kc + seg * 8;
            else if (tile == 1) g = Al + (size_t)(m0 + row) * K + kc + seg * 8;
            else {
                int r = n0 + row;
                if (r >= Nn) { r = Nn - 1; sz = 0; }
                g = ((tile == 2) ? Bh : Bl) + (size_t)r * K + kc + seg * 8;
            }
            cpasync16(sa, g, sz);
        }
        cp_commit();
    };

    load_chunk(0);

    for (int c = 0; c < nchunks; c++) {
        if (c + 1 < nchunks) {
            load_chunk(c + 1);
            cp_wait<1>();
        } else {
            cp_wait<0>();
        }
        __syncthreads();

        uint32_t base = dsm_u + (c & 1) * BUF_B;
        #pragma unroll
        for (int kk = 0; kk < 32; kk += 16) {
            uint32_t aH[2][4], aL[2][4], bH[4][2], bL[4][2];
            {
                int arow = warp_m * 32 + (lane & 15);
                int ak = kk + (lane >> 4) * 8;
                #pragma unroll
                for (int mt = 0; mt < 2; mt++) {
                    uint32_t addr = base + ((arow + mt * 16) * LDSROW + ak) * 2;
                    ldsm4(aH[mt], addr);
                    ldsm4(aL[mt], addr + TILE_H * 2);
                }
            }
            {
                int brow = warp_n * 32 + (lane & 7) + (lane >> 4) * 8;
                int bk = kk + ((lane >> 3) & 1) * 8;
                #pragma unroll
                for (int g2 = 0; g2 < 2; g2++) {
                    uint32_t addr = base + 2 * TILE_H * 2 + ((brow + g2 * 16) * LDSROW + bk) * 2;
                    uint32_t r[4];
                    ldsm4(r, addr);
                    bH[g2 * 2][0] = r[0]; bH[g2 * 2][1] = r[1];
                    bH[g2 * 2 + 1][0] = r[2]; bH[g2 * 2 + 1][1] = r[3];
                    ldsm4(r, addr + TILE_H * 2);
                    bL[g2 * 2][0] = r[0]; bL[g2 * 2][1] = r[1];
                    bL[g2 * 2 + 1][0] = r[2]; bL[g2 * 2 + 1][1] = r[3];
                }
            }
            #pragma unroll
            for (int mt = 0; mt < 2; mt++)
                #pragma unroll
                for (int nt = 0; nt < 4; nt++) {
                    mma16816(acc[mt][nt], aH[mt], bH[nt]);
                    mma16816(acc[mt][nt], aH[mt], bL[nt]);
                    mma16816(acc[mt][nt], aL[mt], bH[nt]);
                }
        }
        __syncthreads();
    }

    // epilogue
    if (mode == 0) {
        #pragma unroll
        for (int mt = 0; mt < 2; mt++) {
            int m = m0 + warp_m * 32 + mt * 16 + (lane >> 2);
            #pragma unroll
            for (int nt = 0; nt < 4; nt++) {
                int n = n0 + warp_n * 32 + nt * 8 + (lane & 3) * 2;
                if (n < Nn) {
                    float2 v0 = make_float2(acc[mt][nt][0], acc[mt][nt][1]);
                    float2 v1 = make_float2(acc[mt][nt][2], acc[mt][nt][3]);
                    *(float2*)&C[(size_t)m * ldc + n] = v0;
                    *(float2*)&C[(size_t)(m + 8) * ldc + n] = v1;
                }
            }
        }
    } else {
        // mode 2: transpose through smem, store to out (B, DIMC, L_SEQ)
        float* sT = (float*)dsm;   // [128 n][132 m]
        #pragma unroll
        for (int mt = 0; mt < 2; mt++) {
            int ml = warp_m * 32 + mt * 16 + (lane >> 2);
            #pragma unroll
            for (int nt = 0; nt < 4; nt++) {
                int nl = warp_n * 32 + nt * 8 + (lane & 3) * 2;
                sT[nl * 132 + ml]           = acc[mt][nt][0];
                sT[(nl + 1) * 132 + ml]     = acc[mt][nt][1];
                sT[nl * 132 + ml + 8]       = acc[mt][nt][2];
                sT[(nl + 1) * 132 + ml + 8] = acc[mt][nt][3];
            }
        }
        __syncthreads();
        int b = m0 >> 12;
        int l0 = m0 & (L_SEQ - 1);
        int n = tid >> 2;
        int part = (tid & 3) * 32;
        float* dst = C + ((size_t)b * DIMC + n0 + n) * L_SEQ + l0 + part;
        const float* src = sT + n * 132 + part;
        #pragma unroll
        for (int q = 0; q < 8; q++)
            *(float4*)(dst + q * 4) = *(const float4*)(src + q * 4);
    }
}

// ---------------- fp32 -> bf16 hi/lo split ----------------
__global__ __launch_bounds__(256) void cvt_kernel(const float* __restrict__ s,
                                                  __nv_bfloat16* __restrict__ hi,
                                                  __nv_bfloat16* __restrict__ lo, int n4) {
    int i = blockIdx.x * blockDim.x + threadIdx.x;
    if (i >= n4) return;
    float4 v = *(const float4*)(s + (size_t)i * 4);
    float vv[4] = {v.x, v.y, v.z, v.w};
    #pragma unroll
    for (int j = 0; j < 4; j++) {
        __nv_bfloat16 h = __float2bfloat16(vv[j]);
        hi[(size_t)i * 4 + j] = h;
        lo[(size_t)i * 4 + j] = __float2bfloat16(vv[j] - __bfloat162float(h));
    }
}

// ---------------- LayerNorm: x (B,C,L) -> xn hi/lo (B*L, C) bf16 ----------------
__global__ __launch_bounds__(256) void ln_kernel(const float* __restrict__ x,
                                                 const float* __restrict__ w,
                                                 const float* __restrict__ bsh,
                                                 __nv_bfloat16* __restrict__ xnh,
                                                 __nv_bfloat16* __restrict__ xnl) {
    int b  = blockIdx.y;
    int l0 = blockIdx.x * 64;
    int tid = threadIdx.x;
    int ll = tid & 63;
    int cg = tid >> 6;

    __shared__ float ssum[4][64];
    __shared__ float ssq[4][64];
    __shared__ float smean[64];
    __shared__ float srstd[64];
    __shared__ float st[16][65];

    const float* xb = x + (size_t)b * DIMC * L_SEQ;

    float s = 0.f, sq = 0.f;
    for (int c = cg; c < DIMC; c += 4) {
        float v = xb[(size_t)c * L_SEQ + l0 + ll];
        s += v; sq += v * v;
    }
    ssum[cg][ll] = s; ssq[cg][ll] = sq;
    __syncthreads();
    if (tid < 64) {
        float S = ssum[0][tid] + ssum[1][tid] + ssum[2][tid] + ssum[3][tid];
        float Q = ssq[0][tid] + ssq[1][tid] + ssq[2][tid] + ssq[3][tid];
        float mu = S * (1.f / DIMC);
        float var = Q * (1.f / DIMC) - mu * mu;
        smean[tid] = mu;
        srstd[tid] = rsqrtf(var + 1e-5f);
    }
    __syncthreads();

    for (int c0 = 0; c0 < DIMC; c0 += 16) {
        #pragma unroll
        for (int r = 0; r < 4; r++) {
            int c = c0 + cg + r * 4;
            float v = xb[(size_t)c * L_SEQ + l0 + ll];
            st[cg + r * 4][ll] = (v - smean[ll]) * srstd[ll] * w[c] + bsh[c];
        }
        __syncthreads();
        int c2 = tid & 15, lr = tid >> 4;
        #pragma unroll
        for (int p = 0; p < 4; p++) {
            int l = lr + p * 16;
            float v = st[c2][l];
            __nv_bfloat16 h = __float2bfloat16(v);
            size_t o = ((size_t)b * L_SEQ + l0 + l) * DIMC + c0 + c2;
            xnh[o] = h;
            xnl[o] = __float2bfloat16(v - __bfloat162float(h));
        }
        __syncthreads();
    }
}

// ---------------- fp32 tiled GEMM (dt only) ----------------
#define BM 128
#define BN 128
#define BKK 16
#define PAD 4

__global__ __launch_bounds__(256, 2) void gemm2_kernel(
    const float* __restrict__ A, int lda, int K,
    const float* __restrict__ W, int ldw, int N,
    float* __restrict__ C, int ldc, int mode,
    const float* __restrict__ bias) {

    __shared__ float As[2][BKK][BM + PAD];
    __shared__ float Bs[2][BKK][BN + PAD];

    int tid = threadIdx.x;
    int m0 = blockIdx.y * BM;
    int n0 = blockIdx.x * BN;
    int tm = tid & 15;
    int tn = tid >> 4;

    int lr = tid >> 2;
    int lk = (tid & 3) * 4;

    float4 pa[2], pb[2];
    int nt = (K + BKK - 1) / BKK;

    {
        int kk = lk;
        #pragma unroll
        for (int r = 0; r < 2; r++) {
            int m = lr + r * 64;
            float4 v = make_float4(0.f, 0.f, 0.f, 0.f);
            if (kk < K) v = *(const float4*)&A[(size_t)(m0 + m) * lda + kk];
            pa[r] = v;
            float4 u = make_float4(0.f, 0.f, 0.f, 0.f);
            if (kk < K && (n0 + m) < N) u = *(const float4*)&W[(size_t)(n0 + m) * ldw + kk];
            pb[r] = u;
        }
    }

    float acc[8][8];
    #pragma unroll
    for (int i = 0; i < 8; i++)
        #pragma unroll
        for (int j = 0; j < 8; j++) acc[i][j] = 0.f;

    for (int t = 0; t < nt; t++) {
        int buf = t & 1;
        #pragma unroll
        for (int r = 0; r < 2; r++) {
            int m = lr + r * 64;
            As[buf][lk + 0][m] = pa[r].x;
            As[buf][lk + 1][m] = pa[r].y;
            As[buf][lk + 2][m] = pa[r].z;
            As[buf][lk + 3][m] = pa[r].w;
            Bs[buf][lk + 0][m] = pb[r].x;
            Bs[buf][lk + 1][m] = pb[r].y;
            Bs[buf][lk + 2][m] = pb[r].z;
            Bs[buf][lk + 3][m] = pb[r].w;
        }
        __syncthreads();

        if (t + 1 < nt) {
            int kk = (t + 1) * BKK + lk;
            #pragma unroll
            for (int r = 0; r < 2; r++) {
                int m = lr + r * 64;
                float4 v = make_float4(0.f, 0.f, 0.f, 0.f);
                if (kk < K) v = *(const float4*)&A[(size_t)(m0 + m) * lda + kk];
                pa[r] = v;
                float4 u = make_float4(0.f, 0.f, 0.f, 0.f);
                if (kk < K && (n0 + m) < N) u = *(const float4*)&W[(size_t)(n0 + m) * ldw + kk];
                pb[r] = u;
            }
        }

        const float (*Ab)[BM + PAD] = As[buf];
        const float (*Bb)[BN + PAD] = Bs[buf];
        #pragma unroll
        for (int k = 0; k < BKK; k++) {
            float a[8], b[8];
            *(float4*)&a[0] = *(const float4*)&Ab[k][tm * 4];
            *(float4*)&a[4] = *(const float4*)&Ab[k][64 + tm * 4];
            *(float4*)&b[0] = *(const float4*)&Bb[k][tn * 4];
            *(float4*)&b[4] = *(const float4*)&Bb[k][64 + tn * 4];
            #pragma unroll
            for (int i = 0; i < 8; i++)
                #pragma unroll
                for (int j = 0; j < 8; j++)
                    acc[i][j] = fmaf(a[i], b[j], acc[i][j]);
        }
        __syncthreads();
    }

    #pragma unroll
    for (int ih = 0; ih < 2; ih++) {
        #pragma unroll
        for (int i4 = 0; i4 < 4; i4++) {
            int i = ih * 4 + i4;
            int m = m0 + ih * 64 + tm * 4 + i4;
            #pragma unroll
            for (int jh = 0; jh < 2; jh++) {
                int n = n0 + jh * 64 + tn * 4;
                if (n < N) {
                    float4 v = make_float4(acc[i][jh * 4 + 0], acc[i][jh * 4 + 1],
                                           acc[i][jh * 4 + 2], acc[i][jh * 4 + 3]);
                    if (mode == 1) {
                        float* vv = (float*)&v;
                        #pragma unroll
                        for (int j = 0; j < 4; j++) {
                            float z = vv[j] + bias[n + j];
                            vv[j] = fmaxf(z, 0.f) + log1pf(__expf(-fabsf(z)));
                        }
                    }
                    if (n + 3 < N) {
                        *(float4*)&C[(size_t)m * ldc + n] = v;
                    } else {
                        float* vv = (float*)&v;
                        #pragma unroll
                        for (int j = 0; j < 4; j++)
                            if (n + j < N) C[(size_t)m * ldc + n + j] = vv[j];
                    }
                }
            }
        }
    }
}

// ---------------- depthwise causal conv1d (k=4) + SiLU; emits fp32 + bf16 hi/lo ----------------
__global__ __launch_bounds__(256) void conv_silu_kernel(const float* __restrict__ cw,
                                                        const float* __restrict__ cb,
                                                        const float* __restrict__ xz,
                                                        float* __restrict__ xc,
                                                        __nv_bfloat16* __restrict__ xch,
                                                        __nv_bfloat16* __restrict__ xcl) {
    int idx = blockIdx.x * blockDim.x + threadIdx.x;
    if (idx >= M_TOTAL * D_INNER) return;
    int d = idx % D_INNER;
    int m = idx / D_INNER;
    int l = m & (L_SEQ - 1);

    float w0 = cw[d * 4 + 0], w1 = cw[d * 4 + 1];
    float w2 = cw[d * 4 + 2], w3 = cw[d * 4 + 3];

    const float* xb = xz + (size_t)m * (2 * D_INNER) + d;
    float acc = cb[d];
    if (l >= 3) acc = fmaf(w0, xb[-3 * 2 * D_INNER], acc);
    if (l >= 2) acc = fmaf(w1, xb[-2 * 2 * D_INNER], acc);
    if (l >= 1) acc = fmaf(w2, xb[-1 * 2 * D_INNER], acc);
    acc = fmaf(w3, xb[0], acc);
    float sg = 1.f / (1.f + __expf(-acc));
    float v = acc * sg;
    size_t o = (size_t)m * D_INNER + d;
    xc[o] = v;
    __nv_bfloat16 h = __float2bfloat16(v);
    xch[o] = h;
    xcl[o] = __float2bfloat16(v - __bfloat162float(h));
}

// ---------------- selective scan: smem-staged, chunked; writes y hi/lo ----------------
#define SCH 64
#define NCHUNK (L_SEQ / SCH)

__global__ __launch_bounds__(256) void scan2_kernel(const float* __restrict__ A_log,
                                                    const float* __restrict__ Dp,
                                                    const float* __restrict__ dtv,
                                                    const float* __restrict__ xc,
                                                    const float* __restrict__ xdbl,
                                                    const float* __restrict__ xz,
                                                    __nv_bfloat16* __restrict__ yh,
                                                    __nv_bfloat16* __restrict__ yl) {
    int b = blockIdx.y;
    int g = blockIdx.x;
    int d0 = g * 16;
    int tid = threadIdx.x;
    size_t bL = (size_t)b * L_SEQ;

    __shared__ float sBC[2][SCH][32];
    __shared__ float sD[2][SCH][16];
    __shared__ float sX[2][SCH][16];
    __shared__ float sZ[2][SCH][16];
    __shared__ float sY[SCH][16];

    int lane = tid & 31;
    int w = tid >> 5;
    int half = lane >> 4;
    int n = lane & 15;
    int dl = 2 * w + half;

    float An = -__expf(A_log[(d0 + dl) * D_STATE + n]);
    float Dd = Dp[d0 + (tid & 15)];
    float h = 0.f;

    float rBC[8], rD[4], rX[4], rZ[4];

    {
        #pragma unroll
        for (int i = 0; i < 8; i++) {
            int idx = tid + i * 256;
            rBC[i] = xdbl[(bL + (idx >> 5)) * XPN + DT_RANK + (idx & 31)];
        }
        #pragma unroll
        for (int i = 0; i < 4; i++) {
            int idx = tid + i * 256;
            int l = idx >> 4, dd = idx & 15;
            size_t row = bL + l;
            rD[i] = dtv[row * D_INNER + d0 + dd];
            rX[i] = xc[row * D_INNER + d0 + dd];
            rZ[i] = xz[row * 2 * D_INNER + D_INNER + d0 + dd];
        }
    }

    for (int c = 0; c < NCHUNK; c++) {
        int buf = c & 1;
        #pragma unroll
        for (int i = 0; i < 8; i++) {
            int idx = tid + i * 256;
            sBC[buf][idx >> 5][idx & 31] = rBC[i];
        }
        #pragma unroll
        for (int i = 0; i < 4; i++) {
            int idx = tid + i * 256;
            int l = idx >> 4, dd = idx & 15;
            sD[buf][l][dd] = rD[i];
            sX[buf][l][dd] = rX[i];
            sZ[buf][l][dd] = rZ[i];
        }
        __syncthreads();

        if (c + 1 < NCHUNK) {
            int l0n = (c + 1) * SCH;
            #pragma unroll
            for (int i = 0; i < 8; i++) {
                int idx = tid + i * 256;
                rBC[i] = xdbl[(bL + l0n + (idx >> 5)) * XPN + DT_RANK + (idx & 31)];
            }
            #pragma unroll
            for (int i = 0; i < 4; i++) {
                int idx = tid + i * 256;
                int l = idx >> 4, dd = idx & 15;
                size_t row = bL + l0n + l;
                rD[i] = dtv[row * D_INNER + d0 + dd];
                rX[i] = xc[row * D_INNER + d0 + dd];
                rZ[i] = xz[row * 2 * D_INNER + D_INNER + d0 + dd];
            }
        }

        #pragma unroll 4
        for (int l = 0; l < SCH; l++) {
            float dt = sD[buf][l][dl];
            float xv = sX[buf][l][dl];
            float Bn = sBC[buf][l][n];
            float Cn = sBC[buf][l][16 + n];
            float e = __expf(dt * An);
            h = fmaf(e, h, dt * xv * Bn);
            float p = h * Cn;
            p += __shfl_xor_sync(0xffffffffu, p, 8);
            p += __shfl_xor_sync(0xffffffffu, p, 4);
            p += __shfl_xor_sync(0xffffffffu, p, 2);
            p += __shfl_xor_sync(0xffffffffu, p, 1);
            if (n == 0) sY[l][dl] = p;
        }
        __syncthreads();

        int l0 = c * SCH;
        #pragma unroll
        for (int i = 0; i < 4; i++) {
            int idx = tid + i * 256;
            int l = idx >> 4, dd = idx & 15;
            float p = sY[l][dd];
            float xv = sX[buf][l][dd];
            float zv = sZ[buf][l][dd];
            float yv = fmaf(xv, Dd, p);
            yv *= zv / (1.f + __expf(-zv));
            size_t o = (bL + l0 + l) * D_INNER + d0 + dd;
            __nv_bfloat16 hh = __float2bfloat16(yv);
            yh[o] = hh;
            yl[o] = __float2bfloat16(yv - __bfloat162float(hh));
        }
    }
}

// ---------------- launch ----------------
extern "C" void kernel_launch(void* const* d_in, const int* in_sizes, int n_in,
                              void* d_out, int out_size) {
    const float* x          = (const float*)d_in[0];
    const float* ln_w       = (const float*)d_in[1];
    const float* ln_b       = (const float*)d_in[2];
    const float* in_proj_w  = (const float*)d_in[3];
    const float* conv_w     = (const float*)d_in[4];
    const float* conv_b     = (const float*)d_in[5];
    const float* x_proj_w   = (const float*)d_in[6];
    const float* dt_w       = (const float*)d_in[7];
    const float* dt_b       = (const float*)d_in[8];
    const float* A_log      = (const float*)d_in[9];
    const float* Dp         = (const float*)d_in[10];
    const float* out_proj_w = (const float*)d_in[11];
    float* out = (float*)d_out;

    float *p_xz, *p_xc, *p_xdbl, *p_dtv;
    __nv_bfloat16 *p_xnh, *p_xnl, *p_xch, *p_xcl, *p_yh, *p_yl;
    __nv_bfloat16 *p_wih, *p_wil, *p_woh, *p_wol, *p_wxh, *p_wxl;
    cudaGetSymbolAddress((void**)&p_xz,   g_xz);
    cudaGetSymbolAddress((void**)&p_xc,   g_xc);
    cudaGetSymbolAddress((void**)&p_xdbl, g_xdbl);
    cudaGetSymbolAddress((void**)&p_dtv,  g_dtv);
    cudaGetSymbolAddress((void**)&p_xnh,  g_xn_hi);
    cudaGetSymbolAddress((void**)&p_xnl,  g_xn_lo);
    cudaGetSymbolAddress((void**)&p_xch,  g_xc_hi);
    cudaGetSymbolAddress((void**)&p_xcl,  g_xc_lo);
    cudaGetSymbolAddress((void**)&p_yh,   g_y_hi);
    cudaGetSymbolAddress((void**)&p_yl,   g_y_lo);
    cudaGetSymbolAddress((void**)&p_wih,  g_wi_hi);
    cudaGetSymbolAddress((void**)&p_wil,  g_wi_lo);
    cudaGetSymbolAddress((void**)&p_woh,  g_wo_hi);
    cudaGetSymbolAddress((void**)&p_wol,  g_wo_lo);
    cudaGetSymbolAddress((void**)&p_wxh,  g_wx_hi);
    cudaGetSymbolAddress((void**)&p_wxl,  g_wx_lo);

    const int MM_SMEM = 2 * BUF_B;   // 81920 B
    cudaFuncSetAttribute(mmagemm_kernel, cudaFuncAttributeMaxDynamicSharedMemorySize, MM_SMEM);

    // 0) weight hi/lo conversion
    {
        int n4i = (2 * D_INNER * DIMC) / 4;
        cvt_kernel<<<(n4i + 255) / 256, 256>>>(in_proj_w, p_wih, p_wil, n4i);
        int n4o = (DIMC * D_INNER) / 4;
        cvt_kernel<<<(n4o + 255) / 256, 256>>>(out_proj_w, p_woh, p_wol, n4o);
        int n4x = (XPN * D_INNER) / 4;
        cvt_kernel<<<(n4x + 255) / 256, 256>>>(x_proj_w, p_wxh, p_wxl, n4x);
    }

    // 1) LayerNorm -> xn hi/lo
    ln_kernel<<<dim3(L_SEQ / 64, B_SZ), 256>>>(x, ln_w, ln_b, p_xnh, p_xnl);

    // 2) in_proj (tensor): (16384,384)x(1536,384)^T -> xz fp32
    mmagemm_kernel<<<dim3(2 * D_INNER / 128, M_TOTAL / 128), 512, MM_SMEM>>>(
        p_xnh, p_xnl, p_wih, p_wil, DIMC, 2 * D_INNER, p_xz, 2 * D_INNER, 0);

    // 3) depthwise conv + silu -> xc fp32 + hi/lo
    {
        int total = M_TOTAL * D_INNER;
        conv_silu_kernel<<<(total + 255) / 256, 256>>>(conv_w, conv_b, p_xz, p_xc, p_xch, p_xcl);
    }

    // 4) x_proj (tensor, N=56 masked): (16384,768)x(56,768)^T -> xdbl fp32
    mmagemm_kernel<<<dim3(1, M_TOTAL / 128), 512, MM_SMEM>>>(
        p_xch, p_xcl, p_wxh, p_wxl, D_INNER, XPN, p_xdbl, XPN, 0);

    // 5) dt + softplus (fp32 SIMT, K=24)
    gemm2_kernel<<<dim3(D_INNER / BN, M_TOTAL / BM), 256>>>(
        p_xdbl, XPN, DT_RANK, dt_w, DT_RANK, D_INNER, p_dtv, D_INNER, 1, dt_b);

    // 6) selective scan -> y hi/lo
    scan2_kernel<<<dim3(D_INNER / 16, B_SZ), 256>>>(
        A_log, Dp, p_dtv, p_xc, p_xdbl, p_xz, p_yh, p_yl);

    // 7) out_proj (tensor, transposed store)
    mmagemm_kernel<<<dim3(DIMC / 128, M_TOTAL / 128), 512, MM_SMEM>>>(
        p_yh, p_yl, p_woh, p_wol, D_INNER, DIMC, out, 0, 2);
}

// round 7
// speedup vs baseline: 5.1304x; 1.0156x over previous
#include <cuda_runtime.h>
#include <cuda_bf16.h>
#include <cstdint>

#define B_SZ 4
#define DIMC 384
#define L_SEQ 4096
#define D_INNER 768
#define D_STATE 16
#define DT_RANK 24
#define XPN 56
#define M_TOTAL (B_SZ * L_SEQ)      // 16384

// ---------------- scratch (no allocations allowed) ----------------
__device__ float g_xz[(size_t)M_TOTAL * 2 * D_INNER];
__device__ float g_xc[(size_t)M_TOTAL * D_INNER];
__device__ float g_xdbl[(size_t)M_TOTAL * XPN];
__device__ float g_dtv[(size_t)M_TOTAL * D_INNER];

__device__ __nv_bfloat16 g_xn_hi[(size_t)M_TOTAL * DIMC];
__device__ __nv_bfloat16 g_xn_lo[(size_t)M_TOTAL * DIMC];
__device__ __nv_bfloat16 g_xc_hi[(size_t)M_TOTAL * D_INNER];
__device__ __nv_bfloat16 g_xc_lo[(size_t)M_TOTAL * D_INNER];
__device__ __nv_bfloat16 g_y_hi[(size_t)M_TOTAL * D_INNER];
__device__ __nv_bfloat16 g_y_lo[(size_t)M_TOTAL * D_INNER];
__device__ __nv_bfloat16 g_wi_hi[(size_t)2 * D_INNER * DIMC];
__device__ __nv_bfloat16 g_wi_lo[(size_t)2 * D_INNER * DIMC];
__device__ __nv_bfloat16 g_wo_hi[(size_t)DIMC * D_INNER];
__device__ __nv_bfloat16 g_wo_lo[(size_t)DIMC * D_INNER];
__device__ __nv_bfloat16 g_wx_hi[(size_t)XPN * D_INNER];
__device__ __nv_bfloat16 g_wx_lo[(size_t)XPN * D_INNER];

// ---------------- small PTX helpers (all base-target, sm_80+) ----------------
__device__ __forceinline__ uint32_t smem_u32(const void* p) {
    uint32_t a;
    asm("{ .reg .u64 t; cvta.to.shared.u64 t, %1; cvt.u32.u64 %0, t; }" : "=r"(a) : "l"(p));
    return a;
}
__device__ __forceinline__ void cpasync16(uint32_t sa, const void* g, int sz) {
    asm volatile("cp.async.cg.shared.global [%0], [%1], 16, %2;" :: "r"(sa), "l"(g), "r"(sz) : "memory");
}
__device__ __forceinline__ void cp_commit() {
    asm volatile("cp.async.commit_group;" ::: "memory");
}
template <int N> __device__ __forceinline__ void cp_wait() {
    asm volatile("cp.async.wait_group %0;" :: "n"(N) : "memory");
}
__device__ __forceinline__ void ldsm4(uint32_t* r, uint32_t addr) {
    asm volatile("ldmatrix.sync.aligned.m8n8.x4.shared.b16 {%0,%1,%2,%3}, [%4];"
                 : "=r"(r[0]), "=r"(r[1]), "=r"(r[2]), "=r"(r[3]) : "r"(addr));
}
__device__ __forceinline__ void mma16816(float* d, const uint32_t* a, const uint32_t* b) {
    asm volatile(
        "mma.sync.aligned.m16n8k16.row.col.f32.bf16.bf16.f32 "
        "{%0,%1,%2,%3}, {%4,%5,%6,%7}, {%8,%9}, {%0,%1,%2,%3};"
        : "+f"(d[0]), "+f"(d[1]), "+f"(d[2]), "+f"(d[3])
        : "r"(a[0]), "r"(a[1]), "r"(a[2]), "r"(a[3]), "r"(b[0]), "r"(b[1]));
}

// ---------------- bf16-split mma.sync GEMM (512 thr, 3-stage cp.async) ----------------
// C[m,n] = sum_k A[m,k]*W[n,k];  A = Ah+Al, W = Bh+Bl (bf16 pairs, row-major [., K])
// CTA tile 128x128, BK=32, 3-stage pipeline. Nn = true N (B rows >= Nn zero-filled).
// mode 0: C[m*ldc+n] fp32 (mask n<Nn);  mode 2: out[(b*DIMC+n)*L_SEQ + l], m = b*L_SEQ + l.
#define LDSROW 40                 // halves per smem row (80B, 16B aligned, conflict-free)
#define TILE_H (128 * LDSROW)     // halves per tile (5120)
#define BUF_B  (4 * TILE_H * 2)   // bytes per buffer (40960)
#define NSTAGE 3

__global__ __launch_bounds__(512, 1) void mmagemm_kernel(
    const __nv_bfloat16* __restrict__ Ah, const __nv_bfloat16* __restrict__ Al,
    const __nv_bfloat16* __restrict__ Bh, const __nv_bfloat16* __restrict__ Bl,
    int K, int Nn, float* __restrict__ C, int ldc, int mode) {

    extern __shared__ __align__(16) uint8_t dsm[];
    uint32_t dsm_u = smem_u32(dsm);

    int tid = threadIdx.x;
    int wid = tid >> 5;
    int lane = tid & 31;
    int warp_m = wid & 3;     // 4 warps over m
    int warp_n = wid >> 2;    // 4 warps over n
    int m0 = blockIdx.y * 128;
    int n0 = blockIdx.x * 128;

    float acc[2][4][4];
    #pragma unroll
    for (int mt = 0; mt < 2; mt++)
        #pragma unroll
        for (int nt = 0; nt < 4; nt++)
            #pragma unroll
            for (int q = 0; q < 4; q++) acc[mt][nt][q] = 0.f;

    int nchunks = K >> 5;

    auto load_chunk = [&](int c) {
        int kc = c << 5;
        uint32_t sbase = dsm_u + (c % NSTAGE) * BUF_B;
        #pragma unroll
        for (int i = 0; i < 4; i++) {
            int u = tid + i * 512;
            int tile = u >> 9;
            int v = u & 511;
            int row = v >> 2;
            int seg = v & 3;
            uint32_t sa = sbase + (tile * TILE_H + row * LDSROW + seg * 8) * 2;
            const __nv_bfloat16* g;
            int sz = 16;
            if (tile == 0)      g = Ah + (size_t)(m0 + row) * K + kc + seg * 8;
            else if (tile == 1) g = Al + (size_t)(m0 + row) * K + kc + seg * 8;
            else {
                int r = n0 + row;
                if (r >= Nn) { r = Nn - 1; sz = 0; }
                g = ((tile == 2) ? Bh : Bl) + (size_t)r * K + kc + seg * 8;
            }
            cpasync16(sa, g, sz);
        }
        cp_commit();
    };

    load_chunk(0);
    load_chunk(1);

    for (int c = 0; c < nchunks; c++) {
        if (c + 2 < nchunks) { load_chunk(c + 2); cp_wait<2>(); }
        else if (c + 1 < nchunks) { cp_wait<1>(); }
        else { cp_wait<0>(); }
        __syncthreads();

        uint32_t base = dsm_u + (c % NSTAGE) * BUF_B;
        #pragma unroll
        for (int kk = 0; kk < 32; kk += 16) {
            uint32_t aH[2][4], aL[2][4], bH[4][2], bL[4][2];
            {
                int arow = warp_m * 32 + (lane & 15);
                int ak = kk + (lane >> 4) * 8;
                #pragma unroll
                for (int mt = 0; mt < 2; mt++) {
                    uint32_t addr = base + ((arow + mt * 16) * LDSROW + ak) * 2;
                    ldsm4(aH[mt], addr);
                    ldsm4(aL[mt], addr + TILE_H * 2);
                }
            }
            {
                int brow = warp_n * 32 + (lane & 7) + (lane >> 4) * 8;
                int bk = kk + ((lane >> 3) & 1) * 8;
                #pragma unroll
                for (int g2 = 0; g2 < 2; g2++) {
                    uint32_t addr = base + 2 * TILE_H * 2 + ((brow + g2 * 16) * LDSROW + bk) * 2;
                    uint32_t r[4];
                    ldsm4(r, addr);
                    bH[g2 * 2][0] = r[0]; bH[g2 * 2][1] = r[1];
                    bH[g2 * 2 + 1][0] = r[2]; bH[g2 * 2 + 1][1] = r[3];
                    ldsm4(r, addr + TILE_H * 2);
                    bL[g2 * 2][0] = r[0]; bL[g2 * 2][1] = r[1];
                    bL[g2 * 2 + 1][0] = r[2]; bL[g2 * 2 + 1][1] = r[3];
                }
            }
            #pragma unroll
            for (int mt = 0; mt < 2; mt++)
                #pragma unroll
                for (int nt = 0; nt < 4; nt++) {
                    mma16816(acc[mt][nt], aH[mt], bH[nt]);
                    mma16816(acc[mt][nt], aH[mt], bL[nt]);
                    mma16816(acc[mt][nt], aL[mt], bH[nt]);
                }
        }
        __syncthreads();
    }

    // epilogue
    if (mode == 0) {
        #pragma unroll
        for (int mt = 0; mt < 2; mt++) {
            int m = m0 + warp_m * 32 + mt * 16 + (lane >> 2);
            #pragma unroll
            for (int nt = 0; nt < 4; nt++) {
                int n = n0 + warp_n * 32 + nt * 8 + (lane & 3) * 2;
                if (n < Nn) {
                    float2 v0 = make_float2(acc[mt][nt][0], acc[mt][nt][1]);
                    float2 v1 = make_float2(acc[mt][nt][2], acc[mt][nt][3]);
                    *(float2*)&C[(size_t)m * ldc + n] = v0;
                    *(float2*)&C[(size_t)(m + 8) * ldc + n] = v1;
                }
            }
        }
    } else {
        // mode 2: transpose through smem, store to out (B, DIMC, L_SEQ)
        float* sT = (float*)dsm;   // [128 n][132 m]
        #pragma unroll
        for (int mt = 0; mt < 2; mt++) {
            int ml = warp_m * 32 + mt * 16 + (lane >> 2);
            #pragma unroll
            for (int nt = 0; nt < 4; nt++) {
                int nl = warp_n * 32 + nt * 8 + (lane & 3) * 2;
                sT[nl * 132 + ml]           = acc[mt][nt][0];
                sT[(nl + 1) * 132 + ml]     = acc[mt][nt][1];
                sT[nl * 132 + ml + 8]       = acc[mt][nt][2];
                sT[(nl + 1) * 132 + ml + 8] = acc[mt][nt][3];
            }
        }
        __syncthreads();
        int b = m0 >> 12;
        int l0 = m0 & (L_SEQ - 1);
        int n = tid >> 2;
        int part = (tid & 3) * 32;
        float* dst = C + ((size_t)b * DIMC + n0 + n) * L_SEQ + l0 + part;
        const float* src = sT + n * 132 + part;
        #pragma unroll
        for (int q = 0; q < 8; q++)
            *(float4*)(dst + q * 4) = *(const float4*)(src + q * 4);
    }
}

// ---------------- fp32 -> bf16 hi/lo split ----------------
__global__ __launch_bounds__(256) void cvt_kernel(const float* __restrict__ s,
                                                  __nv_bfloat16* __restrict__ hi,
                                                  __nv_bfloat16* __restrict__ lo, int n4) {
    int i = blockIdx.x * blockDim.x + threadIdx.x;
    if (i >= n4) return;
    float4 v = *(const float4*)(s + (size_t)i * 4);
    float vv[4] = {v.x, v.y, v.z, v.w};
    #pragma unroll
    for (int j = 0; j < 4; j++) {
        __nv_bfloat16 h = __float2bfloat16(vv[j]);
        hi[(size_t)i * 4 + j] = h;
        lo[(size_t)i * 4 + j] = __float2bfloat16(vv[j] - __bfloat162float(h));
    }
}

// ---------------- LayerNorm: x (B,C,L) -> xn hi/lo (B*L, C) bf16 ----------------
__global__ __launch_bounds__(256) void ln_kernel(const float* __restrict__ x,
                                                 const float* __restrict__ w,
                                                 const float* __restrict__ bsh,
                                                 __nv_bfloat16* __restrict__ xnh,
                                                 __nv_bfloat16* __restrict__ xnl) {
    int b  = blockIdx.y;
    int l0 = blockIdx.x * 64;
    int tid = threadIdx.x;
    int ll = tid & 63;
    int cg = tid >> 6;

    __shared__ float ssum[4][64];
    __shared__ float ssq[4][64];
    __shared__ float smean[64];
    __shared__ float srstd[64];
    __shared__ float st[16][65];

    const float* xb = x + (size_t)b * DIMC * L_SEQ;

    float s = 0.f, sq = 0.f;
    for (int c = cg; c < DIMC; c += 4) {
        float v = xb[(size_t)c * L_SEQ + l0 + ll];
        s += v; sq += v * v;
    }
    ssum[cg][ll] = s; ssq[cg][ll] = sq;
    __syncthreads();
    if (tid < 64) {
        float S = ssum[0][tid] + ssum[1][tid] + ssum[2][tid] + ssum[3][tid];
        float Q = ssq[0][tid] + ssq[1][tid] + ssq[2][tid] + ssq[3][tid];
        float mu = S * (1.f / DIMC);
        float var = Q * (1.f / DIMC) - mu * mu;
        smean[tid] = mu;
        srstd[tid] = rsqrtf(var + 1e-5f);
    }
    __syncthreads();

    for (int c0 = 0; c0 < DIMC; c0 += 16) {
        #pragma unroll
        for (int r = 0; r < 4; r++) {
            int c = c0 + cg + r * 4;
            float v = xb[(size_t)c * L_SEQ + l0 + ll];
            st[cg + r * 4][ll] = (v - smean[ll]) * srstd[ll] * w[c] + bsh[c];
        }
        __syncthreads();
        int c2 = tid & 15, lr = tid >> 4;
        #pragma unroll
        for (int p = 0; p < 4; p++) {
            int l = lr + p * 16;
            float v = st[c2][l];
            __nv_bfloat16 h = __float2bfloat16(v);
            size_t o = ((size_t)b * L_SEQ + l0 + l) * DIMC + c0 + c2;
            xnh[o] = h;
            xnl[o] = __float2bfloat16(v - __bfloat162float(h));
        }
        __syncthreads();
    }
}

// ---------------- fp32 tiled GEMM (dt only) ----------------
#define BM 128
#define BN 128
#define BKK 16
#define PAD 4

__global__ __launch_bounds__(256, 2) void gemm2_kernel(
    const float* __restrict__ A, int lda, int K,
    const float* __restrict__ W, int ldw, int N,
    float* __restrict__ C, int ldc, int mode,
    const float* __restrict__ bias) {

    __shared__ float As[2][BKK][BM + PAD];
    __shared__ float Bs[2][BKK][BN + PAD];

    int tid = threadIdx.x;
    int m0 = blockIdx.y * BM;
    int n0 = blockIdx.x * BN;
    int tm = tid & 15;
    int tn = tid >> 4;

    int lr = tid >> 2;
    int lk = (tid & 3) * 4;

    float4 pa[2], pb[2];
    int nt = (K + BKK - 1) / BKK;

    {
        int kk = lk;
        #pragma unroll
        for (int r = 0; r < 2; r++) {
            int m = lr + r * 64;
            float4 v = make_float4(0.f, 0.f, 0.f, 0.f);
            if (kk < K) v = *(const float4*)&A[(size_t)(m0 + m) * lda + kk];
            pa[r] = v;
            float4 u = make_float4(0.f, 0.f, 0.f, 0.f);
            if (kk < K && (n0 + m) < N) u = *(const float4*)&W[(size_t)(n0 + m) * ldw + kk];
            pb[r] = u;
        }
    }

    float acc[8][8];
    #pragma unroll
    for (int i = 0; i < 8; i++)
        #pragma unroll
        for (int j = 0; j < 8; j++) acc[i][j] = 0.f;

    for (int t = 0; t < nt; t++) {
        int buf = t & 1;
        #pragma unroll
        for (int r = 0; r < 2; r++) {
            int m = lr + r * 64;
            As[buf][lk + 0][m] = pa[r].x;
            As[buf][lk + 1][m] = pa[r].y;
            As[buf][lk + 2][m] = pa[r].z;
            As[buf][lk + 3][m] = pa[r].w;
            Bs[buf][lk + 0][m] = pb[r].x;
            Bs[buf][lk + 1][m] = pb[r].y;
            Bs[buf][lk + 2][m] = pb[r].z;
            Bs[buf][lk + 3][m] = pb[r].w;
        }
        __syncthreads();

        if (t + 1 < nt) {
            int kk = (t + 1) * BKK + lk;
            #pragma unroll
            for (int r = 0; r < 2; r++) {
                int m = lr + r * 64;
                float4 v = make_float4(0.f, 0.f, 0.f, 0.f);
                if (kk < K) v = *(const float4*)&A[(size_t)(m0 + m) * lda + kk];
                pa[r] = v;
                float4 u = make_float4(0.f, 0.f, 0.f, 0.f);
                if (kk < K && (n0 + m) < N) u = *(const float4*)&W[(size_t)(n0 + m) * ldw + kk];
                pb[r] = u;
            }
        }

        const float (*Ab)[BM + PAD] = As[buf];
        const float (*Bb)[BN + PAD] = Bs[buf];
        #pragma unroll
        for (int k = 0; k < BKK; k++) {
            float a[8], b[8];
            *(float4*)&a[0] = *(const float4*)&Ab[k][tm * 4];
            *(float4*)&a[4] = *(const float4*)&Ab[k][64 + tm * 4];
            *(float4*)&b[0] = *(const float4*)&Bb[k][tn * 4];
            *(float4*)&b[4] = *(const float4*)&Bb[k][64 + tn * 4];
            #pragma unroll
            for (int i = 0; i < 8; i++)
                #pragma unroll
                for (int j = 0; j < 8; j++)
                    acc[i][j] = fmaf(a[i], b[j], acc[i][j]);
        }
        __syncthreads();
    }

    #pragma unroll
    for (int ih = 0; ih < 2; ih++) {
        #pragma unroll
        for (int i4 = 0; i4 < 4; i4++) {
            int i = ih * 4 + i4;
            int m = m0 + ih * 64 + tm * 4 + i4;
            #pragma unroll
            for (int jh = 0; jh < 2; jh++) {
                int n = n0 + jh * 64 + tn * 4;
                if (n < N) {
                    float4 v = make_float4(acc[i][jh * 4 + 0], acc[i][jh * 4 + 1],
                                           acc[i][jh * 4 + 2], acc[i][jh * 4 + 3]);
                    if (mode == 1) {
                        float* vv = (float*)&v;
                        #pragma unroll
                        for (int j = 0; j < 4; j++) {
                            float z = vv[j] + bias[n + j];
                            vv[j] = fmaxf(z, 0.f) + log1pf(__expf(-fabsf(z)));
                        }
                    }
                    if (n + 3 < N) {
                        *(float4*)&C[(size_t)m * ldc + n] = v;
                    } else {
                        float* vv = (float*)&v;
                        #pragma unroll
                        for (int j = 0; j < 4; j++)
                            if (n + j < N) C[(size_t)m * ldc + n + j] = vv[j];
                    }
                }
            }
        }
    }
}

// ---------------- depthwise causal conv1d (k=4) + SiLU; emits fp32 + bf16 hi/lo ----------------
__global__ __launch_bounds__(256) void conv_silu_kernel(const float* __restrict__ cw,
                                                        const float* __restrict__ cb,
                                                        const float* __restrict__ xz,
                                                        float* __restrict__ xc,
                                                        __nv_bfloat16* __restrict__ xch,
                                                        __nv_bfloat16* __restrict__ xcl) {
    int idx = blockIdx.x * blockDim.x + threadIdx.x;
    if (idx >= M_TOTAL * D_INNER) return;
    int d = idx % D_INNER;
    int m = idx / D_INNER;
    int l = m & (L_SEQ - 1);

    float w0 = cw[d * 4 + 0], w1 = cw[d * 4 + 1];
    float w2 = cw[d * 4 + 2], w3 = cw[d * 4 + 3];

    const float* xb = xz + (size_t)m * (2 * D_INNER) + d;
    float acc = cb[d];
    if (l >= 3) acc = fmaf(w0, xb[-3 * 2 * D_INNER], acc);
    if (l >= 2) acc = fmaf(w1, xb[-2 * 2 * D_INNER], acc);
    if (l >= 1) acc = fmaf(w2, xb[-1 * 2 * D_INNER], acc);
    acc = fmaf(w3, xb[0], acc);
    float sg = 1.f / (1.f + __expf(-acc));
    float v = acc * sg;
    size_t o = (size_t)m * D_INNER + d;
    xc[o] = v;
    __nv_bfloat16 h = __float2bfloat16(v);
    xch[o] = h;
    xcl[o] = __float2bfloat16(v - __bfloat162float(h));
}

// ---------------- selective scan v3: 24 ch/block, 128 blocks (1/SM), cp.async staged ----------------
#define SCH3 32
#define CH3 24
#define NCH3 (L_SEQ / SCH3)    // 128 chunks

__global__ __launch_bounds__(384) void scan3_kernel(const float* __restrict__ A_log,
                                                    const float* __restrict__ Dp,
                                                    const float* __restrict__ dtv,
                                                    const float* __restrict__ xc,
                                                    const float* __restrict__ xdbl,
                                                    const float* __restrict__ xz,
                                                    __nv_bfloat16* __restrict__ yh,
                                                    __nv_bfloat16* __restrict__ yl) {
    int b = blockIdx.y;
    int g = blockIdx.x;
    int d0 = g * CH3;
    int tid = threadIdx.x;
    size_t bL = (size_t)b * L_SEQ;

    __shared__ float sBC[3][SCH3][32];    // [l][0..15]=B, [16..31]=C
    __shared__ float sD[3][SCH3][CH3];
    __shared__ float sX[3][SCH3][CH3];
    __shared__ float sZ[3][SCH3][CH3];
    __shared__ float sY[SCH3][CH3];

    int lane = tid & 31;
    int w = tid >> 5;           // 0..11
    int half = lane >> 4;
    int n = lane & 15;
    int dl = 2 * w + half;      // 0..23

    float An = -__expf(A_log[(d0 + dl) * D_STATE + n]);
    int fdd = tid % CH3;        // flush channel (stride 384 ≡ 0 mod 24)
    int flb = tid / CH3;        // flush l base (0..15)
    float Dd = Dp[d0 + fdd];
    float h = 0.f;

    auto issue = [&](int c) {
        int l0 = c * SCH3;
        int buf = c % 3;
        uint32_t bcs = smem_u32(&sBC[buf][0][0]);
        uint32_t ds  = smem_u32(&sD[buf][0][0]);
        uint32_t xs  = smem_u32(&sX[buf][0][0]);
        uint32_t zs  = smem_u32(&sZ[buf][0][0]);
        for (int u = tid; u < 832; u += 384) {
            if (u < 256) {
                int l = u >> 3, c4 = u & 7;
                cpasync16(bcs + (uint32_t)(l * 32 + c4 * 4) * 4,
                          xdbl + (bL + l0 + l) * XPN + DT_RANK + c4 * 4, 16);
            } else if (u < 448) {
                int v = u - 256; int l = v / 6, c4 = v % 6;
                cpasync16(ds + (uint32_t)(l * CH3 + c4 * 4) * 4,
                          dtv + (bL + l0 + l) * D_INNER + d0 + c4 * 4, 16);
            } else if (u < 640) {
                int v = u - 448; int l = v / 6, c4 = v % 6;
                cpasync16(xs + (uint32_t)(l * CH3 + c4 * 4) * 4,
                          xc + (bL + l0 + l) * D_INNER + d0 + c4 * 4, 16);
            } else {
                int v = u - 640; int l = v / 6, c4 = v % 6;
                cpasync16(zs + (uint32_t)(l * CH3 + c4 * 4) * 4,
                          xz + (bL + l0 + l) * 2 * D_INNER + D_INNER + d0 + c4 * 4, 16);
            }
        }
        cp_commit();
    };

    issue(0);

    for (int c = 0; c < NCH3; c++) {
        if (c + 1 < NCH3) { issue(c + 1); cp_wait<1>(); }
        else { cp_wait<0>(); }
        __syncthreads();

        int buf = c % 3;
        #pragma unroll 4
        for (int l = 0; l < SCH3; l++) {
            float dt = sD[buf][l][dl];
            float xv = sX[buf][l][dl];
            float Bn = sBC[buf][l][n];
            float Cn = sBC[buf][l][16 + n];
            float e = __expf(dt * An);
            h = fmaf(e, h, dt * xv * Bn);
            float p = h * Cn;
            p += __shfl_xor_sync(0xffffffffu, p, 8);
            p += __shfl_xor_sync(0xffffffffu, p, 4);
            p += __shfl_xor_sync(0xffffffffu, p, 2);
            p += __shfl_xor_sync(0xffffffffu, p, 1);
            if (n == 0) sY[l][dl] = p;
        }
        __syncthreads();

        int l0 = c * SCH3;
        #pragma unroll
        for (int i = 0; i < 2; i++) {
            int l = flb + i * 16;
            float p = sY[l][fdd];
            float xv = sX[buf][l][fdd];
            float zv = sZ[buf][l][fdd];
            float yv = fmaf(xv, Dd, p);
            yv *= zv / (1.f + __expf(-zv));
            size_t o = (bL + l0 + l) * D_INNER + d0 + fdd;
            __nv_bfloat16 hh = __float2bfloat16(yv);
            yh[o] = hh;
            yl[o] = __float2bfloat16(yv - __bfloat162float(hh));
        }
        // no trailing sync needed: next issue targets buf (c+2)%3, flush reads buf c%3,
        // and sY is rewritten only after the next barrier.
    }
}

// ---------------- launch ----------------
extern "C" void kernel_launch(void* const* d_in, const int* in_sizes, int n_in,
                              void* d_out, int out_size) {
    const float* x          = (const float*)d_in[0];
    const float* ln_w       = (const float*)d_in[1];
    const float* ln_b       = (const float*)d_in[2];
    const float* in_proj_w  = (const float*)d_in[3];
    const float* conv_w     = (const float*)d_in[4];
    const float* conv_b     = (const float*)d_in[5];
    const float* x_proj_w   = (const float*)d_in[6];
    const float* dt_w       = (const float*)d_in[7];
    const float* dt_b       = (const float*)d_in[8];
    const float* A_log      = (const float*)d_in[9];
    const float* Dp         = (const float*)d_in[10];
    const float* out_proj_w = (const float*)d_in[11];
    float* out = (float*)d_out;

    float *p_xz, *p_xc, *p_xdbl, *p_dtv;
    __nv_bfloat16 *p_xnh, *p_xnl, *p_xch, *p_xcl, *p_yh, *p_yl;
    __nv_bfloat16 *p_wih, *p_wil, *p_woh, *p_wol, *p_wxh, *p_wxl;
    cudaGetSymbolAddress((void**)&p_xz,   g_xz);
    cudaGetSymbolAddress((void**)&p_xc,   g_xc);
    cudaGetSymbolAddress((void**)&p_xdbl, g_xdbl);
    cudaGetSymbolAddress((void**)&p_dtv,  g_dtv);
    cudaGetSymbolAddress((void**)&p_xnh,  g_xn_hi);
    cudaGetSymbolAddress((void**)&p_xnl,  g_xn_lo);
    cudaGetSymbolAddress((void**)&p_xch,  g_xc_hi);
    cudaGetSymbolAddress((void**)&p_xcl,  g_xc_lo);
    cudaGetSymbolAddress((void**)&p_yh,   g_y_hi);
    cudaGetSymbolAddress((void**)&p_yl,   g_y_lo);
    cudaGetSymbolAddress((void**)&p_wih,  g_wi_hi);
    cudaGetSymbolAddress((void**)&p_wil,  g_wi_lo);
    cudaGetSymbolAddress((void**)&p_woh,  g_wo_hi);
    cudaGetSymbolAddress((void**)&p_wol,  g_wo_lo);
    cudaGetSymbolAddress((void**)&p_wxh,  g_wx_hi);
    cudaGetSymbolAddress((void**)&p_wxl,  g_wx_lo);

    const int MM_SMEM = NSTAGE * BUF_B;   // 122880 B
    cudaFuncSetAttribute(mmagemm_kernel, cudaFuncAttributeMaxDynamicSharedMemorySize, MM_SMEM);

    // 0) weight hi/lo conversion
    {
        int n4i = (2 * D_INNER * DIMC) / 4;
        cvt_kernel<<<(n4i + 255) / 256, 256>>>(in_proj_w, p_wih, p_wil, n4i);
        int n4o = (DIMC * D_INNER) / 4;
        cvt_kernel<<<(n4o + 255) / 256, 256>>>(out_proj_w, p_woh, p_wol, n4o);
        int n4x = (XPN * D_INNER) / 4;
        cvt_kernel<<<(n4x + 255) / 256, 256>>>(x_proj_w, p_wxh, p_wxl, n4x);
    }

    // 1) LayerNorm -> xn hi/lo
    ln_kernel<<<dim3(L_SEQ / 64, B_SZ), 256>>>(x, ln_w, ln_b, p_xnh, p_xnl);

    // 2) in_proj (tensor): (16384,384)x(1536,384)^T -> xz fp32
    mmagemm_kernel<<<dim3(2 * D_INNER / 128, M_TOTAL / 128), 512, MM_SMEM>>>(
        p_xnh, p_xnl, p_wih, p_wil, DIMC, 2 * D_INNER, p_xz, 2 * D_INNER, 0);

    // 3) depthwise conv + silu -> xc fp32 + hi/lo
    {
        int total = M_TOTAL * D_INNER;
        conv_silu_kernel<<<(total + 255) / 256, 256>>>(conv_w, conv_b, p_xz, p_xc, p_xch, p_xcl);
    }

    // 4) x_proj (tensor, N=56 masked): (16384,768)x(56,768)^T -> xdbl fp32
    mmagemm_kernel<<<dim3(1, M_TOTAL / 128), 512, MM_SMEM>>>(
        p_xch, p_xcl, p_wxh, p_wxl, D_INNER, XPN, p_xdbl, XPN, 0);

    // 5) dt + softplus (fp32 SIMT, K=24)
    gemm2_kernel<<<dim3(D_INNER / BN, M_TOTAL / BM), 256>>>(
        p_xdbl, XPN, DT_RANK, dt_w, DT_RANK, D_INNER, p_dtv, D_INNER, 1, dt_b);

    // 6) selective scan v3 -> y hi/lo (128 blocks, 1 per SM)
    scan3_kernel<<<dim3(D_INNER / CH3, B_SZ), 384>>>(
        A_log, Dp, p_dtv, p_xc, p_xdbl, p_xz, p_yh, p_yl);

    // 7) out_proj (tensor, transposed store)
    mmagemm_kernel<<<dim3(DIMC / 128, M_TOTAL / 128), 512, MM_SMEM>>>(
        p_yh, p_yl, p_woh, p_wol, D_INNER, DIMC, out, 0, 2);
}

// round 8
// speedup vs baseline: 6.4862x; 1.2643x over previous
#include <cuda_runtime.h>
#include <cuda_bf16.h>
#include <cstdint>

#define B_SZ 4
#define DIMC 384
#define L_SEQ 4096
#define D_INNER 768
#define D_STATE 16
#define DT_RANK 24
#define XPN 56
#define M_TOTAL (B_SZ * L_SEQ)      // 16384

// ---------------- scratch (no allocations allowed) ----------------
__device__ float g_xz[(size_t)M_TOTAL * 2 * D_INNER];
__device__ float g_xc[(size_t)M_TOTAL * D_INNER];
__device__ float g_xdbl[(size_t)M_TOTAL * XPN];
__device__ float g_dtv[(size_t)M_TOTAL * D_INNER];

__device__ __nv_bfloat16 g_xn_hi[(size_t)M_TOTAL * DIMC];
__device__ __nv_bfloat16 g_xn_lo[(size_t)M_TOTAL * DIMC];
__device__ __nv_bfloat16 g_xc_hi[(size_t)M_TOTAL * D_INNER];
__device__ __nv_bfloat16 g_xc_lo[(size_t)M_TOTAL * D_INNER];
__device__ __nv_bfloat16 g_y_hi[(size_t)M_TOTAL * D_INNER];
__device__ __nv_bfloat16 g_y_lo[(size_t)M_TOTAL * D_INNER];
__device__ __nv_bfloat16 g_wi_hi[(size_t)2 * D_INNER * DIMC];
__device__ __nv_bfloat16 g_wi_lo[(size_t)2 * D_INNER * DIMC];
__device__ __nv_bfloat16 g_wo_hi[(size_t)DIMC * D_INNER];
__device__ __nv_bfloat16 g_wo_lo[(size_t)DIMC * D_INNER];
__device__ __nv_bfloat16 g_wx_hi[(size_t)XPN * D_INNER];
__device__ __nv_bfloat16 g_wx_lo[(size_t)XPN * D_INNER];

// ---------------- small PTX helpers (all base-target, sm_80+) ----------------
__device__ __forceinline__ uint32_t smem_u32(const void* p) {
    uint32_t a;
    asm("{ .reg .u64 t; cvta.to.shared.u64 t, %1; cvt.u32.u64 %0, t; }" : "=r"(a) : "l"(p));
    return a;
}
__device__ __forceinline__ void cpasync16(uint32_t sa, const void* g, int sz) {
    asm volatile("cp.async.cg.shared.global [%0], [%1], 16, %2;" :: "r"(sa), "l"(g), "r"(sz) : "memory");
}
__device__ __forceinline__ void cp_commit() {
    asm volatile("cp.async.commit_group;" ::: "memory");
}
template <int N> __device__ __forceinline__ void cp_wait() {
    asm volatile("cp.async.wait_group %0;" :: "n"(N) : "memory");
}
__device__ __forceinline__ void ldsm4(uint32_t* r, uint32_t addr) {
    asm volatile("ldmatrix.sync.aligned.m8n8.x4.shared.b16 {%0,%1,%2,%3}, [%4];"
                 : "=r"(r[0]), "=r"(r[1]), "=r"(r[2]), "=r"(r[3]) : "r"(addr));
}
__device__ __forceinline__ void mma16816(float* d, const uint32_t* a, const uint32_t* b) {
    asm volatile(
        "mma.sync.aligned.m16n8k16.row.col.f32.bf16.bf16.f32 "
        "{%0,%1,%2,%3}, {%4,%5,%6,%7}, {%8,%9}, {%0,%1,%2,%3};"
        : "+f"(d[0]), "+f"(d[1]), "+f"(d[2]), "+f"(d[3])
        : "r"(a[0]), "r"(a[1]), "r"(a[2]), "r"(a[3]), "r"(b[0]), "r"(b[1]));
}

// ---------------- bf16-split mma.sync GEMM (512 thr, 3-stage cp.async) ----------------
#define LDSROW 40
#define TILE_H (128 * LDSROW)
#define BUF_B  (4 * TILE_H * 2)
#define NSTAGE 3

__global__ __launch_bounds__(512, 1) void mmagemm_kernel(
    const __nv_bfloat16* __restrict__ Ah, const __nv_bfloat16* __restrict__ Al,
    const __nv_bfloat16* __restrict__ Bh, const __nv_bfloat16* __restrict__ Bl,
    int K, int Nn, float* __restrict__ C, int ldc, int mode) {

    extern __shared__ __align__(16) uint8_t dsm[];
    uint32_t dsm_u = smem_u32(dsm);

    int tid = threadIdx.x;
    int wid = tid >> 5;
    int lane = tid & 31;
    int warp_m = wid & 3;
    int warp_n = wid >> 2;
    int m0 = blockIdx.y * 128;
    int n0 = blockIdx.x * 128;

    float acc[2][4][4];
    #pragma unroll
    for (int mt = 0; mt < 2; mt++)
        #pragma unroll
        for (int nt = 0; nt < 4; nt++)
            #pragma unroll
            for (int q = 0; q < 4; q++) acc[mt][nt][q] = 0.f;

    int nchunks = K >> 5;

    auto load_chunk = [&](int c) {
        int kc = c << 5;
        uint32_t sbase = dsm_u + (c % NSTAGE) * BUF_B;
        #pragma unroll
        for (int i = 0; i < 4; i++) {
            int u = tid + i * 512;
            int tile = u >> 9;
            int v = u & 511;
            int row = v >> 2;
            int seg = v & 3;
            uint32_t sa = sbase + (tile * TILE_H + row * LDSROW + seg * 8) * 2;
            const __nv_bfloat16* g;
            int sz = 16;
            if (tile == 0)      g = Ah + (size_t)(m0 + row) * K + kc + seg * 8;
            else if (tile == 1) g = Al + (size_t)(m0 + row) * K + kc + seg * 8;
            else {
                int r = n0 + row;
                if (r >= Nn) { r = Nn - 1; sz = 0; }
                g = ((tile == 2) ? Bh : Bl) + (size_t)r * K + kc + seg * 8;
            }
            cpasync16(sa, g, sz);
        }
        cp_commit();
    };

    load_chunk(0);
    load_chunk(1);

    for (int c = 0; c < nchunks; c++) {
        if (c + 2 < nchunks) { load_chunk(c + 2); cp_wait<2>(); }
        else if (c + 1 < nchunks) { cp_wait<1>(); }
        else { cp_wait<0>(); }
        __syncthreads();

        uint32_t base = dsm_u + (c % NSTAGE) * BUF_B;
        #pragma unroll
        for (int kk = 0; kk < 32; kk += 16) {
            uint32_t aH[2][4], aL[2][4], bH[4][2], bL[4][2];
            {
                int arow = warp_m * 32 + (lane & 15);
                int ak = kk + (lane >> 4) * 8;
                #pragma unroll
                for (int mt = 0; mt < 2; mt++) {
                    uint32_t addr = base + ((arow + mt * 16) * LDSROW + ak) * 2;
                    ldsm4(aH[mt], addr);
                    ldsm4(aL[mt], addr + TILE_H * 2);
                }
            }
            {
                int brow = warp_n * 32 + (lane & 7) + (lane >> 4) * 8;
                int bk = kk + ((lane >> 3) & 1) * 8;
                #pragma unroll
                for (int g2 = 0; g2 < 2; g2++) {
                    uint32_t addr = base + 2 * TILE_H * 2 + ((brow + g2 * 16) * LDSROW + bk) * 2;
                    uint32_t r[4];
                    ldsm4(r, addr);
                    bH[g2 * 2][0] = r[0]; bH[g2 * 2][1] = r[1];
                    bH[g2 * 2 + 1][0] = r[2]; bH[g2 * 2 + 1][1] = r[3];
                    ldsm4(r, addr + TILE_H * 2);
                    bL[g2 * 2][0] = r[0]; bL[g2 * 2][1] = r[1];
                    bL[g2 * 2 + 1][0] = r[2]; bL[g2 * 2 + 1][1] = r[3];
                }
            }
            #pragma unroll
            for (int mt = 0; mt < 2; mt++)
                #pragma unroll
                for (int nt = 0; nt < 4; nt++) {
                    mma16816(acc[mt][nt], aH[mt], bH[nt]);
                    mma16816(acc[mt][nt], aH[mt], bL[nt]);
                    mma16816(acc[mt][nt], aL[mt], bH[nt]);
                }
        }
        __syncthreads();
    }

    if (mode == 0) {
        #pragma unroll
        for (int mt = 0; mt < 2; mt++) {
            int m = m0 + warp_m * 32 + mt * 16 + (lane >> 2);
            #pragma unroll
            for (int nt = 0; nt < 4; nt++) {
                int n = n0 + warp_n * 32 + nt * 8 + (lane & 3) * 2;
                if (n < Nn) {
                    float2 v0 = make_float2(acc[mt][nt][0], acc[mt][nt][1]);
                    float2 v1 = make_float2(acc[mt][nt][2], acc[mt][nt][3]);
                    *(float2*)&C[(size_t)m * ldc + n] = v0;
                    *(float2*)&C[(size_t)(m + 8) * ldc + n] = v1;
                }
            }
        }
    } else {
        float* sT = (float*)dsm;   // [128 n][132 m]
        #pragma unroll
        for (int mt = 0; mt < 2; mt++) {
            int ml = warp_m * 32 + mt * 16 + (lane >> 2);
            #pragma unroll
            for (int nt = 0; nt < 4; nt++) {
                int nl = warp_n * 32 + nt * 8 + (lane & 3) * 2;
                sT[nl * 132 + ml]           = acc[mt][nt][0];
                sT[(nl + 1) * 132 + ml]     = acc[mt][nt][1];
                sT[nl * 132 + ml + 8]       = acc[mt][nt][2];
                sT[(nl + 1) * 132 + ml + 8] = acc[mt][nt][3];
            }
        }
        __syncthreads();
        int b = m0 >> 12;
        int l0 = m0 & (L_SEQ - 1);
        int n = tid >> 2;
        int part = (tid & 3) * 32;
        float* dst = C + ((size_t)b * DIMC + n0 + n) * L_SEQ + l0 + part;
        const float* src = sT + n * 132 + part;
        #pragma unroll
        for (int q = 0; q < 8; q++)
            *(float4*)(dst + q * 4) = *(const float4*)(src + q * 4);
    }
}

// ---------------- fp32 -> bf16 hi/lo split (single array) ----------------
__global__ __launch_bounds__(256) void cvt_kernel(const float* __restrict__ s,
                                                  __nv_bfloat16* __restrict__ hi,
                                                  __nv_bfloat16* __restrict__ lo, int n4) {
    int i = blockIdx.x * blockDim.x + threadIdx.x;
    if (i >= n4) return;
    float4 v = *(const float4*)(s + (size_t)i * 4);
    float vv[4] = {v.x, v.y, v.z, v.w};
    #pragma unroll
    for (int j = 0; j < 4; j++) {
        __nv_bfloat16 h = __float2bfloat16(vv[j]);
        hi[(size_t)i * 4 + j] = h;
        lo[(size_t)i * 4 + j] = __float2bfloat16(vv[j] - __bfloat162float(h));
    }
}

// ---------------- cvt for two arrays in one launch ----------------
__global__ __launch_bounds__(256) void cvt2_kernel(
    const float* __restrict__ s0, __nv_bfloat16* __restrict__ hi0, __nv_bfloat16* __restrict__ lo0, int n40,
    const float* __restrict__ s1, __nv_bfloat16* __restrict__ hi1, __nv_bfloat16* __restrict__ lo1, int n41) {
    int i = blockIdx.x * blockDim.x + threadIdx.x;
    const float* s; __nv_bfloat16 *hi, *lo;
    if (i < n40) { s = s0; hi = hi0; lo = lo0; }
    else { i -= n40; if (i >= n41) return; s = s1; hi = hi1; lo = lo1; }
    float4 v = *(const float4*)(s + (size_t)i * 4);
    float vv[4] = {v.x, v.y, v.z, v.w};
    #pragma unroll
    for (int j = 0; j < 4; j++) {
        __nv_bfloat16 h = __float2bfloat16(vv[j]);
        hi[(size_t)i * 4 + j] = h;
        lo[(size_t)i * 4 + j] = __float2bfloat16(vv[j] - __bfloat162float(h));
    }
}

// ---------------- LayerNorm: x (B,C,L) -> xn hi/lo (B*L, C) bf16 ----------------
__global__ __launch_bounds__(256) void ln_kernel(const float* __restrict__ x,
                                                 const float* __restrict__ w,
                                                 const float* __restrict__ bsh,
                                                 __nv_bfloat16* __restrict__ xnh,
                                                 __nv_bfloat16* __restrict__ xnl) {
    int b  = blockIdx.y;
    int l0 = blockIdx.x * 64;
    int tid = threadIdx.x;
    int ll = tid & 63;
    int cg = tid >> 6;

    __shared__ float ssum[4][64];
    __shared__ float ssq[4][64];
    __shared__ float smean[64];
    __shared__ float srstd[64];
    __shared__ float st[16][65];

    const float* xb = x + (size_t)b * DIMC * L_SEQ;

    float s = 0.f, sq = 0.f;
    for (int c = cg; c < DIMC; c += 4) {
        float v = xb[(size_t)c * L_SEQ + l0 + ll];
        s += v; sq += v * v;
    }
    ssum[cg][ll] = s; ssq[cg][ll] = sq;
    __syncthreads();
    if (tid < 64) {
        float S = ssum[0][tid] + ssum[1][tid] + ssum[2][tid] + ssum[3][tid];
        float Q = ssq[0][tid] + ssq[1][tid] + ssq[2][tid] + ssq[3][tid];
        float mu = S * (1.f / DIMC);
        float var = Q * (1.f / DIMC) - mu * mu;
        smean[tid] = mu;
        srstd[tid] = rsqrtf(var + 1e-5f);
    }
    __syncthreads();

    for (int c0 = 0; c0 < DIMC; c0 += 16) {
        #pragma unroll
        for (int r = 0; r < 4; r++) {
            int c = c0 + cg + r * 4;
            float v = xb[(size_t)c * L_SEQ + l0 + ll];
            st[cg + r * 4][ll] = (v - smean[ll]) * srstd[ll] * w[c] + bsh[c];
        }
        __syncthreads();
        int c2 = tid & 15, lr = tid >> 4;
        #pragma unroll
        for (int p = 0; p < 4; p++) {
            int l = lr + p * 16;
            float v = st[c2][l];
            __nv_bfloat16 h = __float2bfloat16(v);
            size_t o = ((size_t)b * L_SEQ + l0 + l) * DIMC + c0 + c2;
            xnh[o] = h;
            xnl[o] = __float2bfloat16(v - __bfloat162float(h));
        }
        __syncthreads();
    }
}

// ---------------- fp32 tiled GEMM (dt only) ----------------
#define BM 128
#define BN 128
#define BKK 16
#define PAD 4

__global__ __launch_bounds__(256, 2) void gemm2_kernel(
    const float* __restrict__ A, int lda, int K,
    const float* __restrict__ W, int ldw, int N,
    float* __restrict__ C, int ldc, int mode,
    const float* __restrict__ bias) {

    __shared__ float As[2][BKK][BM + PAD];
    __shared__ float Bs[2][BKK][BN + PAD];

    int tid = threadIdx.x;
    int m0 = blockIdx.y * BM;
    int n0 = blockIdx.x * BN;
    int tm = tid & 15;
    int tn = tid >> 4;

    int lr = tid >> 2;
    int lk = (tid & 3) * 4;

    float4 pa[2], pb[2];
    int nt = (K + BKK - 1) / BKK;

    {
        int kk = lk;
        #pragma unroll
        for (int r = 0; r < 2; r++) {
            int m = lr + r * 64;
            float4 v = make_float4(0.f, 0.f, 0.f, 0.f);
            if (kk < K) v = *(const float4*)&A[(size_t)(m0 + m) * lda + kk];
            pa[r] = v;
            float4 u = make_float4(0.f, 0.f, 0.f, 0.f);
            if (kk < K && (n0 + m) < N) u = *(const float4*)&W[(size_t)(n0 + m) * ldw + kk];
            pb[r] = u;
        }
    }

    float acc[8][8];
    #pragma unroll
    for (int i = 0; i < 8; i++)
        #pragma unroll
        for (int j = 0; j < 8; j++) acc[i][j] = 0.f;

    for (int t = 0; t < nt; t++) {
        int buf = t & 1;
        #pragma unroll
        for (int r = 0; r < 2; r++) {
            int m = lr + r * 64;
            As[buf][lk + 0][m] = pa[r].x;
            As[buf][lk + 1][m] = pa[r].y;
            As[buf][lk + 2][m] = pa[r].z;
            As[buf][lk + 3][m] = pa[r].w;
            Bs[buf][lk + 0][m] = pb[r].x;
            Bs[buf][lk + 1][m] = pb[r].y;
            Bs[buf][lk + 2][m] = pb[r].z;
            Bs[buf][lk + 3][m] = pb[r].w;
        }
        __syncthreads();

        if (t + 1 < nt) {
            int kk = (t + 1) * BKK + lk;
            #pragma unroll
            for (int r = 0; r < 2; r++) {
                int m = lr + r * 64;
                float4 v = make_float4(0.f, 0.f, 0.f, 0.f);
                if (kk < K) v = *(const float4*)&A[(size_t)(m0 + m) * lda + kk];
                pa[r] = v;
                float4 u = make_float4(0.f, 0.f, 0.f, 0.f);
                if (kk < K && (n0 + m) < N) u = *(const float4*)&W[(size_t)(n0 + m) * ldw + kk];
                pb[r] = u;
            }
        }

        const float (*Ab)[BM + PAD] = As[buf];
        const float (*Bb)[BN + PAD] = Bs[buf];
        #pragma unroll
        for (int k = 0; k < BKK; k++) {
            float a[8], b[8];
            *(float4*)&a[0] = *(const float4*)&Ab[k][tm * 4];
            *(float4*)&a[4] = *(const float4*)&Ab[k][64 + tm * 4];
            *(float4*)&b[0] = *(const float4*)&Bb[k][tn * 4];
            *(float4*)&b[4] = *(const float4*)&Bb[k][64 + tn * 4];
            #pragma unroll
            for (int i = 0; i < 8; i++)
                #pragma unroll
                for (int j = 0; j < 8; j++)
                    acc[i][j] = fmaf(a[i], b[j], acc[i][j]);
        }
        __syncthreads();
    }

    #pragma unroll
    for (int ih = 0; ih < 2; ih++) {
        #pragma unroll
        for (int i4 = 0; i4 < 4; i4++) {
            int i = ih * 4 + i4;
            int m = m0 + ih * 64 + tm * 4 + i4;
            #pragma unroll
            for (int jh = 0; jh < 2; jh++) {
                int n = n0 + jh * 64 + tn * 4;
                if (n < N) {
                    float4 v = make_float4(acc[i][jh * 4 + 0], acc[i][jh * 4 + 1],
                                           acc[i][jh * 4 + 2], acc[i][jh * 4 + 3]);
                    if (mode == 1) {
                        float* vv = (float*)&v;
                        #pragma unroll
                        for (int j = 0; j < 4; j++) {
                            float z = vv[j] + bias[n + j];
                            vv[j] = fmaxf(z, 0.f) + log1pf(__expf(-fabsf(z)));
                        }
                    }
                    if (n + 3 < N) {
                        *(float4*)&C[(size_t)m * ldc + n] = v;
                    } else {
                        float* vv = (float*)&v;
                        #pragma unroll
                        for (int j = 0; j < 4; j++)
                            if (n + j < N) C[(size_t)m * ldc + n + j] = vv[j];
                    }
                }
            }
        }
    }
}

// ---------------- depthwise causal conv1d (k=4) + SiLU; emits fp32 + bf16 hi/lo ----------------
__global__ __launch_bounds__(256) void conv_silu_kernel(const float* __restrict__ cw,
                                                        const float* __restrict__ cb,
                                                        const float* __restrict__ xz,
                                                        float* __restrict__ xc,
                                                        __nv_bfloat16* __restrict__ xch,
                                                        __nv_bfloat16* __restrict__ xcl) {
    int idx = blockIdx.x * blockDim.x + threadIdx.x;
    if (idx >= M_TOTAL * D_INNER) return;
    int d = idx % D_INNER;
    int m = idx / D_INNER;
    int l = m & (L_SEQ - 1);

    float w0 = cw[d * 4 + 0], w1 = cw[d * 4 + 1];
    float w2 = cw[d * 4 + 2], w3 = cw[d * 4 + 3];

    const float* xb = xz + (size_t)m * (2 * D_INNER) + d;
    float acc = cb[d];
    if (l >= 3) acc = fmaf(w0, xb[-3 * 2 * D_INNER], acc);
    if (l >= 2) acc = fmaf(w1, xb[-2 * 2 * D_INNER], acc);
    if (l >= 1) acc = fmaf(w2, xb[-1 * 2 * D_INNER], acc);
    acc = fmaf(w3, xb[0], acc);
    float sg = 1.f / (1.f + __expf(-acc));
    float v = acc * sg;
    size_t o = (size_t)m * D_INNER + d;
    xc[o] = v;
    __nv_bfloat16 h = __float2bfloat16(v);
    xch[o] = h;
    xcl[o] = __float2bfloat16(v - __bfloat162float(h));
}

// ---------------- selective scan v4: phase-split (no shfl), cp.async 3-stage ----------------
// grid (32, 4), 384 threads. Warp w owns channels 2w, 2w+1; lane = half*16 + n.
// Scan phase stores h*C_n to sP; reduce phase (1 sum/thread) does gate + bf16 store.
#define SCH4 16
#define CH4 24
#define NST4 3
#define NCH4 (L_SEQ / SCH4)     // 256
// dynamic smem (floats): sBC[3][16][32] | sD[3][16][24] | sX | sZ | sP[16][24][20]
#define S4_BC 0
#define S4_D  1536
#define S4_X  2688
#define S4_Z  3840
#define S4_P  4992
#define S4_TOTAL (4992 + 16 * 24 * 20)   // 12672 floats = 50688 B

__global__ __launch_bounds__(384) void scan4_kernel(const float* __restrict__ A_log,
                                                    const float* __restrict__ Dp,
                                                    const float* __restrict__ dtv,
                                                    const float* __restrict__ xc,
                                                    const float* __restrict__ xdbl,
                                                    const float* __restrict__ xz,
                                                    __nv_bfloat16* __restrict__ yh,
                                                    __nv_bfloat16* __restrict__ yl) {
    extern __shared__ float sm4[];
    float* sBC = sm4 + S4_BC;
    float* sD  = sm4 + S4_D;
    float* sX  = sm4 + S4_X;
    float* sZ  = sm4 + S4_Z;
    float* sP  = sm4 + S4_P;

    int b = blockIdx.y;
    int g = blockIdx.x;
    int d0 = g * CH4;
    int tid = threadIdx.x;
    size_t bL = (size_t)b * L_SEQ;

    int lane = tid & 31;
    int w = tid >> 5;
    int half = lane >> 4;
    int n = lane & 15;
    int dl = 2 * w + half;          // channel within group, 0..23

    float An = -__expf(A_log[(d0 + dl) * D_STATE + n]);
    float h = 0.f;

    int rl = tid / CH4;             // reduce: step 0..15
    int rc = tid % CH4;             // reduce: channel 0..23
    float Dd = Dp[d0 + rc];

    auto issue = [&](int c) {
        int l0 = c * SCH4;
        int buf = c % NST4;
        uint32_t bcs = smem_u32(sBC + buf * 512);
        uint32_t ds  = smem_u32(sD  + buf * 384);
        uint32_t xs  = smem_u32(sX  + buf * 384);
        uint32_t zs  = smem_u32(sZ  + buf * 384);
        for (int u = tid; u < 416; u += 384) {
            if (u < 128) {
                int l = u >> 3, c4 = u & 7;
                cpasync16(bcs + (uint32_t)(l * 32 + c4 * 4) * 4,
                          xdbl + (bL + l0 + l) * XPN + DT_RANK + c4 * 4, 16);
            } else if (u < 224) {
                int v = u - 128; int l = v / 6, c4 = v % 6;
                cpasync16(ds + (uint32_t)(l * 24 + c4 * 4) * 4,
                          dtv + (bL + l0 + l) * D_INNER + d0 + c4 * 4, 16);
            } else if (u < 320) {
                int v = u - 224; int l = v / 6, c4 = v % 6;
                cpasync16(xs + (uint32_t)(l * 24 + c4 * 4) * 4,
                          xc + (bL + l0 + l) * D_INNER + d0 + c4 * 4, 16);
            } else {
                int v = u - 320; int l = v / 6, c4 = v % 6;
                cpasync16(zs + (uint32_t)(l * 24 + c4 * 4) * 4,
                          xz + (bL + l0 + l) * 2 * D_INNER + D_INNER + d0 + c4 * 4, 16);
            }
        }
        cp_commit();
    };

    issue(0);
    issue(1);

    for (int c = 0; c < NCH4; c++) {
        if (c + 2 < NCH4) { issue(c + 2); cp_wait<2>(); }
        else if (c + 1 < NCH4) { cp_wait<1>(); }
        else { cp_wait<0>(); }
        __syncthreads();

        int buf = c % NST4;
        const float* bD  = sD  + buf * 384;
        const float* bX  = sX  + buf * 384;
        const float* bBC = sBC + buf * 512;

        // scan phase: carried dep = 1 FFMA; no reductions
        #pragma unroll
        for (int l = 0; l < SCH4; l++) {
            float dt = bD[l * 24 + dl];
            float xv = bX[l * 24 + dl];
            float Bn = bBC[l * 32 + n];
            float Cn = bBC[l * 32 + 16 + n];
            float e = __expf(dt * An);
            h = fmaf(e, h, dt * xv * Bn);
            sP[(l * 24 + dl) * 20 + n] = h * Cn;
        }
        __syncthreads();

        // reduce phase: one (step, channel) per thread
        {
            const float* p = sP + (rl * 24 + rc) * 20;
            float4 a  = *(const float4*)p;
            float4 bq = *(const float4*)(p + 4);
            float4 cq = *(const float4*)(p + 8);
            float4 dq = *(const float4*)(p + 12);
            float s = ((a.x + a.y) + (a.z + a.w)) + ((bq.x + bq.y) + (bq.z + bq.w))
                    + ((cq.x + cq.y) + (cq.z + cq.w)) + ((dq.x + dq.y) + (dq.z + dq.w));
            float xv = bX[rl * 24 + rc];
            float zv = sZ[buf * 384 + rl * 24 + rc];
            float yv = fmaf(xv, Dd, s);
            yv *= zv / (1.f + __expf(-zv));
            size_t o = (bL + (size_t)c * SCH4 + rl) * D_INNER + d0 + rc;
            __nv_bfloat16 hh = __float2bfloat16(yv);
            yh[o] = hh;
            yl[o] = __float2bfloat16(yv - __bfloat162float(hh));
        }
        // next issue targets stage (c+2)%3 != c, and sP is rewritten only after
        // the next __syncthreads(), so no extra barrier is needed here.
    }
}

// ---------------- launch ----------------
extern "C" void kernel_launch(void* const* d_in, const int* in_sizes, int n_in,
                              void* d_out, int out_size) {
    const float* x          = (const float*)d_in[0];
    const float* ln_w       = (const float*)d_in[1];
    const float* ln_b       = (const float*)d_in[2];
    const float* in_proj_w  = (const float*)d_in[3];
    const float* conv_w     = (const float*)d_in[4];
    const float* conv_b     = (const float*)d_in[5];
    const float* x_proj_w   = (const float*)d_in[6];
    const float* dt_w       = (const float*)d_in[7];
    const float* dt_b       = (const float*)d_in[8];
    const float* A_log      = (const float*)d_in[9];
    const float* Dp         = (const float*)d_in[10];
    const float* out_proj_w = (const float*)d_in[11];
    float* out = (float*)d_out;

    float *p_xz, *p_xc, *p_xdbl, *p_dtv;
    __nv_bfloat16 *p_xnh, *p_xnl, *p_xch, *p_xcl, *p_yh, *p_yl;
    __nv_bfloat16 *p_wih, *p_wil, *p_woh, *p_wol, *p_wxh, *p_wxl;
    cudaGetSymbolAddress((void**)&p_xz,   g_xz);
    cudaGetSymbolAddress((void**)&p_xc,   g_xc);
    cudaGetSymbolAddress((void**)&p_xdbl, g_xdbl);
    cudaGetSymbolAddress((void**)&p_dtv,  g_dtv);
    cudaGetSymbolAddress((void**)&p_xnh,  g_xn_hi);
    cudaGetSymbolAddress((void**)&p_xnl,  g_xn_lo);
    cudaGetSymbolAddress((void**)&p_xch,  g_xc_hi);
    cudaGetSymbolAddress((void**)&p_xcl,  g_xc_lo);
    cudaGetSymbolAddress((void**)&p_yh,   g_y_hi);
    cudaGetSymbolAddress((void**)&p_yl,   g_y_lo);
    cudaGetSymbolAddress((void**)&p_wih,  g_wi_hi);
    cudaGetSymbolAddress((void**)&p_wil,  g_wi_lo);
    cudaGetSymbolAddress((void**)&p_woh,  g_wo_hi);
    cudaGetSymbolAddress((void**)&p_wol,  g_wo_lo);
    cudaGetSymbolAddress((void**)&p_wxh,  g_wx_hi);
    cudaGetSymbolAddress((void**)&p_wxl,  g_wx_lo);

    const int MM_SMEM = NSTAGE * BUF_B;        // 122880 B
    const int SC_SMEM = S4_TOTAL * 4;          // 50688 B
    cudaFuncSetAttribute(mmagemm_kernel, cudaFuncAttributeMaxDynamicSharedMemorySize, MM_SMEM);
    cudaFuncSetAttribute(scan4_kernel, cudaFuncAttributeMaxDynamicSharedMemorySize, SC_SMEM);

    // 0) weight hi/lo conversion (2 launches so in_proj mma lands in the profiled slot)
    int n4i = (2 * D_INNER * DIMC) / 4;
    cvt_kernel<<<(n4i + 255) / 256, 256>>>(in_proj_w, p_wih, p_wil, n4i);
    int n4o = (DIMC * D_INNER) / 4;
    int n4x = (XPN * D_INNER) / 4;
    cvt2_kernel<<<(n4o + n4x + 255) / 256, 256>>>(out_proj_w, p_woh, p_wol, n4o,
                                                  x_proj_w, p_wxh, p_wxl, n4x);

    // 1) LayerNorm -> xn hi/lo
    ln_kernel<<<dim3(L_SEQ / 64, B_SZ), 256>>>(x, ln_w, ln_b, p_xnh, p_xnl);

    // 2) in_proj (tensor) — profiled slot
    mmagemm_kernel<<<dim3(2 * D_INNER / 128, M_TOTAL / 128), 512, MM_SMEM>>>(
        p_xnh, p_xnl, p_wih, p_wil, DIMC, 2 * D_INNER, p_xz, 2 * D_INNER, 0);

    // 3) depthwise conv + silu -> xc fp32 + hi/lo
    {
        int total = M_TOTAL * D_INNER;
        conv_silu_kernel<<<(total + 255) / 256, 256>>>(conv_w, conv_b, p_xz, p_xc, p_xch, p_xcl);
    }

    // 4) x_proj (tensor, N=56 masked)
    mmagemm_kernel<<<dim3(1, M_TOTAL / 128), 512, MM_SMEM>>>(
        p_xch, p_xcl, p_wxh, p_wxl, D_INNER, XPN, p_xdbl, XPN, 0);

    // 5) dt + softplus (fp32 SIMT, K=24)
    gemm2_kernel<<<dim3(D_INNER / BN, M_TOTAL / BM), 256>>>(
        p_xdbl, XPN, DT_RANK, dt_w, DT_RANK, D_INNER, p_dtv, D_INNER, 1, dt_b);

    // 6) selective scan v4 -> y hi/lo
    scan4_kernel<<<dim3(D_INNER / CH4, B_SZ), 384, SC_SMEM>>>(
        A_log, Dp, p_dtv, p_xc, p_xdbl, p_xz, p_yh, p_yl);

    // 7) out_proj (tensor, transposed store)
    mmagemm_kernel<<<dim3(DIMC / 128, M_TOTAL / 128), 512, MM_SMEM>>>(
        p_yh, p_yl, p_woh, p_wol, D_INNER, DIMC, out, 0, 2);
}

// round 9
// speedup vs baseline: 6.9985x; 1.0790x over previous
#include <cuda_runtime.h>
#include <cuda_bf16.h>
#include <cstdint>

#define B_SZ 4
#define DIMC 384
#define L_SEQ 4096
#define D_INNER 768
#define D_STATE 16
#define DT_RANK 24
#define XPN 56
#define M_TOTAL (B_SZ * L_SEQ)      // 16384

// ---------------- scratch (no allocations allowed) ----------------
__device__ float g_xz[(size_t)M_TOTAL * 2 * D_INNER];
__device__ float g_xc[(size_t)M_TOTAL * D_INNER];
__device__ float g_xdbl[(size_t)M_TOTAL * XPN];
__device__ float g_dtv[(size_t)M_TOTAL * D_INNER];

__device__ __nv_bfloat16 g_xn_hi[(size_t)M_TOTAL * DIMC];
__device__ __nv_bfloat16 g_xn_lo[(size_t)M_TOTAL * DIMC];
__device__ __nv_bfloat16 g_xc_hi[(size_t)M_TOTAL * D_INNER];
__device__ __nv_bfloat16 g_xc_lo[(size_t)M_TOTAL * D_INNER];
__device__ __nv_bfloat16 g_y_hi[(size_t)M_TOTAL * D_INNER];
__device__ __nv_bfloat16 g_y_lo[(size_t)M_TOTAL * D_INNER];
__device__ __nv_bfloat16 g_wi_hi[(size_t)2 * D_INNER * DIMC];
__device__ __nv_bfloat16 g_wi_lo[(size_t)2 * D_INNER * DIMC];
__device__ __nv_bfloat16 g_wo_hi[(size_t)DIMC * D_INNER];
__device__ __nv_bfloat16 g_wo_lo[(size_t)DIMC * D_INNER];
__device__ __nv_bfloat16 g_wx_hi[(size_t)XPN * D_INNER];
__device__ __nv_bfloat16 g_wx_lo[(size_t)XPN * D_INNER];

// ---------------- small PTX helpers (all base-target, sm_80+) ----------------
__device__ __forceinline__ uint32_t smem_u32(const void* p) {
    uint32_t a;
    asm("{ .reg .u64 t; cvta.to.shared.u64 t, %1; cvt.u32.u64 %0, t; }" : "=r"(a) : "l"(p));
    return a;
}
__device__ __forceinline__ void cpasync16(uint32_t sa, const void* g, int sz) {
    asm volatile("cp.async.cg.shared.global [%0], [%1], 16, %2;" :: "r"(sa), "l"(g), "r"(sz) : "memory");
}
__device__ __forceinline__ void cp_commit() {
    asm volatile("cp.async.commit_group;" ::: "memory");
}
template <int N> __device__ __forceinline__ void cp_wait() {
    asm volatile("cp.async.wait_group %0;" :: "n"(N) : "memory");
}
__device__ __forceinline__ void ldsm4(uint32_t* r, uint32_t addr) {
    asm volatile("ldmatrix.sync.aligned.m8n8.x4.shared.b16 {%0,%1,%2,%3}, [%4];"
                 : "=r"(r[0]), "=r"(r[1]), "=r"(r[2]), "=r"(r[3]) : "r"(addr));
}
__device__ __forceinline__ void mma16816(float* d, const uint32_t* a, const uint32_t* b) {
    asm volatile(
        "mma.sync.aligned.m16n8k16.row.col.f32.bf16.bf16.f32 "
        "{%0,%1,%2,%3}, {%4,%5,%6,%7}, {%8,%9}, {%0,%1,%2,%3};"
        : "+f"(d[0]), "+f"(d[1]), "+f"(d[2]), "+f"(d[3])
        : "r"(a[0]), "r"(a[1]), "r"(a[2]), "r"(a[3]), "r"(b[0]), "r"(b[1]));
}

// ---------------- bf16-split mma.sync GEMM (512 thr, 5-stage, 1 barrier/chunk) ----------------
// C[m,n] = sum_k A[m,k]*W[n,k];  A = Ah+Al, W = Bh+Bl.
// Hazard proof for single barrier: iter c issues cp.async to stage (c+3)%5, whose
// previous reader is compute(c-2). Thread order in iter c-1: issue(c+2) -> wait ->
// BAR(c-1) -> compute(c-1); every thread's compute(c-2) precedes its BAR(c-1) arrival,
// and any thread reaches issue(c+3) only after passing BAR(c-1). So the overwrite is
// ordered after all reads. (Requires NSTAGE >= depth + 2.)
#define LDSROW 40
#define TILE_H (128 * LDSROW)
#define BUF_B  (4 * TILE_H * 2)   // 40960 B per stage
#define NSTAGE 5

__global__ __launch_bounds__(512, 1) void mmagemm_kernel(
    const __nv_bfloat16* __restrict__ Ah, const __nv_bfloat16* __restrict__ Al,
    const __nv_bfloat16* __restrict__ Bh, const __nv_bfloat16* __restrict__ Bl,
    int K, int Nn, float* __restrict__ C, int ldc, int mode) {

    extern __shared__ __align__(16) uint8_t dsm[];
    uint32_t dsm_u = smem_u32(dsm);

    int tid = threadIdx.x;
    int wid = tid >> 5;
    int lane = tid & 31;
    int warp_m = wid & 3;
    int warp_n = wid >> 2;
    int m0 = blockIdx.y * 128;
    int n0 = blockIdx.x * 128;

    float acc[2][4][4];
    #pragma unroll
    for (int mt = 0; mt < 2; mt++)
        #pragma unroll
        for (int nt = 0; nt < 4; nt++)
            #pragma unroll
            for (int q = 0; q < 4; q++) acc[mt][nt][q] = 0.f;

    int nchunks = K >> 5;

    auto load_chunk = [&](int c) {
        int kc = c << 5;
        uint32_t sbase = dsm_u + (c % NSTAGE) * BUF_B;
        #pragma unroll
        for (int i = 0; i < 4; i++) {
            int u = tid + i * 512;
            int tile = u >> 9;
            int v = u & 511;
            int row = v >> 2;
            int seg = v & 3;
            uint32_t sa = sbase + (tile * TILE_H + row * LDSROW + seg * 8) * 2;
            const __nv_bfloat16* g;
            int sz = 16;
            if (tile == 0)      g = Ah + (size_t)(m0 + row) * K + kc + seg * 8;
            else if (tile == 1) g = Al + (size_t)(m0 + row) * K + kc + seg * 8;
            else {
                int r = n0 + row;
                if (r >= Nn) { r = Nn - 1; sz = 0; }
                g = ((tile == 2) ? Bh : Bl) + (size_t)r * K + kc + seg * 8;
            }
            cpasync16(sa, g, sz);
        }
        cp_commit();
    };

    load_chunk(0);
    load_chunk(1);
    load_chunk(2);

    for (int c = 0; c < nchunks; c++) {
        if (c + 3 < nchunks) { load_chunk(c + 3); cp_wait<3>(); }
        else if (c + 2 < nchunks) { cp_wait<2>(); }
        else if (c + 1 < nchunks) { cp_wait<1>(); }
        else { cp_wait<0>(); }
        __syncthreads();   // single barrier per chunk (see hazard proof above)

        uint32_t base = dsm_u + (c % NSTAGE) * BUF_B;
        #pragma unroll
        for (int kk = 0; kk < 32; kk += 16) {
            uint32_t aH[2][4], aL[2][4], bH[4][2], bL[4][2];
            {
                int arow = warp_m * 32 + (lane & 15);
                int ak = kk + (lane >> 4) * 8;
                #pragma unroll
                for (int mt = 0; mt < 2; mt++) {
                    uint32_t addr = base + ((arow + mt * 16) * LDSROW + ak) * 2;
                    ldsm4(aH[mt], addr);
                    ldsm4(aL[mt], addr + TILE_H * 2);
                }
            }
            {
                int brow = warp_n * 32 + (lane & 7) + (lane >> 4) * 8;
                int bk = kk + ((lane >> 3) & 1) * 8;
                #pragma unroll
                for (int g2 = 0; g2 < 2; g2++) {
                    uint32_t addr = base + 2 * TILE_H * 2 + ((brow + g2 * 16) * LDSROW + bk) * 2;
                    uint32_t r[4];
                    ldsm4(r, addr);
                    bH[g2 * 2][0] = r[0]; bH[g2 * 2][1] = r[1];
                    bH[g2 * 2 + 1][0] = r[2]; bH[g2 * 2 + 1][1] = r[3];
                    ldsm4(r, addr + TILE_H * 2);
                    bL[g2 * 2][0] = r[0]; bL[g2 * 2][1] = r[1];
                    bL[g2 * 2 + 1][0] = r[2]; bL[g2 * 2 + 1][1] = r[3];
                }
            }
            #pragma unroll
            for (int mt = 0; mt < 2; mt++)
                #pragma unroll
                for (int nt = 0; nt < 4; nt++) {
                    mma16816(acc[mt][nt], aH[mt], bH[nt]);
                    mma16816(acc[mt][nt], aH[mt], bL[nt]);
                    mma16816(acc[mt][nt], aL[mt], bH[nt]);
                }
        }
    }
    __syncthreads();   // all compute done before epilogue may reuse dsm

    if (mode == 0) {
        #pragma unroll
        for (int mt = 0; mt < 2; mt++) {
            int m = m0 + warp_m * 32 + mt * 16 + (lane >> 2);
            #pragma unroll
            for (int nt = 0; nt < 4; nt++) {
                int n = n0 + warp_n * 32 + nt * 8 + (lane & 3) * 2;
                if (n < Nn) {
                    float2 v0 = make_float2(acc[mt][nt][0], acc[mt][nt][1]);
                    float2 v1 = make_float2(acc[mt][nt][2], acc[mt][nt][3]);
                    *(float2*)&C[(size_t)m * ldc + n] = v0;
                    *(float2*)&C[(size_t)(m + 8) * ldc + n] = v1;
                }
            }
        }
    } else {
        float* sT = (float*)dsm;   // [128 n][132 m]
        #pragma unroll
        for (int mt = 0; mt < 2; mt++) {
            int ml = warp_m * 32 + mt * 16 + (lane >> 2);
            #pragma unroll
            for (int nt = 0; nt < 4; nt++) {
                int nl = warp_n * 32 + nt * 8 + (lane & 3) * 2;
                sT[nl * 132 + ml]           = acc[mt][nt][0];
                sT[(nl + 1) * 132 + ml]     = acc[mt][nt][1];
                sT[nl * 132 + ml + 8]       = acc[mt][nt][2];
                sT[(nl + 1) * 132 + ml + 8] = acc[mt][nt][3];
            }
        }
        __syncthreads();
        int b = m0 >> 12;
        int l0 = m0 & (L_SEQ - 1);
        int n = tid >> 2;
        int part = (tid & 3) * 32;
        float* dst = C + ((size_t)b * DIMC + n0 + n) * L_SEQ + l0 + part;
        const float* src = sT + n * 132 + part;
        #pragma unroll
        for (int q = 0; q < 8; q++)
            *(float4*)(dst + q * 4) = *(const float4*)(src + q * 4);
    }
}

// ---------------- fp32 -> bf16 hi/lo split (single array) ----------------
__global__ __launch_bounds__(256) void cvt_kernel(const float* __restrict__ s,
                                                  __nv_bfloat16* __restrict__ hi,
                                                  __nv_bfloat16* __restrict__ lo, int n4) {
    int i = blockIdx.x * blockDim.x + threadIdx.x;
    if (i >= n4) return;
    float4 v = *(const float4*)(s + (size_t)i * 4);
    float vv[4] = {v.x, v.y, v.z, v.w};
    #pragma unroll
    for (int j = 0; j < 4; j++) {
        __nv_bfloat16 h = __float2bfloat16(vv[j]);
        hi[(size_t)i * 4 + j] = h;
        lo[(size_t)i * 4 + j] = __float2bfloat16(vv[j] - __bfloat162float(h));
    }
}

// ---------------- cvt for two arrays in one launch ----------------
__global__ __launch_bounds__(256) void cvt2_kernel(
    const float* __restrict__ s0, __nv_bfloat16* __restrict__ hi0, __nv_bfloat16* __restrict__ lo0, int n40,
    const float* __restrict__ s1, __nv_bfloat16* __restrict__ hi1, __nv_bfloat16* __restrict__ lo1, int n41) {
    int i = blockIdx.x * blockDim.x + threadIdx.x;
    const float* s; __nv_bfloat16 *hi, *lo;
    if (i < n40) { s = s0; hi = hi0; lo = lo0; }
    else { i -= n40; if (i >= n41) return; s = s1; hi = hi1; lo = lo1; }
    float4 v = *(const float4*)(s + (size_t)i * 4);
    float vv[4] = {v.x, v.y, v.z, v.w};
    #pragma unroll
    for (int j = 0; j < 4; j++) {
        __nv_bfloat16 h = __float2bfloat16(vv[j]);
        hi[(size_t)i * 4 + j] = h;
        lo[(size_t)i * 4 + j] = __float2bfloat16(vv[j] - __bfloat162float(h));
    }
}

// ---------------- LayerNorm: x (B,C,L) -> xn hi/lo (B*L, C) bf16 ----------------
__global__ __launch_bounds__(256) void ln_kernel(const float* __restrict__ x,
                                                 const float* __restrict__ w,
                                                 const float* __restrict__ bsh,
                                                 __nv_bfloat16* __restrict__ xnh,
                                                 __nv_bfloat16* __restrict__ xnl) {
    int b  = blockIdx.y;
    int l0 = blockIdx.x * 64;
    int tid = threadIdx.x;
    int ll = tid & 63;
    int cg = tid >> 6;

    __shared__ float ssum[4][64];
    __shared__ float ssq[4][64];
    __shared__ float smean[64];
    __shared__ float srstd[64];
    __shared__ float st[16][65];

    const float* xb = x + (size_t)b * DIMC * L_SEQ;

    float s = 0.f, sq = 0.f;
    for (int c = cg; c < DIMC; c += 4) {
        float v = xb[(size_t)c * L_SEQ + l0 + ll];
        s += v; sq += v * v;
    }
    ssum[cg][ll] = s; ssq[cg][ll] = sq;
    __syncthreads();
    if (tid < 64) {
        float S = ssum[0][tid] + ssum[1][tid] + ssum[2][tid] + ssum[3][tid];
        float Q = ssq[0][tid] + ssq[1][tid] + ssq[2][tid] + ssq[3][tid];
        float mu = S * (1.f / DIMC);
        float var = Q * (1.f / DIMC) - mu * mu;
        smean[tid] = mu;
        srstd[tid] = rsqrtf(var + 1e-5f);
    }
    __syncthreads();

    for (int c0 = 0; c0 < DIMC; c0 += 16) {
        #pragma unroll
        for (int r = 0; r < 4; r++) {
            int c = c0 + cg + r * 4;
            float v = xb[(size_t)c * L_SEQ + l0 + ll];
            st[cg + r * 4][ll] = (v - smean[ll]) * srstd[ll] * w[c] + bsh[c];
        }
        __syncthreads();
        int c2 = tid & 15, lr = tid >> 4;
        #pragma unroll
        for (int p = 0; p < 4; p++) {
            int l = lr + p * 16;
            float v = st[c2][l];
            __nv_bfloat16 h = __float2bfloat16(v);
            size_t o = ((size_t)b * L_SEQ + l0 + l) * DIMC + c0 + c2;
            xnh[o] = h;
            xnl[o] = __float2bfloat16(v - __bfloat162float(h));
        }
        __syncthreads();
    }
}

// ---------------- fp32 tiled GEMM (dt only) ----------------
#define BM 128
#define BN 128
#define BKK 16
#define PAD 4

__global__ __launch_bounds__(256, 2) void gemm2_kernel(
    const float* __restrict__ A, int lda, int K,
    const float* __restrict__ W, int ldw, int N,
    float* __restrict__ C, int ldc, int mode,
    const float* __restrict__ bias) {

    __shared__ float As[2][BKK][BM + PAD];
    __shared__ float Bs[2][BKK][BN + PAD];

    int tid = threadIdx.x;
    int m0 = blockIdx.y * BM;
    int n0 = blockIdx.x * BN;
    int tm = tid & 15;
    int tn = tid >> 4;

    int lr = tid >> 2;
    int lk = (tid & 3) * 4;

    float4 pa[2], pb[2];
    int nt = (K + BKK - 1) / BKK;

    {
        int kk = lk;
        #pragma unroll
        for (int r = 0; r < 2; r++) {
            int m = lr + r * 64;
            float4 v = make_float4(0.f, 0.f, 0.f, 0.f);
            if (kk < K) v = *(const float4*)&A[(size_t)(m0 + m) * lda + kk];
            pa[r] = v;
            float4 u = make_float4(0.f, 0.f, 0.f, 0.f);
            if (kk < K && (n0 + m) < N) u = *(const float4*)&W[(size_t)(n0 + m) * ldw + kk];
            pb[r] = u;
        }
    }

    float acc[8][8];
    #pragma unroll
    for (int i = 0; i < 8; i++)
        #pragma unroll
        for (int j = 0; j < 8; j++) acc[i][j] = 0.f;

    for (int t = 0; t < nt; t++) {
        int buf = t & 1;
        #pragma unroll
        for (int r = 0; r < 2; r++) {
            int m = lr + r * 64;
            As[buf][lk + 0][m] = pa[r].x;
            As[buf][lk + 1][m] = pa[r].y;
            As[buf][lk + 2][m] = pa[r].z;
            As[buf][lk + 3][m] = pa[r].w;
            Bs[buf][lk + 0][m] = pb[r].x;
            Bs[buf][lk + 1][m] = pb[r].y;
            Bs[buf][lk + 2][m] = pb[r].z;
            Bs[buf][lk + 3][m] = pb[r].w;
        }
        __syncthreads();

        if (t + 1 < nt) {
            int kk = (t + 1) * BKK + lk;
            #pragma unroll
            for (int r = 0; r < 2; r++) {
                int m = lr + r * 64;
                float4 v = make_float4(0.f, 0.f, 0.f, 0.f);
                if (kk < K) v = *(const float4*)&A[(size_t)(m0 + m) * lda + kk];
                pa[r] = v;
                float4 u = make_float4(0.f, 0.f, 0.f, 0.f);
                if (kk < K && (n0 + m) < N) u = *(const float4*)&W[(size_t)(n0 + m) * ldw + kk];
                pb[r] = u;
            }
        }

        const float (*Ab)[BM + PAD] = As[buf];
        const float (*Bb)[BN + PAD] = Bs[buf];
        #pragma unroll
        for (int k = 0; k < BKK; k++) {
            float a[8], b[8];
            *(float4*)&a[0] = *(const float4*)&Ab[k][tm * 4];
            *(float4*)&a[4] = *(const float4*)&Ab[k][64 + tm * 4];
            *(float4*)&b[0] = *(const float4*)&Bb[k][tn * 4];
            *(float4*)&b[4] = *(const float4*)&Bb[k][64 + tn * 4];
            #pragma unroll
            for (int i = 0; i < 8; i++)
                #pragma unroll
                for (int j = 0; j < 8; j++)
                    acc[i][j] = fmaf(a[i], b[j], acc[i][j]);
        }
        __syncthreads();
    }

    #pragma unroll
    for (int ih = 0; ih < 2; ih++) {
        #pragma unroll
        for (int i4 = 0; i4 < 4; i4++) {
            int i = ih * 4 + i4;
            int m = m0 + ih * 64 + tm * 4 + i4;
            #pragma unroll
            for (int jh = 0; jh < 2; jh++) {
                int n = n0 + jh * 64 + tn * 4;
                if (n < N) {
                    float4 v = make_float4(acc[i][jh * 4 + 0], acc[i][jh * 4 + 1],
                                           acc[i][jh * 4 + 2], acc[i][jh * 4 + 3]);
                    if (mode == 1) {
                        float* vv = (float*)&v;
                        #pragma unroll
                        for (int j = 0; j < 4; j++) {
                            float z = vv[j] + bias[n + j];
                            vv[j] = fmaxf(z, 0.f) + log1pf(__expf(-fabsf(z)));
                        }
                    }
                    if (n + 3 < N) {
                        *(float4*)&C[(size_t)m * ldc + n] = v;
                    } else {
                        float* vv = (float*)&v;
                        #pragma unroll
                        for (int j = 0; j < 4; j++)
                            if (n + j < N) C[(size_t)m * ldc + n + j] = vv[j];
                    }
                }
            }
        }
    }
}

// ---------------- depthwise causal conv1d (k=4) + SiLU, smem-tiled ----------------
// block: 64 d x 64 l tile; each xz element read once.
__global__ __launch_bounds__(256) void conv_silu2_kernel(const float* __restrict__ cw,
                                                         const float* __restrict__ cb,
                                                         const float* __restrict__ xz,
                                                         float* __restrict__ xc,
                                                         __nv_bfloat16* __restrict__ xch,
                                                         __nv_bfloat16* __restrict__ xcl) {
    __shared__ float sx[67][64];
    int d0 = blockIdx.x * 64;
    int mchunk = blockIdx.y;           // 0..255
    int l0 = (mchunk & 63) * 64;       // within batch
    int b = mchunk >> 6;
    int tid = threadIdx.x;
    int tx = tid & 63, ty = tid >> 6;
    size_t rowbase = (size_t)b * L_SEQ;

    for (int r = ty; r < 67; r += 4) {
        int l = l0 - 3 + r;
        float v = 0.f;
        if (l >= 0) v = xz[(rowbase + l) * (2 * D_INNER) + d0 + tx];
        sx[r][tx] = v;
    }
    __syncthreads();

    int d = d0 + tx;
    float w0 = cw[d * 4 + 0], w1 = cw[d * 4 + 1];
    float w2 = cw[d * 4 + 2], w3 = cw[d * 4 + 3];
    float bias = cb[d];

    #pragma unroll 4
    for (int i = 0; i < 16; i++) {
        int ll = ty + i * 4;
        int r = ll + 3;
        float acc = bias;
        acc = fmaf(w3, sx[r][tx], acc);
        acc = fmaf(w2, sx[r - 1][tx], acc);
        acc = fmaf(w1, sx[r - 2][tx], acc);
        acc = fmaf(w0, sx[r - 3][tx], acc);
        float sg = 1.f / (1.f + __expf(-acc));
        float v = acc * sg;
        size_t o = (rowbase + l0 + ll) * D_INNER + d;
        xc[o] = v;
        __nv_bfloat16 h = __float2bfloat16(v);
        xch[o] = h;
        xcl[o] = __float2bfloat16(v - __bfloat162float(h));
    }
}

// ---------------- selective scan v4: phase-split (no shfl), cp.async 3-stage ----------------
#define SCH4 16
#define CH4 24
#define NST4 3
#define NCH4 (L_SEQ / SCH4)     // 256
#define S4_BC 0
#define S4_D  1536
#define S4_X  2688
#define S4_Z  3840
#define S4_P  4992
#define S4_TOTAL (4992 + 16 * 24 * 20)   // 12672 floats = 50688 B

__global__ __launch_bounds__(384) void scan4_kernel(const float* __restrict__ A_log,
                                                    const float* __restrict__ Dp,
                                                    const float* __restrict__ dtv,
                                                    const float* __restrict__ xc,
                                                    const float* __restrict__ xdbl,
                                                    const float* __restrict__ xz,
                                                    __nv_bfloat16* __restrict__ yh,
                                                    __nv_bfloat16* __restrict__ yl) {
    extern __shared__ float sm4[];
    float* sBC = sm4 + S4_BC;
    float* sD  = sm4 + S4_D;
    float* sX  = sm4 + S4_X;
    float* sZ  = sm4 + S4_Z;
    float* sP  = sm4 + S4_P;

    int b = blockIdx.y;
    int g = blockIdx.x;
    int d0 = g * CH4;
    int tid = threadIdx.x;
    size_t bL = (size_t)b * L_SEQ;

    int lane = tid & 31;
    int w = tid >> 5;
    int half = lane >> 4;
    int n = lane & 15;
    int dl = 2 * w + half;

    float An = -__expf(A_log[(d0 + dl) * D_STATE + n]);
    float h = 0.f;

    int rl = tid / CH4;
    int rc = tid % CH4;
    float Dd = Dp[d0 + rc];

    auto issue = [&](int c) {
        int l0 = c * SCH4;
        int buf = c % NST4;
        uint32_t bcs = smem_u32(sBC + buf * 512);
        uint32_t ds  = smem_u32(sD  + buf * 384);
        uint32_t xs  = smem_u32(sX  + buf * 384);
        uint32_t zs  = smem_u32(sZ  + buf * 384);
        for (int u = tid; u < 416; u += 384) {
            if (u < 128) {
                int l = u >> 3, c4 = u & 7;
                cpasync16(bcs + (uint32_t)(l * 32 + c4 * 4) * 4,
                          xdbl + (bL + l0 + l) * XPN + DT_RANK + c4 * 4, 16);
            } else if (u < 224) {
                int v = u - 128; int l = v / 6, c4 = v % 6;
                cpasync16(ds + (uint32_t)(l * 24 + c4 * 4) * 4,
                          dtv + (bL + l0 + l) * D_INNER + d0 + c4 * 4, 16);
            } else if (u < 320) {
                int v = u - 224; int l = v / 6, c4 = v % 6;
                cpasync16(xs + (uint32_t)(l * 24 + c4 * 4) * 4,
                          xc + (bL + l0 + l) * D_INNER + d0 + c4 * 4, 16);
            } else {
                int v = u - 320; int l = v / 6, c4 = v % 6;
                cpasync16(zs + (uint32_t)(l * 24 + c4 * 4) * 4,
                          xz + (bL + l0 + l) * 2 * D_INNER + D_INNER + d0 + c4 * 4, 16);
            }
        }
        cp_commit();
    };

    issue(0);
    issue(1);

    for (int c = 0; c < NCH4; c++) {
        if (c + 2 < NCH4) { issue(c + 2); cp_wait<2>(); }
        else if (c + 1 < NCH4) { cp_wait<1>(); }
        else { cp_wait<0>(); }
        __syncthreads();

        int buf = c % NST4;
        const float* bD  = sD  + buf * 384;
        const float* bX  = sX  + buf * 384;
        const float* bBC = sBC + buf * 512;

        #pragma unroll
        for (int l = 0; l < SCH4; l++) {
            float dt = bD[l * 24 + dl];
            float xv = bX[l * 24 + dl];
            float Bn = bBC[l * 32 + n];
            float Cn = bBC[l * 32 + 16 + n];
            float e = __expf(dt * An);
            h = fmaf(e, h, dt * xv * Bn);
            sP[(l * 24 + dl) * 20 + n] = h * Cn;
        }
        __syncthreads();

        {
            const float* p = sP + (rl * 24 + rc) * 20;
            float4 a  = *(const float4*)p;
            float4 bq = *(const float4*)(p + 4);
            float4 cq = *(const float4*)(p + 8);
            float4 dq = *(const float4*)(p + 12);
            float s = ((a.x + a.y) + (a.z + a.w)) + ((bq.x + bq.y) + (bq.z + bq.w))
                    + ((cq.x + cq.y) + (cq.z + cq.w)) + ((dq.x + dq.y) + (dq.z + dq.w));
            float xv = bX[rl * 24 + rc];
            float zv = sZ[buf * 384 + rl * 24 + rc];
            float yv = fmaf(xv, Dd, s);
            yv *= zv / (1.f + __expf(-zv));
            size_t o = (bL + (size_t)c * SCH4 + rl) * D_INNER + d0 + rc;
            __nv_bfloat16 hh = __float2bfloat16(yv);
            yh[o] = hh;
            yl[o] = __float2bfloat16(yv - __bfloat162float(hh));
        }
    }
}

// ---------------- launch ----------------
extern "C" void kernel_launch(void* const* d_in, const int* in_sizes, int n_in,
                              void* d_out, int out_size) {
    const float* x          = (const float*)d_in[0];
    const float* ln_w       = (const float*)d_in[1];
    const float* ln_b       = (const float*)d_in[2];
    const float* in_proj_w  = (const float*)d_in[3];
    const float* conv_w     = (const float*)d_in[4];
    const float* conv_b     = (const float*)d_in[5];
    const float* x_proj_w   = (const float*)d_in[6];
    const float* dt_w       = (const float*)d_in[7];
    const float* dt_b       = (const float*)d_in[8];
    const float* A_log      = (const float*)d_in[9];
    const float* Dp         = (const float*)d_in[10];
    const float* out_proj_w = (const float*)d_in[11];
    float* out = (float*)d_out;

    float *p_xz, *p_xc, *p_xdbl, *p_dtv;
    __nv_bfloat16 *p_xnh, *p_xnl, *p_xch, *p_xcl, *p_yh, *p_yl;
    __nv_bfloat16 *p_wih, *p_wil, *p_woh, *p_wol, *p_wxh, *p_wxl;
    cudaGetSymbolAddress((void**)&p_xz,   g_xz);
    cudaGetSymbolAddress((void**)&p_xc,   g_xc);
    cudaGetSymbolAddress((void**)&p_xdbl, g_xdbl);
    cudaGetSymbolAddress((void**)&p_dtv,  g_dtv);
    cudaGetSymbolAddress((void**)&p_xnh,  g_xn_hi);
    cudaGetSymbolAddress((void**)&p_xnl,  g_xn_lo);
    cudaGetSymbolAddress((void**)&p_xch,  g_xc_hi);
    cudaGetSymbolAddress((void**)&p_xcl,  g_xc_lo);
    cudaGetSymbolAddress((void**)&p_yh,   g_y_hi);
    cudaGetSymbolAddress((void**)&p_yl,   g_y_lo);
    cudaGetSymbolAddress((void**)&p_wih,  g_wi_hi);
    cudaGetSymbolAddress((void**)&p_wil,  g_wi_lo);
    cudaGetSymbolAddress((void**)&p_woh,  g_wo_hi);
    cudaGetSymbolAddress((void**)&p_wol,  g_wo_lo);
    cudaGetSymbolAddress((void**)&p_wxh,  g_wx_hi);
    cudaGetSymbolAddress((void**)&p_wxl,  g_wx_lo);

    const int MM_SMEM = NSTAGE * BUF_B;        // 204800 B
    const int SC_SMEM = S4_TOTAL * 4;          // 50688 B
    cudaFuncSetAttribute(mmagemm_kernel, cudaFuncAttributeMaxDynamicSharedMemorySize, MM_SMEM);
    cudaFuncSetAttribute(scan4_kernel, cudaFuncAttributeMaxDynamicSharedMemorySize, SC_SMEM);

    // 0) weight hi/lo conversion (2 launches so in_proj mma lands in the profiled slot)
    int n4i = (2 * D_INNER * DIMC) / 4;
    cvt_kernel<<<(n4i + 255) / 256, 256>>>(in_proj_w, p_wih, p_wil, n4i);
    int n4o = (DIMC * D_INNER) / 4;
    int n4x = (XPN * D_INNER) / 4;
    cvt2_kernel<<<(n4o + n4x + 255) / 256, 256>>>(out_proj_w, p_woh, p_wol, n4o,
                                                  x_proj_w, p_wxh, p_wxl, n4x);

    // 1) LayerNorm -> xn hi/lo
    ln_kernel<<<dim3(L_SEQ / 64, B_SZ), 256>>>(x, ln_w, ln_b, p_xnh, p_xnl);

    // 2) in_proj (tensor) — profiled slot
    mmagemm_kernel<<<dim3(2 * D_INNER / 128, M_TOTAL / 128), 512, MM_SMEM>>>(
        p_xnh, p_xnl, p_wih, p_wil, DIMC, 2 * D_INNER, p_xz, 2 * D_INNER, 0);

    // 3) depthwise conv + silu -> xc fp32 + hi/lo (smem tiled)
    conv_silu2_kernel<<<dim3(D_INNER / 64, M_TOTAL / 64), 256>>>(
        conv_w, conv_b, p_xz, p_xc, p_xch, p_xcl);

    // 4) x_proj (tensor, N=56 masked)
    mmagemm_kernel<<<dim3(1, M_TOTAL / 128), 512, MM_SMEM>>>(
        p_xch, p_xcl, p_wxh, p_wxl, D_INNER, XPN, p_xdbl, XPN, 0);

    // 5) dt + softplus (fp32 SIMT, K=24)
    gemm2_kernel<<<dim3(D_INNER / BN, M_TOTAL / BM), 256>>>(
        p_xdbl, XPN, DT_RANK, dt_w, DT_RANK, D_INNER, p_dtv, D_INNER, 1, dt_b);

    // 6) selective scan v4 -> y hi/lo
    scan4_kernel<<<dim3(D_INNER / CH4, B_SZ), 384, SC_SMEM>>>(
        A_log, Dp, p_dtv, p_xc, p_xdbl, p_xz, p_yh, p_yl);

    // 7) out_proj (tensor, transposed store)
    mmagemm_kernel<<<dim3(DIMC / 128, M_TOTAL / 128), 512, MM_SMEM>>>(
        p_yh, p_yl, p_woh, p_wol, D_INNER, DIMC, out, 0, 2);
}

// round 10
// speedup vs baseline: 8.0922x; 1.1563x over previous
#include <cuda_runtime.h>
#include <cuda_fp16.h>
#include <cstdint>

#define B_SZ 4
#define DIMC 384
#define L_SEQ 4096
#define D_INNER 768
#define D_STATE 16
#define DT_RANK 24
#define XPN 56
#define M_TOTAL (B_SZ * L_SEQ)      // 16384

// ---------------- scratch (no allocations allowed) ----------------
__device__ float g_xz[(size_t)M_TOTAL * 2 * D_INNER];
__device__ float g_xc[(size_t)M_TOTAL * D_INNER];
__device__ float g_xdbl[(size_t)M_TOTAL * XPN];
__device__ float g_dtv[(size_t)M_TOTAL * D_INNER];

__device__ __half g_xn_h[(size_t)M_TOTAL * DIMC];
__device__ __half g_xc_h[(size_t)M_TOTAL * D_INNER];
__device__ __half g_y_hi[(size_t)M_TOTAL * D_INNER];
__device__ __half g_y_lo[(size_t)M_TOTAL * D_INNER];
__device__ __half g_wi_hi[(size_t)2 * D_INNER * DIMC];
__device__ __half g_wi_lo[(size_t)2 * D_INNER * DIMC];
__device__ __half g_wo_hi[(size_t)DIMC * D_INNER];
__device__ __half g_wo_lo[(size_t)DIMC * D_INNER];
__device__ __half g_wx_hi[(size_t)XPN * D_INNER];
__device__ __half g_wx_lo[(size_t)XPN * D_INNER];

// ---------------- small PTX helpers (all base-target, sm_80+) ----------------
__device__ __forceinline__ uint32_t smem_u32(const void* p) {
    uint32_t a;
    asm("{ .reg .u64 t; cvta.to.shared.u64 t, %1; cvt.u32.u64 %0, t; }" : "=r"(a) : "l"(p));
    return a;
}
__device__ __forceinline__ void cpasync16(uint32_t sa, const void* g, int sz) {
    asm volatile("cp.async.cg.shared.global [%0], [%1], 16, %2;" :: "r"(sa), "l"(g), "r"(sz) : "memory");
}
__device__ __forceinline__ void cp_commit() {
    asm volatile("cp.async.commit_group;" ::: "memory");
}
template <int N> __device__ __forceinline__ void cp_wait() {
    asm volatile("cp.async.wait_group %0;" :: "n"(N) : "memory");
}
__device__ __forceinline__ void ldsm4(uint32_t* r, uint32_t addr) {
    asm volatile("ldmatrix.sync.aligned.m8n8.x4.shared.b16 {%0,%1,%2,%3}, [%4];"
                 : "=r"(r[0]), "=r"(r[1]), "=r"(r[2]), "=r"(r[3]) : "r"(addr));
}
__device__ __forceinline__ void mma16816h(float* d, const uint32_t* a, const uint32_t* b) {
    asm volatile(
        "mma.sync.aligned.m16n8k16.row.col.f32.f16.f16.f32 "
        "{%0,%1,%2,%3}, {%4,%5,%6,%7}, {%8,%9}, {%0,%1,%2,%3};"
        : "+f"(d[0]), "+f"(d[1]), "+f"(d[2]), "+f"(d[3])
        : "r"(a[0]), "r"(a[1]), "r"(a[2]), "r"(a[3]), "r"(b[0]), "r"(b[1]));
}

// ---------------- fp16-split mma.sync GEMM (512 thr, 5-stage, 1 barrier/chunk) ----------------
// TERMS=2: C = (Ah) * (Bh+Bl)^T    — error = Al*B ~ 2^-12.8 rel (A truncated to fp16)
// TERMS=3: C = (Ah+Al) * (Bh+Bl)^T minus AlBl — error ~2^-24
// Single-barrier hazard proof: iter c issues cp.async to stage (c+3)%5, last read in
// compute(c-2); every thread's compute(c-2) precedes its BAR(c-1) arrival, and any
// thread reaches issue(c+3) only after passing BAR(c-1). Requires NSTAGE >= depth+2.
#define LDSROW 40
#define TILE_H (128 * LDSROW)
#define NSTAGE 5

template <int TERMS>
__global__ __launch_bounds__(512, 1) void mmagemm_kernel(
    const __half* __restrict__ Ah, const __half* __restrict__ Al,
    const __half* __restrict__ Bh, const __half* __restrict__ Bl,
    int K, int Nn, float* __restrict__ C, int ldc, int mode) {

    constexpr int NT = TERMS + 1;              // tiles per stage
    constexpr int BUFB = NT * TILE_H * 2;      // bytes per stage

    extern __shared__ __align__(16) uint8_t dsm[];
    uint32_t dsm_u = smem_u32(dsm);

    int tid = threadIdx.x;
    int wid = tid >> 5;
    int lane = tid & 31;
    int warp_m = wid & 3;
    int warp_n = wid >> 2;
    int m0 = blockIdx.y * 128;
    int n0 = blockIdx.x * 128;

    float acc[2][4][4];
    #pragma unroll
    for (int mt = 0; mt < 2; mt++)
        #pragma unroll
        for (int nt = 0; nt < 4; nt++)
            #pragma unroll
            for (int q = 0; q < 4; q++) acc[mt][nt][q] = 0.f;

    int nchunks = K >> 5;

    auto load_chunk = [&](int c) {
        int kc = c << 5;
        uint32_t sbase = dsm_u + (c % NSTAGE) * BUFB;
        #pragma unroll
        for (int i = 0; i < NT; i++) {
            int u = tid + i * 512;
            int tile = u >> 9;
            int v = u & 511;
            int row = v >> 2;
            int seg = v & 3;
            uint32_t sa = sbase + (tile * TILE_H + row * LDSROW + seg * 8) * 2;
            const __half* g;
            int sz = 16;
            if (tile < TERMS - 1) {
                g = ((TERMS == 3 && tile == 1) ? Al : Ah) + (size_t)(m0 + row) * K + kc + seg * 8;
            } else {
                int r = n0 + row;
                if (r >= Nn) { r = Nn - 1; sz = 0; }
                g = ((tile == TERMS - 1) ? Bh : Bl) + (size_t)r * K + kc + seg * 8;
            }
            cpasync16(sa, g, sz);
        }
        cp_commit();
    };

    load_chunk(0);
    load_chunk(1);
    load_chunk(2);

    for (int c = 0; c < nchunks; c++) {
        if (c + 3 < nchunks) { load_chunk(c + 3); cp_wait<3>(); }
        else if (c + 2 < nchunks) { cp_wait<2>(); }
        else if (c + 1 < nchunks) { cp_wait<1>(); }
        else { cp_wait<0>(); }
        __syncthreads();   // single barrier per chunk (see proof above)

        uint32_t base = dsm_u + (c % NSTAGE) * BUFB;
        #pragma unroll
        for (int kk = 0; kk < 32; kk += 16) {
            uint32_t aF[TERMS - 1][2][4];
            uint32_t bF[2][4][2];
            {
                int arow = warp_m * 32 + (lane & 15);
                int ak = kk + (lane >> 4) * 8;
                #pragma unroll
                for (int t = 0; t < TERMS - 1; t++)
                    #pragma unroll
                    for (int mt = 0; mt < 2; mt++)
                        ldsm4(aF[t][mt], base + (t * TILE_H + (arow + mt * 16) * LDSROW + ak) * 2);
            }
            {
                int brow = warp_n * 32 + (lane & 7) + (lane >> 4) * 8;
                int bk = kk + ((lane >> 3) & 1) * 8;
                #pragma unroll
                for (int hb = 0; hb < 2; hb++) {
                    uint32_t btile = (uint32_t)(TERMS - 1 + hb) * TILE_H * 2;
                    #pragma unroll
                    for (int g2 = 0; g2 < 2; g2++) {
                        uint32_t r[4];
                        ldsm4(r, base + btile + ((brow + g2 * 16) * LDSROW + bk) * 2);
                        bF[hb][g2 * 2][0] = r[0]; bF[hb][g2 * 2][1] = r[1];
                        bF[hb][g2 * 2 + 1][0] = r[2]; bF[hb][g2 * 2 + 1][1] = r[3];
                    }
                }
            }
            #pragma unroll
            for (int mt = 0; mt < 2; mt++)
                #pragma unroll
                for (int nt = 0; nt < 4; nt++) {
                    mma16816h(acc[mt][nt], aF[0][mt], bF[0][nt]);
                    mma16816h(acc[mt][nt], aF[0][mt], bF[1][nt]);
                    if (TERMS == 3)
                        mma16816h(acc[mt][nt], aF[1][mt], bF[0][nt]);
                }
        }
    }
    __syncthreads();   // compute done before epilogue reuses dsm

    if (mode == 0) {
        #pragma unroll
        for (int mt = 0; mt < 2; mt++) {
            int m = m0 + warp_m * 32 + mt * 16 + (lane >> 2);
            #pragma unroll
            for (int nt = 0; nt < 4; nt++) {
                int n = n0 + warp_n * 32 + nt * 8 + (lane & 3) * 2;
                if (n < Nn) {
                    float2 v0 = make_float2(acc[mt][nt][0], acc[mt][nt][1]);
                    float2 v1 = make_float2(acc[mt][nt][2], acc[mt][nt][3]);
                    *(float2*)&C[(size_t)m * ldc + n] = v0;
                    *(float2*)&C[(size_t)(m + 8) * ldc + n] = v1;
                }
            }
        }
    } else {
        float* sT = (float*)dsm;   // [128 n][132 m]
        #pragma unroll
        for (int mt = 0; mt < 2; mt++) {
            int ml = warp_m * 32 + mt * 16 + (lane >> 2);
            #pragma unroll
            for (int nt = 0; nt < 4; nt++) {
                int nl = warp_n * 32 + nt * 8 + (lane & 3) * 2;
                sT[nl * 132 + ml]           = acc[mt][nt][0];
                sT[(nl + 1) * 132 + ml]     = acc[mt][nt][1];
                sT[nl * 132 + ml + 8]       = acc[mt][nt][2];
                sT[(nl + 1) * 132 + ml + 8] = acc[mt][nt][3];
            }
        }
        __syncthreads();
        int b = m0 >> 12;
        int l0 = m0 & (L_SEQ - 1);
        int n = tid >> 2;
        int part = (tid & 3) * 32;
        float* dst = C + ((size_t)b * DIMC + n0 + n) * L_SEQ + l0 + part;
        const float* src = sT + n * 132 + part;
        #pragma unroll
        for (int q = 0; q < 8; q++)
            *(float4*)(dst + q * 4) = *(const float4*)(src + q * 4);
    }
}

// ---------------- fp32 -> fp16 hi/lo split ----------------
__global__ __launch_bounds__(256) void cvt_kernel(const float* __restrict__ s,
                                                  __half* __restrict__ hi,
                                                  __half* __restrict__ lo, int n4) {
    int i = blockIdx.x * blockDim.x + threadIdx.x;
    if (i >= n4) return;
    float4 v = *(const float4*)(s + (size_t)i * 4);
    float vv[4] = {v.x, v.y, v.z, v.w};
    #pragma unroll
    for (int j = 0; j < 4; j++) {
        __half h = __float2half_rn(vv[j]);
        hi[(size_t)i * 4 + j] = h;
        lo[(size_t)i * 4 + j] = __float2half_rn(vv[j] - __half2float(h));
    }
}

__global__ __launch_bounds__(256) void cvt2_kernel(
    const float* __restrict__ s0, __half* __restrict__ hi0, __half* __restrict__ lo0, int n40,
    const float* __restrict__ s1, __half* __restrict__ hi1, __half* __restrict__ lo1, int n41) {
    int i = blockIdx.x * blockDim.x + threadIdx.x;
    const float* s; __half *hi, *lo;
    if (i < n40) { s = s0; hi = hi0; lo = lo0; }
    else { i -= n40; if (i >= n41) return; s = s1; hi = hi1; lo = lo1; }
    float4 v = *(const float4*)(s + (size_t)i * 4);
    float vv[4] = {v.x, v.y, v.z, v.w};
    #pragma unroll
    for (int j = 0; j < 4; j++) {
        __half h = __float2half_rn(vv[j]);
        hi[(size_t)i * 4 + j] = h;
        lo[(size_t)i * 4 + j] = __float2half_rn(vv[j] - __half2float(h));
    }
}

// ---------------- LayerNorm: x (B,C,L) -> xn (B*L, C) fp16 ----------------
__global__ __launch_bounds__(256) void ln_kernel(const float* __restrict__ x,
                                                 const float* __restrict__ w,
                                                 const float* __restrict__ bsh,
                                                 __half* __restrict__ xnh) {
    int b  = blockIdx.y;
    int l0 = blockIdx.x * 64;
    int tid = threadIdx.x;
    int ll = tid & 63;
    int cg = tid >> 6;

    __shared__ float ssum[4][64];
    __shared__ float ssq[4][64];
    __shared__ float smean[64];
    __shared__ float srstd[64];
    __shared__ float st[16][65];

    const float* xb = x + (size_t)b * DIMC * L_SEQ;

    float s = 0.f, sq = 0.f;
    for (int c = cg; c < DIMC; c += 4) {
        float v = xb[(size_t)c * L_SEQ + l0 + ll];
        s += v; sq += v * v;
    }
    ssum[cg][ll] = s; ssq[cg][ll] = sq;
    __syncthreads();
    if (tid < 64) {
        float S = ssum[0][tid] + ssum[1][tid] + ssum[2][tid] + ssum[3][tid];
        float Q = ssq[0][tid] + ssq[1][tid] + ssq[2][tid] + ssq[3][tid];
        float mu = S * (1.f / DIMC);
        float var = Q * (1.f / DIMC) - mu * mu;
        smean[tid] = mu;
        srstd[tid] = rsqrtf(var + 1e-5f);
    }
    __syncthreads();

    for (int c0 = 0; c0 < DIMC; c0 += 16) {
        #pragma unroll
        for (int r = 0; r < 4; r++) {
            int c = c0 + cg + r * 4;
            float v = xb[(size_t)c * L_SEQ + l0 + ll];
            st[cg + r * 4][ll] = (v - smean[ll]) * srstd[ll] * w[c] + bsh[c];
        }
        __syncthreads();
        int c2 = tid & 15, lr = tid >> 4;
        #pragma unroll
        for (int p = 0; p < 4; p++) {
            int l = lr + p * 16;
            xnh[((size_t)b * L_SEQ + l0 + l) * DIMC + c0 + c2] = __float2half_rn(st[c2][l]);
        }
        __syncthreads();
    }
}

// ---------------- fp32 tiled GEMM (dt only) ----------------
#define BM 128
#define BN 128
#define BKK 16
#define PAD 4

__global__ __launch_bounds__(256, 2) void gemm2_kernel(
    const float* __restrict__ A, int lda, int K,
    const float* __restrict__ W, int ldw, int N,
    float* __restrict__ C, int ldc, int mode,
    const float* __restrict__ bias) {

    __shared__ float As[2][BKK][BM + PAD];
    __shared__ float Bs[2][BKK][BN + PAD];

    int tid = threadIdx.x;
    int m0 = blockIdx.y * BM;
    int n0 = blockIdx.x * BN;
    int tm = tid & 15;
    int tn = tid >> 4;

    int lr = tid >> 2;
    int lk = (tid & 3) * 4;

    float4 pa[2], pb[2];
    int nt = (K + BKK - 1) / BKK;

    {
        int kk = lk;
        #pragma unroll
        for (int r = 0; r < 2; r++) {
            int m = lr + r * 64;
            float4 v = make_float4(0.f, 0.f, 0.f, 0.f);
            if (kk < K) v = *(const float4*)&A[(size_t)(m0 + m) * lda + kk];
            pa[r] = v;
            float4 u = make_float4(0.f, 0.f, 0.f, 0.f);
            if (kk < K && (n0 + m) < N) u = *(const float4*)&W[(size_t)(n0 + m) * ldw + kk];
            pb[r] = u;
        }
    }

    float acc[8][8];
    #pragma unroll
    for (int i = 0; i < 8; i++)
        #pragma unroll
        for (int j = 0; j < 8; j++) acc[i][j] = 0.f;

    for (int t = 0; t < nt; t++) {
        int buf = t & 1;
        #pragma unroll
        for (int r = 0; r < 2; r++) {
            int m = lr + r * 64;
            As[buf][lk + 0][m] = pa[r].x;
            As[buf][lk + 1][m] = pa[r].y;
            As[buf][lk + 2][m] = pa[r].z;
            As[buf][lk + 3][m] = pa[r].w;
            Bs[buf][lk + 0][m] = pb[r].x;
            Bs[buf][lk + 1][m] = pb[r].y;
            Bs[buf][lk + 2][m] = pb[r].z;
            Bs[buf][lk + 3][m] = pb[r].w;
        }
        __syncthreads();

        if (t + 1 < nt) {
            int kk = (t + 1) * BKK + lk;
            #pragma unroll
            for (int r = 0; r < 2; r++) {
                int m = lr + r * 64;
                float4 v = make_float4(0.f, 0.f, 0.f, 0.f);
                if (kk < K) v = *(const float4*)&A[(size_t)(m0 + m) * lda + kk];
                pa[r] = v;
                float4 u = make_float4(0.f, 0.f, 0.f, 0.f);
                if (kk < K && (n0 + m) < N) u = *(const float4*)&W[(size_t)(n0 + m) * ldw + kk];
                pb[r] = u;
            }
        }

        const float (*Ab)[BM + PAD] = As[buf];
        const float (*Bb)[BN + PAD] = Bs[buf];
        #pragma unroll
        for (int k = 0; k < BKK; k++) {
            float a[8], b[8];
            *(float4*)&a[0] = *(const float4*)&Ab[k][tm * 4];
            *(float4*)&a[4] = *(const float4*)&Ab[k][64 + tm * 4];
            *(float4*)&b[0] = *(const float4*)&Bb[k][tn * 4];
            *(float4*)&b[4] = *(const float4*)&Bb[k][64 + tn * 4];
            #pragma unroll
            for (int i = 0; i < 8; i++)
                #pragma unroll
                for (int j = 0; j < 8; j++)
                    acc[i][j] = fmaf(a[i], b[j], acc[i][j]);
        }
        __syncthreads();
    }

    #pragma unroll
    for (int ih = 0; ih < 2; ih++) {
        #pragma unroll
        for (int i4 = 0; i4 < 4; i4++) {
            int i = ih * 4 + i4;
            int m = m0 + ih * 64 + tm * 4 + i4;
            #pragma unroll
            for (int jh = 0; jh < 2; jh++) {
                int n = n0 + jh * 64 + tn * 4;
                if (n < N) {
                    float4 v = make_float4(acc[i][jh * 4 + 0], acc[i][jh * 4 + 1],
                                           acc[i][jh * 4 + 2], acc[i][jh * 4 + 3]);
                    if (mode == 1) {
                        float* vv = (float*)&v;
                        #pragma unroll
                        for (int j = 0; j < 4; j++) {
                            float z = vv[j] + bias[n + j];
                            vv[j] = fmaxf(z, 0.f) + log1pf(__expf(-fabsf(z)));
                        }
                    }
                    if (n + 3 < N) {
                        *(float4*)&C[(size_t)m * ldc + n] = v;
                    } else {
                        float* vv = (float*)&v;
                        #pragma unroll
                        for (int j = 0; j < 4; j++)
                            if (n + j < N) C[(size_t)m * ldc + n + j] = vv[j];
                    }
                }
            }
        }
    }
}

// ---------------- depthwise causal conv1d (k=4) + SiLU, smem-tiled ----------------
__global__ __launch_bounds__(256) void conv_silu2_kernel(const float* __restrict__ cw,
                                                         const float* __restrict__ cb,
                                                         const float* __restrict__ xz,
                                                         float* __restrict__ xc,
                                                         __half* __restrict__ xch) {
    __shared__ float sx[67][64];
    int d0 = blockIdx.x * 64;
    int mchunk = blockIdx.y;
    int l0 = (mchunk & 63) * 64;
    int b = mchunk >> 6;
    int tid = threadIdx.x;
    int tx = tid & 63, ty = tid >> 6;
    size_t rowbase = (size_t)b * L_SEQ;

    for (int r = ty; r < 67; r += 4) {
        int l = l0 - 3 + r;
        float v = 0.f;
        if (l >= 0) v = xz[(rowbase + l) * (2 * D_INNER) + d0 + tx];
        sx[r][tx] = v;
    }
    __syncthreads();

    int d = d0 + tx;
    float w0 = cw[d * 4 + 0], w1 = cw[d * 4 + 1];
    float w2 = cw[d * 4 + 2], w3 = cw[d * 4 + 3];
    float bias = cb[d];

    #pragma unroll 4
    for (int i = 0; i < 16; i++) {
        int ll = ty + i * 4;
        int r = ll + 3;
        float acc = bias;
        acc = fmaf(w3, sx[r][tx], acc);
        acc = fmaf(w2, sx[r - 1][tx], acc);
        acc = fmaf(w1, sx[r - 2][tx], acc);
        acc = fmaf(w0, sx[r - 3][tx], acc);
        float sg = 1.f / (1.f + __expf(-acc));
        float v = acc * sg;
        size_t o = (rowbase + l0 + ll) * D_INNER + d;
        xc[o] = v;
        xch[o] = __float2half_rn(v);
    }
}

// ---------------- selective scan v5: phase-split, 4-stage cp.async, SCH=32 ----------------
// grid (32, 4), 384 threads. 4-stage ring with depth 2: stage written at issue(c+2)
// (= (c-2)%4) was last read in reduce(c-2), and BAR_a(c-1) orders all of reduce(c-2)
// before any thread reaches issue(c+2) in iter c — race-free by barrier chain.
#define SCH5 32
#define CH5 24
#define NST5 4
#define NCH5 (L_SEQ / SCH5)     // 128
// float offsets: sBC[4][32][32] | sD[4][32][24] | sX | sZ | sP[32][24][20]
#define S5_BC 0
#define S5_D  4096
#define S5_X  7168
#define S5_Z  10240
#define S5_P  13312
#define S5_TOTAL (13312 + 32 * 24 * 20)   // 28672 floats = 114688 B

__global__ __launch_bounds__(384) void scan5_kernel(const float* __restrict__ A_log,
                                                    const float* __restrict__ Dp,
                                                    const float* __restrict__ dtv,
                                                    const float* __restrict__ xc,
                                                    const float* __restrict__ xdbl,
                                                    const float* __restrict__ xz,
                                                    __half* __restrict__ yh,
                                                    __half* __restrict__ yl) {
    extern __shared__ float sm5[];
    float* sBC = sm5 + S5_BC;
    float* sD  = sm5 + S5_D;
    float* sX  = sm5 + S5_X;
    float* sZ  = sm5 + S5_Z;
    float* sP  = sm5 + S5_P;

    int b = blockIdx.y;
    int g = blockIdx.x;
    int d0 = g * CH5;
    int tid = threadIdx.x;
    size_t bL = (size_t)b * L_SEQ;

    int lane = tid & 31;
    int w = tid >> 5;
    int half = lane >> 4;
    int n = lane & 15;
    int dl = 2 * w + half;

    float An = -__expf(A_log[(d0 + dl) * D_STATE + n]);
    float h = 0.f;

    int rl = tid / CH5;     // 0..15
    int rc = tid % CH5;
    float Dd = Dp[d0 + rc];

    auto issue = [&](int c) {
        int l0 = c * SCH5;
        int buf = c % NST5;
        uint32_t bcs = smem_u32(sBC + buf * 1024);
        uint32_t ds  = smem_u32(sD  + buf * 768);
        uint32_t xs  = smem_u32(sX  + buf * 768);
        uint32_t zs  = smem_u32(sZ  + buf * 768);
        for (int u = tid; u < 832; u += 384) {
            if (u < 256) {
                int l = u >> 3, c4 = u & 7;
                cpasync16(bcs + (uint32_t)(l * 32 + c4 * 4) * 4,
                          xdbl + (bL + l0 + l) * XPN + DT_RANK + c4 * 4, 16);
            } else if (u < 448) {
                int v = u - 256; int l = v / 6, c4 = v % 6;
                cpasync16(ds + (uint32_t)(l * 24 + c4 * 4) * 4,
                          dtv + (bL + l0 + l) * D_INNER + d0 + c4 * 4, 16);
            } else if (u < 640) {
                int v = u - 448; int l = v / 6, c4 = v % 6;
                cpasync16(xs + (uint32_t)(l * 24 + c4 * 4) * 4,
                          xc + (bL + l0 + l) * D_INNER + d0 + c4 * 4, 16);
            } else {
                int v = u - 640; int l = v / 6, c4 = v % 6;
                cpasync16(zs + (uint32_t)(l * 24 + c4 * 4) * 4,
                          xz + (bL + l0 + l) * 2 * D_INNER + D_INNER + d0 + c4 * 4, 16);
            }
        }
        cp_commit();
    };

    issue(0);
    issue(1);

    for (int c = 0; c < NCH5; c++) {
        if (c + 2 < NCH5) { issue(c + 2); cp_wait<2>(); }
        else if (c + 1 < NCH5) { cp_wait<1>(); }
        else { cp_wait<0>(); }
        __syncthreads();                 // BAR_a

        int buf = c % NST5;
        const float* bD  = sD  + buf * 768;
        const float* bX  = sX  + buf * 768;
        const float* bBC = sBC + buf * 1024;

        #pragma unroll 8
        for (int l = 0; l < SCH5; l++) {
            float dt = bD[l * 24 + dl];
            float xv = bX[l * 24 + dl];
            float Bn = bBC[l * 32 + n];
            float Cn = bBC[l * 32 + 16 + n];
            float e = __expf(dt * An);
            h = fmaf(e, h, dt * xv * Bn);
            sP[(l * 24 + dl) * 20 + n] = h * Cn;
        }
        __syncthreads();                 // BAR_b

        #pragma unroll
        for (int i = 0; i < 2; i++) {
            int l = rl + i * 16;
            const float* p = sP + (l * 24 + rc) * 20;
            float4 a  = *(const float4*)p;
            float4 bq = *(const float4*)(p + 4);
            float4 cq = *(const float4*)(p + 8);
            float4 dq = *(const float4*)(p + 12);
            float s = ((a.x + a.y) + (a.z + a.w)) + ((bq.x + bq.y) + (bq.z + bq.w))
                    + ((cq.x + cq.y) + (cq.z + cq.w)) + ((dq.x + dq.y) + (dq.z + dq.w));
            float xv = bX[l * 24 + rc];
            float zv = sZ[buf * 768 + l * 24 + rc];
            float yv = fmaf(xv, Dd, s);
            yv *= zv / (1.f + __expf(-zv));
            size_t o = (bL + (size_t)c * SCH5 + l) * D_INNER + d0 + rc;
            __half hh = __float2half_rn(yv);
            yh[o] = hh;
            yl[o] = __float2half_rn(yv - __half2float(hh));
        }
    }
}

// ---------------- launch ----------------
extern "C" void kernel_launch(void* const* d_in, const int* in_sizes, int n_in,
                              void* d_out, int out_size) {
    const float* x          = (const float*)d_in[0];
    const float* ln_w       = (const float*)d_in[1];
    const float* ln_b       = (const float*)d_in[2];
    const float* in_proj_w  = (const float*)d_in[3];
    const float* conv_w     = (const float*)d_in[4];
    const float* conv_b     = (const float*)d_in[5];
    const float* x_proj_w   = (const float*)d_in[6];
    const float* dt_w       = (const float*)d_in[7];
    const float* dt_b       = (const float*)d_in[8];
    const float* A_log      = (const float*)d_in[9];
    const float* Dp         = (const float*)d_in[10];
    const float* out_proj_w = (const float*)d_in[11];
    float* out = (float*)d_out;

    float *p_xz, *p_xc, *p_xdbl, *p_dtv;
    __half *p_xnh, *p_xch, *p_yh, *p_yl;
    __half *p_wih, *p_wil, *p_woh, *p_wol, *p_wxh, *p_wxl;
    cudaGetSymbolAddress((void**)&p_xz,   g_xz);
    cudaGetSymbolAddress((void**)&p_xc,   g_xc);
    cudaGetSymbolAddress((void**)&p_xdbl, g_xdbl);
    cudaGetSymbolAddress((void**)&p_dtv,  g_dtv);
    cudaGetSymbolAddress((void**)&p_xnh,  g_xn_h);
    cudaGetSymbolAddress((void**)&p_xch,  g_xc_h);
    cudaGetSymbolAddress((void**)&p_yh,   g_y_hi);
    cudaGetSymbolAddress((void**)&p_yl,   g_y_lo);
    cudaGetSymbolAddress((void**)&p_wih,  g_wi_hi);
    cudaGetSymbolAddress((void**)&p_wil,  g_wi_lo);
    cudaGetSymbolAddress((void**)&p_woh,  g_wo_hi);
    cudaGetSymbolAddress((void**)&p_wol,  g_wo_lo);
    cudaGetSymbolAddress((void**)&p_wxh,  g_wx_hi);
    cudaGetSymbolAddress((void**)&p_wxl,  g_wx_lo);

    const int MM_SMEM2 = NSTAGE * 3 * TILE_H * 2;   // 153600 B
    const int MM_SMEM3 = NSTAGE * 4 * TILE_H * 2;   // 204800 B
    const int SC_SMEM  = S5_TOTAL * 4;              // 114688 B
    cudaFuncSetAttribute(mmagemm_kernel<2>, cudaFuncAttributeMaxDynamicSharedMemorySize, MM_SMEM2);
    cudaFuncSetAttribute(mmagemm_kernel<3>, cudaFuncAttributeMaxDynamicSharedMemorySize, MM_SMEM3);
    cudaFuncSetAttribute(scan5_kernel, cudaFuncAttributeMaxDynamicSharedMemorySize, SC_SMEM);

    // 0) weight hi/lo conversion
    int n4i = (2 * D_INNER * DIMC) / 4;
    cvt_kernel<<<(n4i + 255) / 256, 256>>>(in_proj_w, p_wih, p_wil, n4i);
    int n4o = (DIMC * D_INNER) / 4;
    int n4x = (XPN * D_INNER) / 4;
    cvt2_kernel<<<(n4o + n4x + 255) / 256, 256>>>(out_proj_w, p_woh, p_wol, n4o,
                                                  x_proj_w, p_wxh, p_wxl, n4x);

    // 1) LayerNorm -> xn fp16
    ln_kernel<<<dim3(L_SEQ / 64, B_SZ), 256>>>(x, ln_w, ln_b, p_xnh);

    // 2) in_proj (fp16 2-term) — profiled slot
    mmagemm_kernel<2><<<dim3(2 * D_INNER / 128, M_TOTAL / 128), 512, MM_SMEM2>>>(
        p_xnh, nullptr, p_wih, p_wil, DIMC, 2 * D_INNER, p_xz, 2 * D_INNER, 0);

    // 3) depthwise conv + silu -> xc fp32 + fp16
    conv_silu2_kernel<<<dim3(D_INNER / 64, M_TOTAL / 64), 256>>>(
        conv_w, conv_b, p_xz, p_xc, p_xch);

    // 4) x_proj (fp16 2-term, N=56 masked)
    mmagemm_kernel<2><<<dim3(1, M_TOTAL / 128), 512, MM_SMEM2>>>(
        p_xch, nullptr, p_wxh, p_wxl, D_INNER, XPN, p_xdbl, XPN, 0);

    // 5) dt + softplus (fp32 SIMT, K=24)
    gemm2_kernel<<<dim3(D_INNER / BN, M_TOTAL / BM), 256>>>(
        p_xdbl, XPN, DT_RANK, dt_w, DT_RANK, D_INNER, p_dtv, D_INNER, 1, dt_b);

    // 6) selective scan v5 -> y fp16 hi/lo
    scan5_kernel<<<dim3(D_INNER / CH5, B_SZ), 384, SC_SMEM>>>(
        A_log, Dp, p_dtv, p_xc, p_xdbl, p_xz, p_yh, p_yl);

    // 7) out_proj (fp16 3-term, transposed store)
    mmagemm_kernel<3><<<dim3(DIMC / 128, M_TOTAL / 128), 512, MM_SMEM3>>>(
        p_yh, p_yl, p_woh, p_wol, D_INNER, DIMC, out, 0, 2);
}

// round 11
// speedup vs baseline: 9.1452x; 1.1301x over previous
#include <cuda_runtime.h>
#include <cuda_fp16.h>
#include <cstdint>

#define B_SZ 4
#define DIMC 384
#define L_SEQ 4096
#define D_INNER 768
#define D_STATE 16
#define DT_RANK 24
#define XPN 56
#define M_TOTAL (B_SZ * L_SEQ)      // 16384

// ---------------- scratch (no allocations allowed) ----------------
__device__ float g_xz[(size_t)M_TOTAL * 2 * D_INNER];
__device__ float g_xc[(size_t)M_TOTAL * D_INNER];
__device__ float g_xdbl[(size_t)M_TOTAL * XPN];
__device__ float g_dtv[(size_t)M_TOTAL * D_INNER];

__device__ __half g_xn_h[(size_t)M_TOTAL * DIMC];
__device__ __half g_xc_h[(size_t)M_TOTAL * D_INNER];
__device__ __half g_y_h[(size_t)M_TOTAL * D_INNER];
__device__ __half g_wi_hi[(size_t)2 * D_INNER * DIMC];
__device__ __half g_wi_lo[(size_t)2 * D_INNER * DIMC];
__device__ __half g_wo_hi[(size_t)DIMC * D_INNER];
__device__ __half g_wo_lo[(size_t)DIMC * D_INNER];
__device__ __half g_wx_hi[(size_t)XPN * D_INNER];
__device__ __half g_wx_lo[(size_t)XPN * D_INNER];

// ---------------- small PTX helpers (all base-target, sm_80+) ----------------
__device__ __forceinline__ uint32_t smem_u32(const void* p) {
    uint32_t a;
    asm("{ .reg .u64 t; cvta.to.shared.u64 t, %1; cvt.u32.u64 %0, t; }" : "=r"(a) : "l"(p));
    return a;
}
__device__ __forceinline__ void cpasync16(uint32_t sa, const void* g, int sz) {
    asm volatile("cp.async.cg.shared.global [%0], [%1], 16, %2;" :: "r"(sa), "l"(g), "r"(sz) : "memory");
}
__device__ __forceinline__ void cp_commit() {
    asm volatile("cp.async.commit_group;" ::: "memory");
}
template <int N> __device__ __forceinline__ void cp_wait() {
    asm volatile("cp.async.wait_group %0;" :: "n"(N) : "memory");
}
__device__ __forceinline__ void ldsm4(uint32_t* r, uint32_t addr) {
    asm volatile("ldmatrix.sync.aligned.m8n8.x4.shared.b16 {%0,%1,%2,%3}, [%4];"
                 : "=r"(r[0]), "=r"(r[1]), "=r"(r[2]), "=r"(r[3]) : "r"(addr));
}
__device__ __forceinline__ void mma16816h(float* d, const uint32_t* a, const uint32_t* b) {
    asm volatile(
        "mma.sync.aligned.m16n8k16.row.col.f32.f16.f16.f32 "
        "{%0,%1,%2,%3}, {%4,%5,%6,%7}, {%8,%9}, {%0,%1,%2,%3};"
        : "+f"(d[0]), "+f"(d[1]), "+f"(d[2]), "+f"(d[3])
        : "r"(a[0]), "r"(a[1]), "r"(a[2]), "r"(a[3]), "r"(b[0]), "r"(b[1]));
}

// ---------------- fp16 2-term mma.sync GEMM (256 thr, 2 CTA/SM, 3-stage ring) ----------------
// C[m,n] = sum_k A[m,k] * (Wh+Wl)[n,k]   (A truncated fp16; error = Al*W ~ 2^-12.8 rel)
// CTA tile 128x128, 8 warps (2m x 4n), warp tile 64x32, BK=32.
// 3-stage ring, prefetch depth 1, single barrier per chunk (NSTAGE >= depth+2):
//   load(c+1) in iter c targets stage (c+1)%3, last read by compute(c-2); every thread's
//   compute(c-2) precedes its BAR(c-1) arrival, and load(c+1) happens only after BAR(c-1).
// Two CTAs per SM overlap each other's wait/barrier bubbles.
#define LDSROW 40
#define TILE_H (128 * LDSROW)       // 5120 halves
#define STAGE_B (3 * TILE_H * 2)    // 30720 B per stage
#define NST 3
#define MM_SMEM (NST * STAGE_B)     // 92160 B

__global__ __launch_bounds__(256, 2) void mmagemm_kernel(
    const __half* __restrict__ Ah,
    const __half* __restrict__ Bh, const __half* __restrict__ Bl,
    int K, int Nn, float* __restrict__ C, int ldc, int mode) {

    extern __shared__ __align__(16) uint8_t dsm[];
    uint32_t dsm_u = smem_u32(dsm);

    int tid = threadIdx.x;
    int wid = tid >> 5;
    int lane = tid & 31;
    int warp_m = wid & 1;      // 2 warps over m (2*64 = 128)
    int warp_n = wid >> 1;     // 4 warps over n (4*32 = 128)
    int m0 = blockIdx.y * 128;
    int n0 = blockIdx.x * 128;

    float acc[4][4][4];
    #pragma unroll
    for (int mt = 0; mt < 4; mt++)
        #pragma unroll
        for (int nt = 0; nt < 4; nt++)
            #pragma unroll
            for (int q = 0; q < 4; q++) acc[mt][nt][q] = 0.f;

    int nchunks = K >> 5;

    auto load_chunk = [&](int c) {
        int kc = c << 5;
        uint32_t sbase = dsm_u + (c % NST) * STAGE_B;
        #pragma unroll
        for (int i = 0; i < 6; i++) {
            int u = tid + i * 256;
            int tile = u >> 9;      // 0=A, 1=Bh, 2=Bl
            int v = u & 511;
            int row = v >> 2;
            int seg = v & 3;
            uint32_t sa = sbase + (tile * TILE_H + row * LDSROW + seg * 8) * 2;
            const __half* g;
            int sz = 16;
            if (tile == 0) {
                g = Ah + (size_t)(m0 + row) * K + kc + seg * 8;
            } else {
                int r = n0 + row;
                if (r >= Nn) { r = Nn - 1; sz = 0; }
                g = ((tile == 1) ? Bh : Bl) + (size_t)r * K + kc + seg * 8;
            }
            cpasync16(sa, g, sz);
        }
        cp_commit();
    };

    load_chunk(0);

    for (int c = 0; c < nchunks; c++) {
        if (c + 1 < nchunks) { load_chunk(c + 1); cp_wait<1>(); }
        else { cp_wait<0>(); }
        __syncthreads();   // single barrier per chunk (see proof above)

        uint32_t base = dsm_u + (c % NST) * STAGE_B;
        #pragma unroll
        for (int kk = 0; kk < 32; kk += 16) {
            uint32_t aF[4][4], bF[2][4][2];
            {
                int arow = warp_m * 64 + (lane & 15);
                int ak = kk + (lane >> 4) * 8;
                #pragma unroll
                for (int mt = 0; mt < 4; mt++)
                    ldsm4(aF[mt], base + ((arow + mt * 16) * LDSROW + ak) * 2);
            }
            {
                int brow = warp_n * 32 + (lane & 7) + (lane >> 4) * 8;
                int bk = kk + ((lane >> 3) & 1) * 8;
                #pragma unroll
                for (int hb = 0; hb < 2; hb++) {
                    uint32_t btile = (uint32_t)(1 + hb) * TILE_H * 2;
                    #pragma unroll
                    for (int g2 = 0; g2 < 2; g2++) {
                        uint32_t r[4];
                        ldsm4(r, base + btile + ((brow + g2 * 16) * LDSROW + bk) * 2);
                        bF[hb][g2 * 2][0] = r[0]; bF[hb][g2 * 2][1] = r[1];
                        bF[hb][g2 * 2 + 1][0] = r[2]; bF[hb][g2 * 2 + 1][1] = r[3];
                    }
                }
            }
            #pragma unroll
            for (int mt = 0; mt < 4; mt++)
                #pragma unroll
                for (int nt = 0; nt < 4; nt++) {
                    mma16816h(acc[mt][nt], aF[mt], bF[0][nt]);
                    mma16816h(acc[mt][nt], aF[mt], bF[1][nt]);
                }
        }
    }
    __syncthreads();   // compute done before epilogue may reuse dsm

    if (mode == 0) {
        #pragma unroll
        for (int mt = 0; mt < 4; mt++) {
            int m = m0 + warp_m * 64 + mt * 16 + (lane >> 2);
            #pragma unroll
            for (int nt = 0; nt < 4; nt++) {
                int n = n0 + warp_n * 32 + nt * 8 + (lane & 3) * 2;
                if (n < Nn) {
                    float2 v0 = make_float2(acc[mt][nt][0], acc[mt][nt][1]);
                    float2 v1 = make_float2(acc[mt][nt][2], acc[mt][nt][3]);
                    *(float2*)&C[(size_t)m * ldc + n] = v0;
                    *(float2*)&C[(size_t)(m + 8) * ldc + n] = v1;
                }
            }
        }
    } else {
        // mode 2: transpose through smem, store to out (B, DIMC, L_SEQ)
        float* sT = (float*)dsm;   // [128 n][132 m] = 67584 B < MM_SMEM
        #pragma unroll
        for (int mt = 0; mt < 4; mt++) {
            int ml = warp_m * 64 + mt * 16 + (lane >> 2);
            #pragma unroll
            for (int nt = 0; nt < 4; nt++) {
                int nl = warp_n * 32 + nt * 8 + (lane & 3) * 2;
                sT[nl * 132 + ml]           = acc[mt][nt][0];
                sT[(nl + 1) * 132 + ml]     = acc[mt][nt][1];
                sT[nl * 132 + ml + 8]       = acc[mt][nt][2];
                sT[(nl + 1) * 132 + ml + 8] = acc[mt][nt][3];
            }
        }
        __syncthreads();
        int b = m0 >> 12;
        int l0 = m0 & (L_SEQ - 1);
        int n = tid >> 1;
        int part = (tid & 1) * 64;
        float* dst = C + ((size_t)b * DIMC + n0 + n) * L_SEQ + l0 + part;
        const float* src = sT + n * 132 + part;
        #pragma unroll
        for (int q = 0; q < 16; q++)
            *(float4*)(dst + q * 4) = *(const float4*)(src + q * 4);
    }
}

// ---------------- fp32 -> fp16 hi/lo split ----------------
__global__ __launch_bounds__(256) void cvt_kernel(const float* __restrict__ s,
                                                  __half* __restrict__ hi,
                                                  __half* __restrict__ lo, int n4) {
    int i = blockIdx.x * blockDim.x + threadIdx.x;
    if (i >= n4) return;
    float4 v = *(const float4*)(s + (size_t)i * 4);
    float vv[4] = {v.x, v.y, v.z, v.w};
    #pragma unroll
    for (int j = 0; j < 4; j++) {
        __half h = __float2half_rn(vv[j]);
        hi[(size_t)i * 4 + j] = h;
        lo[(size_t)i * 4 + j] = __float2half_rn(vv[j] - __half2float(h));
    }
}

__global__ __launch_bounds__(256) void cvt2_kernel(
    const float* __restrict__ s0, __half* __restrict__ hi0, __half* __restrict__ lo0, int n40,
    const float* __restrict__ s1, __half* __restrict__ hi1, __half* __restrict__ lo1, int n41) {
    int i = blockIdx.x * blockDim.x + threadIdx.x;
    const float* s; __half *hi, *lo;
    if (i < n40) { s = s0; hi = hi0; lo = lo0; }
    else { i -= n40; if (i >= n41) return; s = s1; hi = hi1; lo = lo1; }
    float4 v = *(const float4*)(s + (size_t)i * 4);
    float vv[4] = {v.x, v.y, v.z, v.w};
    #pragma unroll
    for (int j = 0; j < 4; j++) {
        __half h = __float2half_rn(vv[j]);
        hi[(size_t)i * 4 + j] = h;
        lo[(size_t)i * 4 + j] = __float2half_rn(vv[j] - __half2float(h));
    }
}

// ---------------- LayerNorm: x (B,C,L) -> xn (B*L, C) fp16 ----------------
__global__ __launch_bounds__(256) void ln_kernel(const float* __restrict__ x,
                                                 const float* __restrict__ w,
                                                 const float* __restrict__ bsh,
                                                 __half* __restrict__ xnh) {
    int b  = blockIdx.y;
    int l0 = blockIdx.x * 64;
    int tid = threadIdx.x;
    int ll = tid & 63;
    int cg = tid >> 6;

    __shared__ float ssum[4][64];
    __shared__ float ssq[4][64];
    __shared__ float smean[64];
    __shared__ float srstd[64];
    __shared__ float st[16][65];

    const float* xb = x + (size_t)b * DIMC * L_SEQ;

    float s = 0.f, sq = 0.f;
    for (int c = cg; c < DIMC; c += 4) {
        float v = xb[(size_t)c * L_SEQ + l0 + ll];
        s += v; sq += v * v;
    }
    ssum[cg][ll] = s; ssq[cg][ll] = sq;
    __syncthreads();
    if (tid < 64) {
        float S = ssum[0][tid] + ssum[1][tid] + ssum[2][tid] + ssum[3][tid];
        float Q = ssq[0][tid] + ssq[1][tid] + ssq[2][tid] + ssq[3][tid];
        float mu = S * (1.f / DIMC);
        float var = Q * (1.f / DIMC) - mu * mu;
        smean[tid] = mu;
        srstd[tid] = rsqrtf(var + 1e-5f);
    }
    __syncthreads();

    for (int c0 = 0; c0 < DIMC; c0 += 16) {
        #pragma unroll
        for (int r = 0; r < 4; r++) {
            int c = c0 + cg + r * 4;
            float v = xb[(size_t)c * L_SEQ + l0 + ll];
            st[cg + r * 4][ll] = (v - smean[ll]) * srstd[ll] * w[c] + bsh[c];
        }
        __syncthreads();
        int c2 = tid & 15, lr = tid >> 4;
        #pragma unroll
        for (int p = 0; p < 4; p++) {
            int l = lr + p * 16;
            xnh[((size_t)b * L_SEQ + l0 + l) * DIMC + c0 + c2] = __float2half_rn(st[c2][l]);
        }
        __syncthreads();
    }
}

// ---------------- fp32 tiled GEMM (dt only) ----------------
#define BM 128
#define BN 128
#define BKK 16
#define PAD 4

__global__ __launch_bounds__(256, 2) void gemm2_kernel(
    const float* __restrict__ A, int lda, int K,
    const float* __restrict__ W, int ldw, int N,
    float* __restrict__ C, int ldc, int mode,
    const float* __restrict__ bias) {

    __shared__ float As[2][BKK][BM + PAD];
    __shared__ float Bs[2][BKK][BN + PAD];

    int tid = threadIdx.x;
    int m0 = blockIdx.y * BM;
    int n0 = blockIdx.x * BN;
    int tm = tid & 15;
    int tn = tid >> 4;

    int lr = tid >> 2;
    int lk = (tid & 3) * 4;

    float4 pa[2], pb[2];
    int nt = (K + BKK - 1) / BKK;

    {
        int kk = lk;
        #pragma unroll
        for (int r = 0; r < 2; r++) {
            int m = lr + r * 64;
            float4 v = make_float4(0.f, 0.f, 0.f, 0.f);
            if (kk < K) v = *(const float4*)&A[(size_t)(m0 + m) * lda + kk];
            pa[r] = v;
            float4 u = make_float4(0.f, 0.f, 0.f, 0.f);
            if (kk < K && (n0 + m) < N) u = *(const float4*)&W[(size_t)(n0 + m) * ldw + kk];
            pb[r] = u;
        }
    }

    float acc[8][8];
    #pragma unroll
    for (int i = 0; i < 8; i++)
        #pragma unroll
        for (int j = 0; j < 8; j++) acc[i][j] = 0.f;

    for (int t = 0; t < nt; t++) {
        int buf = t & 1;
        #pragma unroll
        for (int r = 0; r < 2; r++) {
            int m = lr + r * 64;
            As[buf][lk + 0][m] = pa[r].x;
            As[buf][lk + 1][m] = pa[r].y;
            As[buf][lk + 2][m] = pa[r].z;
            As[buf][lk + 3][m] = pa[r].w;
            Bs[buf][lk + 0][m] = pb[r].x;
            Bs[buf][lk + 1][m] = pb[r].y;
            Bs[buf][lk + 2][m] = pb[r].z;
            Bs[buf][lk + 3][m] = pb[r].w;
        }
        __syncthreads();

        if (t + 1 < nt) {
            int kk = (t + 1) * BKK + lk;
            #pragma unroll
            for (int r = 0; r < 2; r++) {
                int m = lr + r * 64;
                float4 v = make_float4(0.f, 0.f, 0.f, 0.f);
                if (kk < K) v = *(const float4*)&A[(size_t)(m0 + m) * lda + kk];
                pa[r] = v;
                float4 u = make_float4(0.f, 0.f, 0.f, 0.f);
                if (kk < K && (n0 + m) < N) u = *(const float4*)&W[(size_t)(n0 + m) * ldw + kk];
                pb[r] = u;
            }
        }

        const float (*Ab)[BM + PAD] = As[buf];
        const float (*Bb)[BN + PAD] = Bs[buf];
        #pragma unroll
        for (int k = 0; k < BKK; k++) {
            float a[8], b[8];
            *(float4*)&a[0] = *(const float4*)&Ab[k][tm * 4];
            *(float4*)&a[4] = *(const float4*)&Ab[k][64 + tm * 4];
            *(float4*)&b[0] = *(const float4*)&Bb[k][tn * 4];
            *(float4*)&b[4] = *(const float4*)&Bb[k][64 + tn * 4];
            #pragma unroll
            for (int i = 0; i < 8; i++)
                #pragma unroll
                for (int j = 0; j < 8; j++)
                    acc[i][j] = fmaf(a[i], b[j], acc[i][j]);
        }
        __syncthreads();
    }

    #pragma unroll
    for (int ih = 0; ih < 2; ih++) {
        #pragma unroll
        for (int i4 = 0; i4 < 4; i4++) {
            int i = ih * 4 + i4;
            int m = m0 + ih * 64 + tm * 4 + i4;
            #pragma unroll
            for (int jh = 0; jh < 2; jh++) {
                int n = n0 + jh * 64 + tn * 4;
                if (n < N) {
                    float4 v = make_float4(acc[i][jh * 4 + 0], acc[i][jh * 4 + 1],
                                           acc[i][jh * 4 + 2], acc[i][jh * 4 + 3]);
                    if (mode == 1) {
                        float* vv = (float*)&v;
                        #pragma unroll
                        for (int j = 0; j < 4; j++) {
                            float z = vv[j] + bias[n + j];
                            vv[j] = fmaxf(z, 0.f) + log1pf(__expf(-fabsf(z)));
                        }
                    }
                    if (n + 3 < N) {
                        *(float4*)&C[(size_t)m * ldc + n] = v;
                    } else {
                        float* vv = (float*)&v;
                        #pragma unroll
                        for (int j = 0; j < 4; j++)
                            if (n + j < N) C[(size_t)m * ldc + n + j] = vv[j];
                    }
                }
            }
        }
    }
}

// ---------------- depthwise causal conv1d (k=4) + SiLU, smem-tiled ----------------
__global__ __launch_bounds__(256) void conv_silu2_kernel(const float* __restrict__ cw,
                                                         const float* __restrict__ cb,
                                                         const float* __restrict__ xz,
                                                         float* __restrict__ xc,
                                                         __half* __restrict__ xch) {
    __shared__ float sx[67][64];
    int d0 = blockIdx.x * 64;
    int mchunk = blockIdx.y;
    int l0 = (mchunk & 63) * 64;
    int b = mchunk >> 6;
    int tid = threadIdx.x;
    int tx = tid & 63, ty = tid >> 6;
    size_t rowbase = (size_t)b * L_SEQ;

    for (int r = ty; r < 67; r += 4) {
        int l = l0 - 3 + r;
        float v = 0.f;
        if (l >= 0) v = xz[(rowbase + l) * (2 * D_INNER) + d0 + tx];
        sx[r][tx] = v;
    }
    __syncthreads();

    int d = d0 + tx;
    float w0 = cw[d * 4 + 0], w1 = cw[d * 4 + 1];
    float w2 = cw[d * 4 + 2], w3 = cw[d * 4 + 3];
    float bias = cb[d];

    #pragma unroll 4
    for (int i = 0; i < 16; i++) {
        int ll = ty + i * 4;
        int r = ll + 3;
        float acc = bias;
        acc = fmaf(w3, sx[r][tx], acc);
        acc = fmaf(w2, sx[r - 1][tx], acc);
        acc = fmaf(w1, sx[r - 2][tx], acc);
        acc = fmaf(w0, sx[r - 3][tx], acc);
        float sg = 1.f / (1.f + __expf(-acc));
        float v = acc * sg;
        size_t o = (rowbase + l0 + ll) * D_INNER + d;
        xc[o] = v;
        xch[o] = __float2half_rn(v);
    }
}

// ---------------- selective scan v5: phase-split, 4-stage cp.async, SCH=32 ----------------
#define SCH5 32
#define CH5 24
#define NST5 4
#define NCH5 (L_SEQ / SCH5)     // 128
#define S5_BC 0
#define S5_D  4096
#define S5_X  7168
#define S5_Z  10240
#define S5_P  13312
#define S5_TOTAL (13312 + 32 * 24 * 20)   // 28672 floats = 114688 B

__global__ __launch_bounds__(384) void scan5_kernel(const float* __restrict__ A_log,
                                                    const float* __restrict__ Dp,
                                                    const float* __restrict__ dtv,
                                                    const float* __restrict__ xc,
                                                    const float* __restrict__ xdbl,
                                                    const float* __restrict__ xz,
                                                    __half* __restrict__ yh) {
    extern __shared__ float sm5[];
    float* sBC = sm5 + S5_BC;
    float* sD  = sm5 + S5_D;
    float* sX  = sm5 + S5_X;
    float* sZ  = sm5 + S5_Z;
    float* sP  = sm5 + S5_P;

    int b = blockIdx.y;
    int g = blockIdx.x;
    int d0 = g * CH5;
    int tid = threadIdx.x;
    size_t bL = (size_t)b * L_SEQ;

    int lane = tid & 31;
    int w = tid >> 5;
    int half = lane >> 4;
    int n = lane & 15;
    int dl = 2 * w + half;

    float An = -__expf(A_log[(d0 + dl) * D_STATE + n]);
    float h = 0.f;

    int rl = tid / CH5;
    int rc = tid % CH5;
    float Dd = Dp[d0 + rc];

    auto issue = [&](int c) {
        int l0 = c * SCH5;
        int buf = c % NST5;
        uint32_t bcs = smem_u32(sBC + buf * 1024);
        uint32_t ds  = smem_u32(sD  + buf * 768);
        uint32_t xs  = smem_u32(sX  + buf * 768);
        uint32_t zs  = smem_u32(sZ  + buf * 768);
        for (int u = tid; u < 832; u += 384) {
            if (u < 256) {
                int l = u >> 3, c4 = u & 7;
                cpasync16(bcs + (uint32_t)(l * 32 + c4 * 4) * 4,
                          xdbl + (bL + l0 + l) * XPN + DT_RANK + c4 * 4, 16);
            } else if (u < 448) {
                int v = u - 256; int l = v / 6, c4 = v % 6;
                cpasync16(ds + (uint32_t)(l * 24 + c4 * 4) * 4,
                          dtv + (bL + l0 + l) * D_INNER + d0 + c4 * 4, 16);
            } else if (u < 640) {
                int v = u - 448; int l = v / 6, c4 = v % 6;
                cpasync16(xs + (uint32_t)(l * 24 + c4 * 4) * 4,
                          xc + (bL + l0 + l) * D_INNER + d0 + c4 * 4, 16);
            } else {
                int v = u - 640; int l = v / 6, c4 = v % 6;
                cpasync16(zs + (uint32_t)(l * 24 + c4 * 4) * 4,
                          xz + (bL + l0 + l) * 2 * D_INNER + D_INNER + d0 + c4 * 4, 16);
            }
        }
        cp_commit();
    };

    issue(0);
    issue(1);

    for (int c = 0; c < NCH5; c++) {
        if (c + 2 < NCH5) { issue(c + 2); cp_wait<2>(); }
        else if (c + 1 < NCH5) { cp_wait<1>(); }
        else { cp_wait<0>(); }
        __syncthreads();                 // BAR_a

        int buf = c % NST5;
        const float* bD  = sD  + buf * 768;
        const float* bX  = sX  + buf * 768;
        const float* bBC = sBC + buf * 1024;

        #pragma unroll 8
        for (int l = 0; l < SCH5; l++) {
            float dt = bD[l * 24 + dl];
            float xv = bX[l * 24 + dl];
            float Bn = bBC[l * 32 + n];
            float Cn = bBC[l * 32 + 16 + n];
            float e = __expf(dt * An);
            h = fmaf(e, h, dt * xv * Bn);
            sP[(l * 24 + dl) * 20 + n] = h * Cn;
        }
        __syncthreads();                 // BAR_b

        #pragma unroll
        for (int i = 0; i < 2; i++) {
            int l = rl + i * 16;
            const float* p = sP + (l * 24 + rc) * 20;
            float4 a  = *(const float4*)p;
            float4 bq = *(const float4*)(p + 4);
            float4 cq = *(const float4*)(p + 8);
            float4 dq = *(const float4*)(p + 12);
            float s = ((a.x + a.y) + (a.z + a.w)) + ((bq.x + bq.y) + (bq.z + bq.w))
                    + ((cq.x + cq.y) + (cq.z + cq.w)) + ((dq.x + dq.y) + (dq.z + dq.w));
            float xv = bX[l * 24 + rc];
            float zv = sZ[buf * 768 + l * 24 + rc];
            float yv = fmaf(xv, Dd, s);
            yv *= zv / (1.f + __expf(-zv));
            size_t o = (bL + (size_t)c * SCH5 + l) * D_INNER + d0 + rc;
            yh[o] = __float2half_rn(yv);
        }
    }
}

// ---------------- launch ----------------
extern "C" void kernel_launch(void* const* d_in, const int* in_sizes, int n_in,
                              void* d_out, int out_size) {
    const float* x          = (const float*)d_in[0];
    const float* ln_w       = (const float*)d_in[1];
    const float* ln_b       = (const float*)d_in[2];
    const float* in_proj_w  = (const float*)d_in[3];
    const float* conv_w     = (const float*)d_in[4];
    const float* conv_b     = (const float*)d_in[5];
    const float* x_proj_w   = (const float*)d_in[6];
    const float* dt_w       = (const float*)d_in[7];
    const float* dt_b       = (const float*)d_in[8];
    const float* A_log      = (const float*)d_in[9];
    const float* Dp         = (const float*)d_in[10];
    const float* out_proj_w = (const float*)d_in[11];
    float* out = (float*)d_out;

    float *p_xz, *p_xc, *p_xdbl, *p_dtv;
    __half *p_xnh, *p_xch, *p_yh;
    __half *p_wih, *p_wil, *p_woh, *p_wol, *p_wxh, *p_wxl;
    cudaGetSymbolAddress((void**)&p_xz,   g_xz);
    cudaGetSymbolAddress((void**)&p_xc,   g_xc);
    cudaGetSymbolAddress((void**)&p_xdbl, g_xdbl);
    cudaGetSymbolAddress((void**)&p_dtv,  g_dtv);
    cudaGetSymbolAddress((void**)&p_xnh,  g_xn_h);
    cudaGetSymbolAddress((void**)&p_xch,  g_xc_h);
    cudaGetSymbolAddress((void**)&p_yh,   g_y_h);
    cudaGetSymbolAddress((void**)&p_wih,  g_wi_hi);
    cudaGetSymbolAddress((void**)&p_wil,  g_wi_lo);
    cudaGetSymbolAddress((void**)&p_woh,  g_wo_hi);
    cudaGetSymbolAddress((void**)&p_wol,  g_wo_lo);
    cudaGetSymbolAddress((void**)&p_wxh,  g_wx_hi);
    cudaGetSymbolAddress((void**)&p_wxl,  g_wx_lo);

    const int SC_SMEM = S5_TOTAL * 4;   // 114688 B
    cudaFuncSetAttribute(mmagemm_kernel, cudaFuncAttributeMaxDynamicSharedMemorySize, MM_SMEM);
    cudaFuncSetAttribute(scan5_kernel, cudaFuncAttributeMaxDynamicSharedMemorySize, SC_SMEM);

    // 0) weight hi/lo conversion
    int n4i = (2 * D_INNER * DIMC) / 4;
    cvt_kernel<<<(n4i + 255) / 256, 256>>>(in_proj_w, p_wih, p_wil, n4i);
    int n4o = (DIMC * D_INNER) / 4;
    int n4x = (XPN * D_INNER) / 4;
    cvt2_kernel<<<(n4o + n4x + 255) / 256, 256>>>(out_proj_w, p_woh, p_wol, n4o,
                                                  x_proj_w, p_wxh, p_wxl, n4x);

    // 1) LayerNorm -> xn fp16
    ln_kernel<<<dim3(L_SEQ / 64, B_SZ), 256>>>(x, ln_w, ln_b, p_xnh);

    // 2) in_proj (fp16 2-term) — profiled slot
    mmagemm_kernel<<<dim3(2 * D_INNER / 128, M_TOTAL / 128), 256, MM_SMEM>>>(
        p_xnh, p_wih, p_wil, DIMC, 2 * D_INNER, p_xz, 2 * D_INNER, 0);

    // 3) depthwise conv + silu -> xc fp32 + fp16
    conv_silu2_kernel<<<dim3(D_INNER / 64, M_TOTAL / 64), 256>>>(
        conv_w, conv_b, p_xz, p_xc, p_xch);

    // 4) x_proj (fp16 2-term, N=56 masked)
    mmagemm_kernel<<<dim3(1, M_TOTAL / 128), 256, MM_SMEM>>>(
        p_xch, p_wxh, p_wxl, D_INNER, XPN, p_xdbl, XPN, 0);

    // 5) dt + softplus (fp32 SIMT, K=24)
    gemm2_kernel<<<dim3(D_INNER / BN, M_TOTAL / BM), 256>>>(
        p_xdbl, XPN, DT_RANK, dt_w, DT_RANK, D_INNER, p_dtv, D_INNER, 1, dt_b);

    // 6) selective scan v5 -> y fp16
    scan5_kernel<<<dim3(D_INNER / CH5, B_SZ), 384, SC_SMEM>>>(
        A_log, Dp, p_dtv, p_xc, p_xdbl, p_xz, p_yh);

    // 7) out_proj (fp16 2-term, transposed store)
    mmagemm_kernel<<<dim3(DIMC / 128, M_TOTAL / 128), 256, MM_SMEM>>>(
        p_yh, p_woh, p_wol, D_INNER, DIMC, out, 0, 2);
}